// round 8
// baseline (speedup 1.0000x reference)
#include <cuda_runtime.h>
#include <cuda_bf16.h>
#include <math.h>
#include <stdint.h>

// ---------------- problem constants (static per reference) ----------------
#define BSZ   8
#define NQ    4096
#define CDIM  256
#define NHEAD 8
#define NPT   4
#define NLVL  6
#define NVAL  10752
#define DHEAD 32
#define NOFF  384
#define NATT  192
#define NQA   576          // NOFF + NATT fused GEMM width
#define NWT   1088         // 256 (val) + 576 (off|attn) + 256 (out)
#define MQ    (BSZ * NQ)   // 32768
#define MV    (BSZ * NVAL) // 86016

// ---------------- device scratch (static, no allocation) ------------------
__device__ float g_vproj[(size_t)MV * CDIM];
__device__ float g_qa   [(size_t)MQ * NQA];            // [off(384) | attn(192)]
__device__ __nv_bfloat16 g_val_h[(size_t)MV * CDIM];   // value, bf16 hi
__device__ __nv_bfloat16 g_val_l[(size_t)MV * CDIM];   // value, bf16 lo
__device__ __nv_bfloat16 g_q_h  [(size_t)MQ * CDIM];   // query+qpos hi
__device__ __nv_bfloat16 g_q_l  [(size_t)MQ * CDIM];   // query+qpos lo
__device__ __nv_bfloat16 g_ms_h [(size_t)MQ * CDIM];   // deform-attn out hi
__device__ __nv_bfloat16 g_ms_l [(size_t)MQ * CDIM];   // deform-attn out lo
__device__ __nv_bfloat16 g_Wt_hi[NWT * CDIM];          // all weights^T hi
__device__ __nv_bfloat16 g_Wt_lo[NWT * CDIM];          // all weights^T lo
__device__ float g_bias[NWT];

__constant__ int c_H[NLVL] = {64, 32, 16, 64, 32, 16};
__constant__ int c_W[NLVL] = {64, 32, 16, 64, 32, 16};
__constant__ int c_S[NLVL] = {0, 4096, 5120, 5376, 9472, 10496};

// ---------------- small helpers -------------------------------------------
__device__ __forceinline__ uint32_t smem_u32(const void* p) {
    uint32_t a;
    asm("{ .reg .u64 t; cvta.to.shared.u64 t, %1; cvt.u32.u64 %0, t; }"
        : "=r"(a) : "l"(p));
    return a;
}
__device__ __forceinline__ void ldsm_x4(uint32_t* r, uint32_t addr) {
    asm volatile("ldmatrix.sync.aligned.m8n8.x4.shared.b16 {%0,%1,%2,%3}, [%4];"
                 : "=r"(r[0]), "=r"(r[1]), "=r"(r[2]), "=r"(r[3]) : "r"(addr));
}
__device__ __forceinline__ void mma_bf16(float* c, const uint32_t* a,
                                         const uint32_t* b) {
    asm volatile(
        "mma.sync.aligned.m16n8k16.row.col.f32.bf16.bf16.f32 "
        "{%0,%1,%2,%3}, {%4,%5,%6,%7}, {%8,%9}, {%0,%1,%2,%3};"
        : "+f"(c[0]), "+f"(c[1]), "+f"(c[2]), "+f"(c[3])
        : "r"(a[0]), "r"(a[1]), "r"(a[2]), "r"(a[3]), "r"(b[0]), "r"(b[1]));
}
__device__ __forceinline__ uint32_t pack_bf16(float x, float y) {
    __nv_bfloat162 t = __halves2bfloat162(__float2bfloat16_rn(x),
                                          __float2bfloat16_rn(y));
    return *(uint32_t*)&t;
}
__device__ __forceinline__ void cp16(uint32_t dst, const void* src) {
    asm volatile("cp.async.cg.shared.global [%0], [%1], 16;"
                 :: "r"(dst), "l"(src));
}
#define CP_COMMIT() asm volatile("cp.async.commit_group;" ::: "memory")
#define CP_WAIT(n)  asm volatile("cp.async.wait_group %0;" :: "n"(n) : "memory")

// ============== fused prep: weights + value split + q split =================
// blocks [0,1088): weight transpose + hi/lo split + bias concat
// blocks [1088, 1088+21504): value hi/lo split
// blocks [22592, 30784): (query+qpos) hi/lo split
#define PREP_B0 1088
#define PREP_B1 (PREP_B0 + (MV * CDIM / 4) / 256)   // 1088 + 21504
#define PREP_NB (PREP_B1 + (MQ * CDIM / 4) / 256)   // + 8192 = 30784

__global__ __launch_bounds__(256)
void prep_all_kernel(const float* __restrict__ W_val,
                     const float* __restrict__ b_val,
                     const float* __restrict__ W_off,
                     const float* __restrict__ b_off,
                     const float* __restrict__ W_attn,
                     const float* __restrict__ b_attn,
                     const float* __restrict__ W_out,
                     const float* __restrict__ b_out,
                     const float* __restrict__ value,
                     const float* __restrict__ query,
                     const float* __restrict__ qpos)
{
    const int bx = blockIdx.x;
    const int tid = threadIdx.x;
    if (bx < PREP_B0) {
        const int n = bx, k = tid;
        float x, bb;
        if (n < 256)      { x = W_val[k * 256 + n];          bb = b_val[n]; }
        else if (n < 832) {
            const int m = n - 256;
            if (m < 384)  { x = W_off[k * 384 + m];          bb = b_off[m]; }
            else          { x = W_attn[k * 192 + (m - 384)]; bb = b_attn[m - 384]; }
        }
        else              { x = W_out[k * 256 + (n - 832)];  bb = b_out[n - 832]; }
        const __nv_bfloat16 hi = __float2bfloat16_rn(x);
        const __nv_bfloat16 lo = __float2bfloat16_rn(x - __bfloat162float(hi));
        g_Wt_hi[n * CDIM + k] = hi;
        g_Wt_lo[n * CDIM + k] = lo;
        if (k == 0) g_bias[n] = bb;
        return;
    }
    float4 v;
    size_t i4;
    __nv_bfloat16 *H, *L;
    if (bx < PREP_B1) {
        i4 = (size_t)(bx - PREP_B0) * 256 + tid;
        v = ((const float4*)value)[i4];
        H = g_val_h; L = g_val_l;
    } else {
        i4 = (size_t)(bx - PREP_B1) * 256 + tid;
        v = ((const float4*)query)[i4];
        const float4 u = ((const float4*)qpos)[i4];
        v.x += u.x; v.y += u.y; v.z += u.z; v.w += u.w;
        H = g_q_h; L = g_q_l;
    }
    const float hx = __bfloat162float(__float2bfloat16_rn(v.x));
    const float hy = __bfloat162float(__float2bfloat16_rn(v.y));
    const float hz = __bfloat162float(__float2bfloat16_rn(v.z));
    const float hw = __bfloat162float(__float2bfloat16_rn(v.w));
    ((uint2*)H)[i4] = make_uint2(pack_bf16(v.x, v.y), pack_bf16(v.z, v.w));
    ((uint2*)L)[i4] = make_uint2(pack_bf16(v.x - hx, v.y - hy),
                                 pack_bf16(v.z - hz, v.w - hw));
}

// ============== bf16-split HMMA GEMM, 3-stage cp.async pipeline =============
// C[M,N] = A@B^T + bias (+resid);  A = Ah+Al (bf16 [M,K]), B = Bh+Bl ([N,K]).
// D = Ah*Bh + Ah*Bl + Al*Bh, fp32 accum. BM=128, BN=64, BK=32, 8 warps.
// 3 stages x (Ah 10240 | Al 10240 | Bh 5120 | Bl 5120) = 92160 B dyn smem.
#define HG_STG   30720
#define HG_SMEM  (3 * HG_STG)

template <bool RESID>
__global__ __launch_bounds__(256)
void hgemm3_kernel(const __nv_bfloat16* __restrict__ Ath,
                   const __nv_bfloat16* __restrict__ Atl,
                   const __nv_bfloat16* __restrict__ Bth,
                   const __nv_bfloat16* __restrict__ Btl,
                   const float* __restrict__ bias,
                   const float* __restrict__ resid, float* __restrict__ C,
                   int M, int N, int K)
{
    extern __shared__ __align__(16) uint8_t smem[];
    const uint32_t uS = smem_u32(smem);

    const int tid  = threadIdx.x;
    const int lane = tid & 31;
    const int wid  = tid >> 5;
    const int wm   = wid >> 1;         // 0..3
    const int wn   = wid & 1;          // 0..1
    const int bm   = blockIdx.x * 128;
    const int bn   = blockIdx.y * 64;
    const int KT   = K >> 5;           // 8

    // ldmatrix lane offsets (relative to stage base)
    const int lrA = ((lane >> 3) & 1) * 8 + (lane & 7);
    const int lkA = (lane >> 4) * 8;
    const uint32_t offAh = (uint32_t)((wm * 32 + lrA) * 80 + lkA * 2);
    const uint32_t offAl = offAh + 10240u;
    const int lrB = (lane >> 4) * 8 + (lane & 7);
    const int lkB = ((lane >> 3) & 1) * 8;
    const uint32_t offBh = 20480u + (uint32_t)((wn * 32 + lrB) * 80 + lkB * 2);
    const uint32_t offBl = offBh + 5120u;

    // staging indices
    const int ar0 = tid >> 2, ac0 = tid & 3;            // rows 0..63
    const int ar1 = (tid + 256) >> 2;                   // rows 64..127
    const int br  = tid >> 2, bc = tid & 3;             // B rows 0..63

    float acc[2][4][4];
#pragma unroll
    for (int t = 0; t < 2; t++)
#pragma unroll
        for (int u = 0; u < 4; u++)
#pragma unroll
            for (int i = 0; i < 4; i++) acc[t][u][i] = 0.f;

    auto issue = [&](int kt) {
        const int k0 = kt * 32;
        const uint32_t base = uS + (kt % 3) * HG_STG;
        const size_t oa0 = (size_t)(bm + ar0) * K + k0 + ac0 * 8;
        const size_t oa1 = (size_t)(bm + ar1) * K + k0 + ac0 * 8;
        const size_t ob  = (size_t)(bn + br ) * K + k0 + bc  * 8;
        cp16(base +          ar0 * 80 + ac0 * 16, Ath + oa0);
        cp16(base +          ar1 * 80 + ac0 * 16, Ath + oa1);
        cp16(base + 10240u + ar0 * 80 + ac0 * 16, Atl + oa0);
        cp16(base + 10240u + ar1 * 80 + ac0 * 16, Atl + oa1);
        cp16(base + 20480u + br  * 80 + bc  * 16, Bth + ob);
        cp16(base + 25600u + br  * 80 + bc  * 16, Btl + ob);
        CP_COMMIT();
    };

    issue(0);
    issue(1);

#pragma unroll 1
    for (int kt = 0; kt < KT; kt++) {
        if (kt == KT - 1) { CP_WAIT(0); } else { CP_WAIT(1); }
        __syncthreads();
        // prefetch 2 ahead into buffer (kt+2)%3 == (kt-1)%3, which every
        // warp finished consuming (we are past the sync of iteration kt).
        if (kt + 2 < KT) issue(kt + 2);

        const uint32_t sb = uS + (kt % 3) * HG_STG;
#pragma unroll
        for (int ks = 0; ks < 2; ks++) {
            const uint32_t ko = ks * 32;
            uint32_t aH[2][4], aL[2][4], bH[4][2], bL[4][2];
            ldsm_x4(aH[0], sb + offAh + ko);
            ldsm_x4(aH[1], sb + offAh + 1280 + ko);
            ldsm_x4(aL[0], sb + offAl + ko);
            ldsm_x4(aL[1], sb + offAl + 1280 + ko);
            ldsm_x4(&bH[0][0], sb + offBh + ko);
            ldsm_x4(&bH[2][0], sb + offBh + 1280 + ko);
            ldsm_x4(&bL[0][0], sb + offBl + ko);
            ldsm_x4(&bL[2][0], sb + offBl + 1280 + ko);
#pragma unroll
            for (int t = 0; t < 2; t++)
#pragma unroll
                for (int u = 0; u < 4; u++) {
                    mma_bf16(acc[t][u], aH[t], bH[u]);
                    mma_bf16(acc[t][u], aH[t], bL[u]);
                    mma_bf16(acc[t][u], aL[t], bH[u]);
                }
        }
    }

    // ---- epilogue (verified mapping, unchanged) ----
    const int g = lane >> 2, tg = lane & 3;
#pragma unroll
    for (int t = 0; t < 2; t++)
#pragma unroll
        for (int u = 0; u < 4; u++) {
            const int row = bm + wm * 32 + t * 16 + g;
            const int col = bn + wn * 32 + u * 8 + tg * 2;
            const float2 bv = *(const float2*)(bias + col);
            float2 o0 = make_float2(acc[t][u][0] + bv.x, acc[t][u][1] + bv.y);
            float2 o1 = make_float2(acc[t][u][2] + bv.x, acc[t][u][3] + bv.y);
            if (RESID) {
                const float2 r0 = *(const float2*)(resid + (size_t)row * N + col);
                const float2 r1 = *(const float2*)(resid + (size_t)(row + 8) * N + col);
                o0.x += r0.x; o0.y += r0.y;
                o1.x += r1.x; o1.y += r1.y;
            }
            *(float2*)(C + (size_t)row * N + col) = o0;
            *(float2*)(C + (size_t)(row + 8) * N + col) = o1;
        }
}

// ---------------- sampling kernel ------------------------------------------
// Phase 1: lanes 0..23 softmax + corner (byte-offset<<0, weight) pairs into
// smem laid out [corner][point] so phase 2 reads TWO points per LDS.128.
__global__ __launch_bounds__(256)
void sample_kernel(const float* __restrict__ refp)
{
    __shared__ __align__(16) unsigned long long sm_iw[8][4][24]; // [warp][corner][point]

    const int wslot = threadIdx.x >> 5;
    const int warp = blockIdx.x * 8 + wslot;
    const int lane = threadIdx.x & 31;
    const int h  = warp & 7;
    const int bq = warp >> 3;
    const int b  = bq >> 12;

    float a = -INFINITY;
    if (lane < 24) a = g_qa[(size_t)bq * NQA + NOFF + h * 24 + lane];
    float m = a;
#pragma unroll
    for (int s = 16; s; s >>= 1) m = fmaxf(m, __shfl_xor_sync(0xffffffffu, m, s));
    float e = (lane < 24) ? __expf(a - m) : 0.f;
    float ssum = e;
#pragma unroll
    for (int s = 16; s; s >>= 1) ssum += __shfl_xor_sync(0xffffffffu, ssum, s);
    const float aw = e / ssum;

    if (lane < 24) {
        const int l = lane >> 2;
        const int p = lane & 3;
        const int H = c_H[l], W = c_W[l], S = c_S[l];
        const size_t ob = (size_t)bq * NQA + (((h * NLVL + l) * NPT + p) << 1);
        const float offx = g_qa[ob + 0];
        const float offy = g_qa[ob + 1];
        const size_t rb = ((size_t)bq * NLVL + l) << 1;
        const float rx = refp[rb + 0];
        const float ry = refp[rb + 1];
        const float x = rx * (float)W + offx - 0.5f;
        const float y = ry * (float)H + offy - 0.5f;
        const float xf = floorf(x), yf = floorf(y);
        const float lx = x - xf, ly = y - yf;
        const int ix = (int)xf, iy = (int)yf;
        const bool vx0 = (ix     >= 0) && (ix     < W);
        const bool vx1 = (ix + 1 >= 0) && (ix + 1 < W);
        const bool vy0 = (iy     >= 0) && (iy     < H);
        const bool vy1 = (iy + 1 >= 0) && (iy + 1 < H);
        const int cx0 = min(max(ix, 0), W - 1);
        const int cx1 = min(max(ix + 1, 0), W - 1);
        const int cy0 = min(max(iy, 0), H - 1);
        const int cy1 = min(max(iy + 1, 0), H - 1);
        // byte offsets (idx * CDIM floats * 4B = idx << 10)
        const unsigned o00 = (unsigned)(S + cy0 * W + cx0) << 10;
        const unsigned o01 = (unsigned)(S + cy0 * W + cx1) << 10;
        const unsigned o10 = (unsigned)(S + cy1 * W + cx0) << 10;
        const unsigned o11 = (unsigned)(S + cy1 * W + cx1) << 10;
        const float w00 = aw * (1.f - lx) * (1.f - ly) * (float)(vx0 && vy0);
        const float w01 = aw * lx         * (1.f - ly) * (float)(vx1 && vy0);
        const float w10 = aw * (1.f - lx) * ly         * (float)(vx0 && vy1);
        const float w11 = aw * lx         * ly         * (float)(vx1 && vy1);
        sm_iw[wslot][0][lane] =
            (unsigned long long)o00 | ((unsigned long long)__float_as_uint(w00) << 32);
        sm_iw[wslot][1][lane] =
            (unsigned long long)o01 | ((unsigned long long)__float_as_uint(w01) << 32);
        sm_iw[wslot][2][lane] =
            (unsigned long long)o10 | ((unsigned long long)__float_as_uint(w10) << 32);
        sm_iw[wslot][3][lane] =
            (unsigned long long)o11 | ((unsigned long long)__float_as_uint(w11) << 32);
    }
    __syncwarp();

    const int g  = lane >> 3;
    const int li = lane & 7;
    const char* __restrict__ vbb =
        (const char*)(g_vproj + (size_t)b * NVAL * CDIM + h * DHEAD + li * 4);

    float4 acc0 = make_float4(0.f, 0.f, 0.f, 0.f);
    float4 acc1 = make_float4(0.f, 0.f, 0.f, 0.f);
#pragma unroll
    for (int j = 0; j < 12; j++) {
        const uint4 t = *(const uint4*)&sm_iw[wslot][g][2 * j];
        const float w0 = __uint_as_float(t.y);
        const float w1 = __uint_as_float(t.w);
        const float4 v0 = *(const float4*)(vbb + t.x);
        const float4 v1 = *(const float4*)(vbb + t.z);
        acc0.x = fmaf(w0, v0.x, acc0.x);
        acc0.y = fmaf(w0, v0.y, acc0.y);
        acc0.z = fmaf(w0, v0.z, acc0.z);
        acc0.w = fmaf(w0, v0.w, acc0.w);
        acc1.x = fmaf(w1, v1.x, acc1.x);
        acc1.y = fmaf(w1, v1.y, acc1.y);
        acc1.z = fmaf(w1, v1.z, acc1.z);
        acc1.w = fmaf(w1, v1.w, acc1.w);
    }
    float4 acc = make_float4(acc0.x + acc1.x, acc0.y + acc1.y,
                             acc0.z + acc1.z, acc0.w + acc1.w);
#pragma unroll
    for (int s = 8; s <= 16; s <<= 1) {
        acc.x += __shfl_xor_sync(0xffffffffu, acc.x, s);
        acc.y += __shfl_xor_sync(0xffffffffu, acc.y, s);
        acc.z += __shfl_xor_sync(0xffffffffu, acc.z, s);
        acc.w += __shfl_xor_sync(0xffffffffu, acc.w, s);
    }
    if (lane < 8) {
        const size_t o4 = ((size_t)bq * CDIM + h * DHEAD + lane * 4) >> 2;
        const float hx = __bfloat162float(__float2bfloat16_rn(acc.x));
        const float hy = __bfloat162float(__float2bfloat16_rn(acc.y));
        const float hz = __bfloat162float(__float2bfloat16_rn(acc.z));
        const float hw = __bfloat162float(__float2bfloat16_rn(acc.w));
        ((uint2*)g_ms_h)[o4] = make_uint2(pack_bf16(acc.x, acc.y),
                                          pack_bf16(acc.z, acc.w));
        ((uint2*)g_ms_l)[o4] = make_uint2(pack_bf16(acc.x - hx, acc.y - hy),
                                          pack_bf16(acc.z - hz, acc.w - hw));
    }
}

// ---------------- launch ----------------
extern "C" void kernel_launch(void* const* d_in, const int* in_sizes, int n_in,
                              void* d_out, int out_size)
{
    const float* query  = (const float*)d_in[0];
    const float* qpos   = (const float*)d_in[1];
    const float* value  = (const float*)d_in[2];
    const float* refp   = (const float*)d_in[3];
    const float* W_off  = (const float*)d_in[5];
    const float* b_off  = (const float*)d_in[6];
    const float* W_attn = (const float*)d_in[7];
    const float* b_attn = (const float*)d_in[8];
    const float* W_val  = (const float*)d_in[9];
    const float* b_val  = (const float*)d_in[10];
    const float* W_out  = (const float*)d_in[11];
    const float* b_out  = (const float*)d_in[12];
    float* out = (float*)d_out;

    float *vproj, *qa, *biasb;
    __nv_bfloat16 *wth, *wtl, *valh, *vall, *qh, *ql, *msh, *msl;
    cudaGetSymbolAddress((void**)&vproj, g_vproj);
    cudaGetSymbolAddress((void**)&qa,    g_qa);
    cudaGetSymbolAddress((void**)&biasb, g_bias);
    cudaGetSymbolAddress((void**)&wth,   g_Wt_hi);
    cudaGetSymbolAddress((void**)&wtl,   g_Wt_lo);
    cudaGetSymbolAddress((void**)&valh,  g_val_h);
    cudaGetSymbolAddress((void**)&vall,  g_val_l);
    cudaGetSymbolAddress((void**)&qh,    g_q_h);
    cudaGetSymbolAddress((void**)&ql,    g_q_l);
    cudaGetSymbolAddress((void**)&msh,   g_ms_h);
    cudaGetSymbolAddress((void**)&msl,   g_ms_l);

    static bool attr_done = false;
    if (!attr_done) {
        cudaFuncSetAttribute(hgemm3_kernel<false>,
                             cudaFuncAttributeMaxDynamicSharedMemorySize, HG_SMEM);
        cudaFuncSetAttribute(hgemm3_kernel<true>,
                             cudaFuncAttributeMaxDynamicSharedMemorySize, HG_SMEM);
        attr_done = true;
    }

    // 0) fused prep: weights + value split + q split
    prep_all_kernel<<<PREP_NB, 256>>>(W_val, b_val, W_off, b_off,
                                      W_attn, b_attn, W_out, b_out,
                                      value, query, qpos);

    // 1) value projection: [MV,256] @ W_val -> g_vproj (fp32)
    hgemm3_kernel<false><<<dim3(MV / 128, CDIM / 64), 256, HG_SMEM>>>(
        valh, vall, wth, wtl, biasb, nullptr, vproj, MV, CDIM, CDIM);

    // 2) fused offsets+attn: q @ [W_off|W_attn] -> g_qa [MQ,576]
    hgemm3_kernel<false><<<dim3(MQ / 128, NQA / 64), 256, HG_SMEM>>>(
        qh, ql, wth + 256 * CDIM, wtl + 256 * CDIM, biasb + 256,
        nullptr, qa, MQ, NQA, CDIM);

    // 3) softmax + bilinear sampling -> g_ms hi/lo (bf16)
    sample_kernel<<<(MQ * NHEAD) / 8, 256>>>(refp);

    // 4) output projection + residual -> out
    hgemm3_kernel<true><<<dim3(MQ / 128, CDIM / 64), 256, HG_SMEM>>>(
        msh, msl, wth + 832 * CDIM, wtl + 832 * CDIM, biasb + 832,
        query, out, MQ, CDIM, CDIM);
}

// round 9
// speedup vs baseline: 1.0804x; 1.0804x over previous
#include <cuda_runtime.h>
#include <cuda_bf16.h>
#include <math.h>
#include <stdint.h>

// ---------------- problem constants (static per reference) ----------------
#define BSZ   8
#define NQ    4096
#define CDIM  256
#define NHEAD 8
#define NPT   4
#define NLVL  6
#define NVAL  10752
#define DHEAD 32
#define NOFF  384
#define NATT  192
#define NQA   576          // NOFF + NATT fused GEMM width
#define NWT   1088         // 256 (val) + 576 (off|attn) + 256 (out)
#define MQ    (BSZ * NQ)   // 32768
#define MV    (BSZ * NVAL) // 86016

// ---------------- device scratch (static, no allocation) ------------------
__device__ __nv_bfloat16 g_vbf [(size_t)MV * CDIM];    // vproj bf16, head-major
__device__ float g_qa   [(size_t)MQ * NQA];            // [off(384) | attn(192)]
__device__ __nv_bfloat16 g_val_h[(size_t)MV * CDIM];   // value, bf16 hi
__device__ __nv_bfloat16 g_val_l[(size_t)MV * CDIM];   // value, bf16 lo
__device__ __nv_bfloat16 g_q_h  [(size_t)MQ * CDIM];   // query+qpos hi
__device__ __nv_bfloat16 g_q_l  [(size_t)MQ * CDIM];   // query+qpos lo
__device__ __nv_bfloat16 g_ms_h [(size_t)MQ * CDIM];   // deform-attn out hi
__device__ __nv_bfloat16 g_ms_l [(size_t)MQ * CDIM];   // deform-attn out lo
__device__ __nv_bfloat16 g_Wt_hi[NWT * CDIM];          // all weights^T hi
__device__ __nv_bfloat16 g_Wt_lo[NWT * CDIM];          // all weights^T lo
__device__ float g_bias[NWT];

__constant__ int c_H[NLVL] = {64, 32, 16, 64, 32, 16};
__constant__ int c_W[NLVL] = {64, 32, 16, 64, 32, 16};
__constant__ int c_S[NLVL] = {0, 4096, 5120, 5376, 9472, 10496};

// ---------------- small helpers -------------------------------------------
__device__ __forceinline__ uint32_t smem_u32(const void* p) {
    uint32_t a;
    asm("{ .reg .u64 t; cvta.to.shared.u64 t, %1; cvt.u32.u64 %0, t; }"
        : "=r"(a) : "l"(p));
    return a;
}
__device__ __forceinline__ void ldsm_x4(uint32_t* r, uint32_t addr) {
    asm volatile("ldmatrix.sync.aligned.m8n8.x4.shared.b16 {%0,%1,%2,%3}, [%4];"
                 : "=r"(r[0]), "=r"(r[1]), "=r"(r[2]), "=r"(r[3]) : "r"(addr));
}
__device__ __forceinline__ void mma_bf16(float* c, const uint32_t* a,
                                         const uint32_t* b) {
    asm volatile(
        "mma.sync.aligned.m16n8k16.row.col.f32.bf16.bf16.f32 "
        "{%0,%1,%2,%3}, {%4,%5,%6,%7}, {%8,%9}, {%0,%1,%2,%3};"
        : "+f"(c[0]), "+f"(c[1]), "+f"(c[2]), "+f"(c[3])
        : "r"(a[0]), "r"(a[1]), "r"(a[2]), "r"(a[3]), "r"(b[0]), "r"(b[1]));
}
__device__ __forceinline__ uint32_t pack_bf16(float x, float y) {
    __nv_bfloat162 t = __halves2bfloat162(__float2bfloat16_rn(x),
                                          __float2bfloat16_rn(y));
    return *(uint32_t*)&t;
}
__device__ __forceinline__ void cp16(uint32_t dst, const void* src) {
    asm volatile("cp.async.cg.shared.global [%0], [%1], 16;"
                 :: "r"(dst), "l"(src));
}
#define CP_COMMIT() asm volatile("cp.async.commit_group;" ::: "memory")
#define CP_WAIT(n)  asm volatile("cp.async.wait_group %0;" :: "n"(n) : "memory")

// ============== fused prep: weights + value split + q split =================
#define PREP_B0 1088
#define PREP_B1 (PREP_B0 + (MV * CDIM / 4) / 256)   // 1088 + 21504
#define PREP_NB (PREP_B1 + (MQ * CDIM / 4) / 256)   // + 8192 = 30784

__global__ __launch_bounds__(256)
void prep_all_kernel(const float* __restrict__ W_val,
                     const float* __restrict__ b_val,
                     const float* __restrict__ W_off,
                     const float* __restrict__ b_off,
                     const float* __restrict__ W_attn,
                     const float* __restrict__ b_attn,
                     const float* __restrict__ W_out,
                     const float* __restrict__ b_out,
                     const float* __restrict__ value,
                     const float* __restrict__ query,
                     const float* __restrict__ qpos)
{
    const int bx = blockIdx.x;
    const int tid = threadIdx.x;
    if (bx < PREP_B0) {
        const int n = bx, k = tid;
        float x, bb;
        if (n < 256)      { x = W_val[k * 256 + n];          bb = b_val[n]; }
        else if (n < 832) {
            const int m = n - 256;
            if (m < 384)  { x = W_off[k * 384 + m];          bb = b_off[m]; }
            else          { x = W_attn[k * 192 + (m - 384)]; bb = b_attn[m - 384]; }
        }
        else              { x = W_out[k * 256 + (n - 832)];  bb = b_out[n - 832]; }
        const __nv_bfloat16 hi = __float2bfloat16_rn(x);
        const __nv_bfloat16 lo = __float2bfloat16_rn(x - __bfloat162float(hi));
        g_Wt_hi[n * CDIM + k] = hi;
        g_Wt_lo[n * CDIM + k] = lo;
        if (k == 0) g_bias[n] = bb;
        return;
    }
    float4 v;
    size_t i4;
    __nv_bfloat16 *H, *L;
    if (bx < PREP_B1) {
        i4 = (size_t)(bx - PREP_B0) * 256 + tid;
        v = ((const float4*)value)[i4];
        H = g_val_h; L = g_val_l;
    } else {
        i4 = (size_t)(bx - PREP_B1) * 256 + tid;
        v = ((const float4*)query)[i4];
        const float4 u = ((const float4*)qpos)[i4];
        v.x += u.x; v.y += u.y; v.z += u.z; v.w += u.w;
        H = g_q_h; L = g_q_l;
    }
    const float hx = __bfloat162float(__float2bfloat16_rn(v.x));
    const float hy = __bfloat162float(__float2bfloat16_rn(v.y));
    const float hz = __bfloat162float(__float2bfloat16_rn(v.z));
    const float hw = __bfloat162float(__float2bfloat16_rn(v.w));
    ((uint2*)H)[i4] = make_uint2(pack_bf16(v.x, v.y), pack_bf16(v.z, v.w));
    ((uint2*)L)[i4] = make_uint2(pack_bf16(v.x - hx, v.y - hy),
                                 pack_bf16(v.z - hz, v.w - hw));
}

// ============== bf16-split HMMA GEMM, 2-stage cp.async (round-7 core) ======
// MODE 0: C fp32            (qa GEMM)
// MODE 1: C fp32 + residual (out GEMM)
// MODE 2: C bf16 head-major [b][h][nv][32] (vproj GEMM)
#define HG_STG   30720
#define HG_SMEM  61440

template <int MODE>
__global__ __launch_bounds__(256)
void hgemm2_kernel(const __nv_bfloat16* __restrict__ Ath,
                   const __nv_bfloat16* __restrict__ Atl,
                   const __nv_bfloat16* __restrict__ Bth,
                   const __nv_bfloat16* __restrict__ Btl,
                   const float* __restrict__ bias,
                   const float* __restrict__ resid, float* __restrict__ Cf,
                   __nv_bfloat16* __restrict__ Cb,
                   int M, int N, int K)
{
    extern __shared__ __align__(16) uint8_t smem[];
    const uint32_t uS = smem_u32(smem);

    const int tid  = threadIdx.x;
    const int lane = tid & 31;
    const int wid  = tid >> 5;
    const int wm   = wid >> 1;
    const int wn   = wid & 1;
    const int bm   = blockIdx.x * 128;
    const int bn   = blockIdx.y * 64;
    const int KT   = K >> 5;           // 8

    const int lrA = ((lane >> 3) & 1) * 8 + (lane & 7);
    const int lkA = (lane >> 4) * 8;
    const uint32_t offAh = (uint32_t)((wm * 32 + lrA) * 80 + lkA * 2);
    const uint32_t offAl = offAh + 10240u;
    const int lrB = (lane >> 4) * 8 + (lane & 7);
    const int lkB = ((lane >> 3) & 1) * 8;
    const uint32_t offBh = 20480u + (uint32_t)((wn * 32 + lrB) * 80 + lkB * 2);
    const uint32_t offBl = offBh + 5120u;

    const int ar0 = tid >> 2, ac0 = tid & 3;
    const int ar1 = (tid + 256) >> 2;
    const int br  = tid >> 2, bc = tid & 3;

    float acc[2][4][4];
#pragma unroll
    for (int t = 0; t < 2; t++)
#pragma unroll
        for (int u = 0; u < 4; u++)
#pragma unroll
            for (int i = 0; i < 4; i++) acc[t][u][i] = 0.f;

    auto issue = [&](int kt, int buf) {
        const int k0 = kt * 32;
        const uint32_t base = uS + buf * HG_STG;
        const size_t oa0 = (size_t)(bm + ar0) * K + k0 + ac0 * 8;
        const size_t oa1 = (size_t)(bm + ar1) * K + k0 + ac0 * 8;
        const size_t ob  = (size_t)(bn + br ) * K + k0 + bc  * 8;
        cp16(base +          ar0 * 80 + ac0 * 16, Ath + oa0);
        cp16(base +          ar1 * 80 + ac0 * 16, Ath + oa1);
        cp16(base + 10240u + ar0 * 80 + ac0 * 16, Atl + oa0);
        cp16(base + 10240u + ar1 * 80 + ac0 * 16, Atl + oa1);
        cp16(base + 20480u + br  * 80 + bc  * 16, Bth + ob);
        cp16(base + 25600u + br  * 80 + bc  * 16, Btl + ob);
        CP_COMMIT();
    };

    issue(0, 0);
    issue(1, 1);

#pragma unroll 1
    for (int kt = 0; kt < KT; kt++) {
        if (kt == KT - 1) { CP_WAIT(0); } else { CP_WAIT(1); }
        __syncthreads();

        const uint32_t sb = uS + (kt & 1) * HG_STG;
#pragma unroll
        for (int ks = 0; ks < 2; ks++) {
            const uint32_t ko = ks * 32;
            uint32_t aH[2][4], aL[2][4], bH[4][2], bL[4][2];
            ldsm_x4(aH[0], sb + offAh + ko);
            ldsm_x4(aH[1], sb + offAh + 1280 + ko);
            ldsm_x4(aL[0], sb + offAl + ko);
            ldsm_x4(aL[1], sb + offAl + 1280 + ko);
            ldsm_x4(&bH[0][0], sb + offBh + ko);
            ldsm_x4(&bH[2][0], sb + offBh + 1280 + ko);
            ldsm_x4(&bL[0][0], sb + offBl + ko);
            ldsm_x4(&bL[2][0], sb + offBl + 1280 + ko);
#pragma unroll
            for (int t = 0; t < 2; t++)
#pragma unroll
                for (int u = 0; u < 4; u++) {
                    mma_bf16(acc[t][u], aH[t], bH[u]);
                    mma_bf16(acc[t][u], aH[t], bL[u]);
                    mma_bf16(acc[t][u], aL[t], bH[u]);
                }
        }
        __syncthreads();
        if (kt + 2 < KT) issue(kt + 2, kt & 1);
    }

    // ---- epilogue ----
    const int g = lane >> 2, tg = lane & 3;
    const int batch = bm / NVAL;               // 128 | 10752 -> CTA in one batch
    const int head  = (bn + wn * 32) >> 5;     // MODE 2 only (N=256)
#pragma unroll
    for (int t = 0; t < 2; t++)
#pragma unroll
        for (int u = 0; u < 4; u++) {
            const int row = bm + wm * 32 + t * 16 + g;
            const int col = bn + wn * 32 + u * 8 + tg * 2;
            const float2 bv = *(const float2*)(bias + col);
            float2 o0 = make_float2(acc[t][u][0] + bv.x, acc[t][u][1] + bv.y);
            float2 o1 = make_float2(acc[t][u][2] + bv.x, acc[t][u][3] + bv.y);
            if (MODE == 1) {
                const float2 r0 = *(const float2*)(resid + (size_t)row * N + col);
                const float2 r1 = *(const float2*)(resid + (size_t)(row + 8) * N + col);
                o0.x += r0.x; o0.y += r0.y;
                o1.x += r1.x; o1.y += r1.y;
            }
            if (MODE == 2) {
                const int nv = row - batch * NVAL;
                const int dim = u * 8 + tg * 2;
                const size_t base =
                    ((size_t)(batch * NHEAD + head) * NVAL + nv) * DHEAD + dim;
                *(uint32_t*)(Cb + base)              = pack_bf16(o0.x, o0.y);
                *(uint32_t*)(Cb + base + 8 * DHEAD)  = pack_bf16(o1.x, o1.y);
            } else {
                *(float2*)(Cf + (size_t)row * N + col) = o0;
                *(float2*)(Cf + (size_t)(row + 8) * N + col) = o1;
            }
        }
}

// ---------------- sampling kernel: bf16 head-major gather ------------------
__global__ __launch_bounds__(256)
void sample_kernel(const float* __restrict__ refp)
{
    __shared__ __align__(16) unsigned long long sm_iw[8][4][24]; // [warp][corner][point]

    const int wslot = threadIdx.x >> 5;
    const int warp = blockIdx.x * 8 + wslot;
    const int lane = threadIdx.x & 31;
    const int h  = warp & 7;
    const int bq = warp >> 3;
    const int b  = bq >> 12;

    float a = -INFINITY;
    if (lane < 24) a = g_qa[(size_t)bq * NQA + NOFF + h * 24 + lane];
    float m = a;
#pragma unroll
    for (int s = 16; s; s >>= 1) m = fmaxf(m, __shfl_xor_sync(0xffffffffu, m, s));
    float e = (lane < 24) ? __expf(a - m) : 0.f;
    float ssum = e;
#pragma unroll
    for (int s = 16; s; s >>= 1) ssum += __shfl_xor_sync(0xffffffffu, ssum, s);
    const float aw = e / ssum;

    if (lane < 24) {
        const int l = lane >> 2;
        const int p = lane & 3;
        const int H = c_H[l], W = c_W[l], S = c_S[l];
        const size_t ob = (size_t)bq * NQA + (((h * NLVL + l) * NPT + p) << 1);
        const float offx = g_qa[ob + 0];
        const float offy = g_qa[ob + 1];
        const size_t rb = ((size_t)bq * NLVL + l) << 1;
        const float rx = refp[rb + 0];
        const float ry = refp[rb + 1];
        const float x = rx * (float)W + offx - 0.5f;
        const float y = ry * (float)H + offy - 0.5f;
        const float xf = floorf(x), yf = floorf(y);
        const float lx = x - xf, ly = y - yf;
        const int ix = (int)xf, iy = (int)yf;
        const bool vx0 = (ix     >= 0) && (ix     < W);
        const bool vx1 = (ix + 1 >= 0) && (ix + 1 < W);
        const bool vy0 = (iy     >= 0) && (iy     < H);
        const bool vy1 = (iy + 1 >= 0) && (iy + 1 < H);
        const int cx0 = min(max(ix, 0), W - 1);
        const int cx1 = min(max(ix + 1, 0), W - 1);
        const int cy0 = min(max(iy, 0), H - 1);
        const int cy1 = min(max(iy + 1, 0), H - 1);
        // byte offsets into the (b,h) slice: idx * 32 bf16 * 2B = idx << 6
        const unsigned o00 = (unsigned)(S + cy0 * W + cx0) << 6;
        const unsigned o01 = (unsigned)(S + cy0 * W + cx1) << 6;
        const unsigned o10 = (unsigned)(S + cy1 * W + cx0) << 6;
        const unsigned o11 = (unsigned)(S + cy1 * W + cx1) << 6;
        const float w00 = aw * (1.f - lx) * (1.f - ly) * (float)(vx0 && vy0);
        const float w01 = aw * lx         * (1.f - ly) * (float)(vx1 && vy0);
        const float w10 = aw * (1.f - lx) * ly         * (float)(vx0 && vy1);
        const float w11 = aw * lx         * ly         * (float)(vx1 && vy1);
        sm_iw[wslot][0][lane] =
            (unsigned long long)o00 | ((unsigned long long)__float_as_uint(w00) << 32);
        sm_iw[wslot][1][lane] =
            (unsigned long long)o01 | ((unsigned long long)__float_as_uint(w01) << 32);
        sm_iw[wslot][2][lane] =
            (unsigned long long)o10 | ((unsigned long long)__float_as_uint(w10) << 32);
        sm_iw[wslot][3][lane] =
            (unsigned long long)o11 | ((unsigned long long)__float_as_uint(w11) << 32);
    }
    __syncwarp();

    const int g  = lane >> 3;          // corner group
    const int li = lane & 7;           // dim slice (4 channels)
    const char* __restrict__ vbb =
        (const char*)g_vbf + (size_t)(b * NHEAD + h) * NVAL * (DHEAD * 2) + li * 8;

    float4 acc0 = make_float4(0.f, 0.f, 0.f, 0.f);
    float4 acc1 = make_float4(0.f, 0.f, 0.f, 0.f);
#pragma unroll
    for (int j = 0; j < 12; j++) {
        const uint4 t = *(const uint4*)&sm_iw[wslot][g][2 * j];
        const float w0 = __uint_as_float(t.y);
        const float w1 = __uint_as_float(t.w);
        const uint2 v0 = *(const uint2*)(vbb + t.x);
        const uint2 v1 = *(const uint2*)(vbb + t.z);
        // bf16 -> fp32 via shift (low half = even channel)
        acc0.x = fmaf(w0, __uint_as_float(v0.x << 16),         acc0.x);
        acc0.y = fmaf(w0, __uint_as_float(v0.x & 0xffff0000u), acc0.y);
        acc0.z = fmaf(w0, __uint_as_float(v0.y << 16),         acc0.z);
        acc0.w = fmaf(w0, __uint_as_float(v0.y & 0xffff0000u), acc0.w);
        acc1.x = fmaf(w1, __uint_as_float(v1.x << 16),         acc1.x);
        acc1.y = fmaf(w1, __uint_as_float(v1.x & 0xffff0000u), acc1.y);
        acc1.z = fmaf(w1, __uint_as_float(v1.y << 16),         acc1.z);
        acc1.w = fmaf(w1, __uint_as_float(v1.y & 0xffff0000u), acc1.w);
    }
    float4 acc = make_float4(acc0.x + acc1.x, acc0.y + acc1.y,
                             acc0.z + acc1.z, acc0.w + acc1.w);
#pragma unroll
    for (int s = 8; s <= 16; s <<= 1) {
        acc.x += __shfl_xor_sync(0xffffffffu, acc.x, s);
        acc.y += __shfl_xor_sync(0xffffffffu, acc.y, s);
        acc.z += __shfl_xor_sync(0xffffffffu, acc.z, s);
        acc.w += __shfl_xor_sync(0xffffffffu, acc.w, s);
    }
    if (lane < 8) {
        const size_t o4 = ((size_t)bq * CDIM + h * DHEAD + lane * 4) >> 2;
        const float hx = __bfloat162float(__float2bfloat16_rn(acc.x));
        const float hy = __bfloat162float(__float2bfloat16_rn(acc.y));
        const float hz = __bfloat162float(__float2bfloat16_rn(acc.z));
        const float hw = __bfloat162float(__float2bfloat16_rn(acc.w));
        ((uint2*)g_ms_h)[o4] = make_uint2(pack_bf16(acc.x, acc.y),
                                          pack_bf16(acc.z, acc.w));
        ((uint2*)g_ms_l)[o4] = make_uint2(pack_bf16(acc.x - hx, acc.y - hy),
                                          pack_bf16(acc.z - hz, acc.w - hw));
    }
}

// ---------------- launch ----------------
extern "C" void kernel_launch(void* const* d_in, const int* in_sizes, int n_in,
                              void* d_out, int out_size)
{
    const float* query  = (const float*)d_in[0];
    const float* qpos   = (const float*)d_in[1];
    const float* value  = (const float*)d_in[2];
    const float* refp   = (const float*)d_in[3];
    const float* W_off  = (const float*)d_in[5];
    const float* b_off  = (const float*)d_in[6];
    const float* W_attn = (const float*)d_in[7];
    const float* b_attn = (const float*)d_in[8];
    const float* W_val  = (const float*)d_in[9];
    const float* b_val  = (const float*)d_in[10];
    const float* W_out  = (const float*)d_in[11];
    const float* b_out  = (const float*)d_in[12];
    float* out = (float*)d_out;

    float *qa, *biasb;
    __nv_bfloat16 *vbf, *wth, *wtl, *valh, *vall, *qh, *ql, *msh, *msl;
    cudaGetSymbolAddress((void**)&vbf,   g_vbf);
    cudaGetSymbolAddress((void**)&qa,    g_qa);
    cudaGetSymbolAddress((void**)&biasb, g_bias);
    cudaGetSymbolAddress((void**)&wth,   g_Wt_hi);
    cudaGetSymbolAddress((void**)&wtl,   g_Wt_lo);
    cudaGetSymbolAddress((void**)&valh,  g_val_h);
    cudaGetSymbolAddress((void**)&vall,  g_val_l);
    cudaGetSymbolAddress((void**)&qh,    g_q_h);
    cudaGetSymbolAddress((void**)&ql,    g_q_l);
    cudaGetSymbolAddress((void**)&msh,   g_ms_h);
    cudaGetSymbolAddress((void**)&msl,   g_ms_l);

    static bool attr_done = false;
    if (!attr_done) {
        cudaFuncSetAttribute(hgemm2_kernel<0>,
                             cudaFuncAttributeMaxDynamicSharedMemorySize, HG_SMEM);
        cudaFuncSetAttribute(hgemm2_kernel<1>,
                             cudaFuncAttributeMaxDynamicSharedMemorySize, HG_SMEM);
        cudaFuncSetAttribute(hgemm2_kernel<2>,
                             cudaFuncAttributeMaxDynamicSharedMemorySize, HG_SMEM);
        attr_done = true;
    }

    // 0) fused prep: weights + value split + q split
    prep_all_kernel<<<PREP_NB, 256>>>(W_val, b_val, W_off, b_off,
                                      W_attn, b_attn, W_out, b_out,
                                      value, query, qpos);

    // 1) value projection -> g_vbf (bf16 head-major)
    hgemm2_kernel<2><<<dim3(MV / 128, CDIM / 64), 256, HG_SMEM>>>(
        valh, vall, wth, wtl, biasb, nullptr, nullptr, vbf, MV, CDIM, CDIM);

    // 2) fused offsets+attn: q @ [W_off|W_attn] -> g_qa [MQ,576]
    hgemm2_kernel<0><<<dim3(MQ / 128, NQA / 64), 256, HG_SMEM>>>(
        qh, ql, wth + 256 * CDIM, wtl + 256 * CDIM, biasb + 256,
        nullptr, qa, nullptr, MQ, NQA, CDIM);

    // 3) softmax + bilinear sampling -> g_ms hi/lo (bf16)
    sample_kernel<<<(MQ * NHEAD) / 8, 256>>>(refp);

    // 4) output projection + residual -> out
    hgemm2_kernel<1><<<dim3(MQ / 128, CDIM / 64), 256, HG_SMEM>>>(
        msh, msl, wth + 832 * CDIM, wtl + 832 * CDIM, biasb + 832,
        query, out, nullptr, MQ, CDIM, CDIM);
}

// round 10
// speedup vs baseline: 1.1067x; 1.0244x over previous
#include <cuda_runtime.h>
#include <cuda_bf16.h>
#include <math.h>
#include <stdint.h>

// ---------------- problem constants (static per reference) ----------------
#define BSZ   8
#define NQ    4096
#define CDIM  256
#define NHEAD 8
#define NPT   4
#define NLVL  6
#define NVAL  10752
#define DHEAD 32
#define NOFF  384
#define NATT  192
#define NQA   576          // NOFF + NATT fused GEMM width
#define NWT   1088         // 256 (val) + 576 (off|attn) + 256 (out)
#define MQ    (BSZ * NQ)   // 32768
#define MV    (BSZ * NVAL) // 86016

// ---------------- device scratch (static, no allocation) ------------------
__device__ __nv_bfloat16 g_vbf [(size_t)MV * CDIM];    // vproj bf16, head-major
__device__ float g_qa   [(size_t)MQ * NQA];            // [off(384) | attn(192)]
__device__ __nv_bfloat16 g_val_h[(size_t)MV * CDIM];   // value, bf16 hi
__device__ __nv_bfloat16 g_val_l[(size_t)MV * CDIM];   // value, bf16 lo
__device__ __nv_bfloat16 g_q_h  [(size_t)MQ * CDIM];   // query+qpos hi
__device__ __nv_bfloat16 g_q_l  [(size_t)MQ * CDIM];   // query+qpos lo
__device__ __nv_bfloat16 g_ms_h [(size_t)MQ * CDIM];   // deform-attn out hi
__device__ __nv_bfloat16 g_ms_l [(size_t)MQ * CDIM];   // deform-attn out lo
__device__ __nv_bfloat16 g_Wt_hi[NWT * CDIM];          // all weights^T hi
__device__ __nv_bfloat16 g_Wt_lo[NWT * CDIM];          // all weights^T lo
__device__ float g_bias[NWT];

__constant__ int c_H[NLVL] = {64, 32, 16, 64, 32, 16};
__constant__ int c_W[NLVL] = {64, 32, 16, 64, 32, 16};
__constant__ int c_S[NLVL] = {0, 4096, 5120, 5376, 9472, 10496};

// ---------------- small helpers -------------------------------------------
__device__ __forceinline__ uint32_t smem_u32(const void* p) {
    uint32_t a;
    asm("{ .reg .u64 t; cvta.to.shared.u64 t, %1; cvt.u32.u64 %0, t; }"
        : "=r"(a) : "l"(p));
    return a;
}
__device__ __forceinline__ void ldsm_x4(uint32_t* r, uint32_t addr) {
    asm volatile("ldmatrix.sync.aligned.m8n8.x4.shared.b16 {%0,%1,%2,%3}, [%4];"
                 : "=r"(r[0]), "=r"(r[1]), "=r"(r[2]), "=r"(r[3]) : "r"(addr));
}
__device__ __forceinline__ void mma_bf16(float* c, const uint32_t* a,
                                         const uint32_t* b) {
    asm volatile(
        "mma.sync.aligned.m16n8k16.row.col.f32.bf16.bf16.f32 "
        "{%0,%1,%2,%3}, {%4,%5,%6,%7}, {%8,%9}, {%0,%1,%2,%3};"
        : "+f"(c[0]), "+f"(c[1]), "+f"(c[2]), "+f"(c[3])
        : "r"(a[0]), "r"(a[1]), "r"(a[2]), "r"(a[3]), "r"(b[0]), "r"(b[1]));
}
__device__ __forceinline__ uint32_t pack_bf16(float x, float y) {
    __nv_bfloat162 t = __halves2bfloat162(__float2bfloat16_rn(x),
                                          __float2bfloat16_rn(y));
    return *(uint32_t*)&t;
}
__device__ __forceinline__ void cp16(uint32_t dst, const void* src) {
    asm volatile("cp.async.cg.shared.global [%0], [%1], 16;"
                 :: "r"(dst), "l"(src));
}
#define CP_COMMIT() asm volatile("cp.async.commit_group;" ::: "memory")
#define CP_WAIT(n)  asm volatile("cp.async.wait_group %0;" :: "n"(n) : "memory")

// ============== prep branch A: weights + q split ============================
// blocks [0,1088): weight transpose + hi/lo split + bias concat
// blocks [1088, 1088+8192): (query+qpos) hi/lo split
#define PQW_B0 1088
#define PQW_NB (PQW_B0 + (MQ * CDIM / 4) / 256)     // 1088 + 8192 = 9280

__global__ __launch_bounds__(256)
void prep_qw_kernel(const float* __restrict__ W_val,
                    const float* __restrict__ b_val,
                    const float* __restrict__ W_off,
                    const float* __restrict__ b_off,
                    const float* __restrict__ W_attn,
                    const float* __restrict__ b_attn,
                    const float* __restrict__ W_out,
                    const float* __restrict__ b_out,
                    const float* __restrict__ query,
                    const float* __restrict__ qpos)
{
    const int bx = blockIdx.x;
    const int tid = threadIdx.x;
    if (bx < PQW_B0) {
        const int n = bx, k = tid;
        float x, bb;
        if (n < 256)      { x = W_val[k * 256 + n];          bb = b_val[n]; }
        else if (n < 832) {
            const int m = n - 256;
            if (m < 384)  { x = W_off[k * 384 + m];          bb = b_off[m]; }
            else          { x = W_attn[k * 192 + (m - 384)]; bb = b_attn[m - 384]; }
        }
        else              { x = W_out[k * 256 + (n - 832)];  bb = b_out[n - 832]; }
        const __nv_bfloat16 hi = __float2bfloat16_rn(x);
        const __nv_bfloat16 lo = __float2bfloat16_rn(x - __bfloat162float(hi));
        g_Wt_hi[n * CDIM + k] = hi;
        g_Wt_lo[n * CDIM + k] = lo;
        if (k == 0) g_bias[n] = bb;
        return;
    }
    const size_t i4 = (size_t)(bx - PQW_B0) * 256 + tid;
    float4 v = ((const float4*)query)[i4];
    const float4 u = ((const float4*)qpos)[i4];
    v.x += u.x; v.y += u.y; v.z += u.z; v.w += u.w;
    const float hx = __bfloat162float(__float2bfloat16_rn(v.x));
    const float hy = __bfloat162float(__float2bfloat16_rn(v.y));
    const float hz = __bfloat162float(__float2bfloat16_rn(v.z));
    const float hw = __bfloat162float(__float2bfloat16_rn(v.w));
    ((uint2*)g_q_h)[i4] = make_uint2(pack_bf16(v.x, v.y), pack_bf16(v.z, v.w));
    ((uint2*)g_q_l)[i4] = make_uint2(pack_bf16(v.x - hx, v.y - hy),
                                     pack_bf16(v.z - hz, v.w - hw));
}

// ============== prep branch B: value split ==================================
#define PV_NB ((MV * CDIM / 4) / 256)               // 21504

__global__ __launch_bounds__(256)
void prep_v_kernel(const float* __restrict__ value)
{
    const size_t i4 = (size_t)blockIdx.x * 256 + threadIdx.x;
    const float4 v = ((const float4*)value)[i4];
    const float hx = __bfloat162float(__float2bfloat16_rn(v.x));
    const float hy = __bfloat162float(__float2bfloat16_rn(v.y));
    const float hz = __bfloat162float(__float2bfloat16_rn(v.z));
    const float hw = __bfloat162float(__float2bfloat16_rn(v.w));
    ((uint2*)g_val_h)[i4] = make_uint2(pack_bf16(v.x, v.y), pack_bf16(v.z, v.w));
    ((uint2*)g_val_l)[i4] = make_uint2(pack_bf16(v.x - hx, v.y - hy),
                                       pack_bf16(v.z - hz, v.w - hw));
}

// ============== bf16-split HMMA GEMM, 2-stage cp.async =====================
// MODE 0: C fp32            (qa GEMM)
// MODE 1: C fp32 + residual (out GEMM)
// MODE 2: C bf16 head-major [b][h][nv][32] (vproj GEMM)
#define HG_STG   30720
#define HG_SMEM  61440

template <int MODE>
__global__ __launch_bounds__(256)
void hgemm2_kernel(const __nv_bfloat16* __restrict__ Ath,
                   const __nv_bfloat16* __restrict__ Atl,
                   const __nv_bfloat16* __restrict__ Bth,
                   const __nv_bfloat16* __restrict__ Btl,
                   const float* __restrict__ bias,
                   const float* __restrict__ resid, float* __restrict__ Cf,
                   __nv_bfloat16* __restrict__ Cb,
                   int M, int N, int K)
{
    extern __shared__ __align__(16) uint8_t smem[];
    const uint32_t uS = smem_u32(smem);

    const int tid  = threadIdx.x;
    const int lane = tid & 31;
    const int wid  = tid >> 5;
    const int wm   = wid >> 1;
    const int wn   = wid & 1;
    const int bm   = blockIdx.x * 128;
    const int bn   = blockIdx.y * 64;
    const int KT   = K >> 5;           // 8

    const int lrA = ((lane >> 3) & 1) * 8 + (lane & 7);
    const int lkA = (lane >> 4) * 8;
    const uint32_t offAh = (uint32_t)((wm * 32 + lrA) * 80 + lkA * 2);
    const uint32_t offAl = offAh + 10240u;
    const int lrB = (lane >> 4) * 8 + (lane & 7);
    const int lkB = ((lane >> 3) & 1) * 8;
    const uint32_t offBh = 20480u + (uint32_t)((wn * 32 + lrB) * 80 + lkB * 2);
    const uint32_t offBl = offBh + 5120u;

    const int ar0 = tid >> 2, ac0 = tid & 3;
    const int ar1 = (tid + 256) >> 2;
    const int br  = tid >> 2, bc = tid & 3;

    float acc[2][4][4];
#pragma unroll
    for (int t = 0; t < 2; t++)
#pragma unroll
        for (int u = 0; u < 4; u++)
#pragma unroll
            for (int i = 0; i < 4; i++) acc[t][u][i] = 0.f;

    auto issue = [&](int kt, int buf) {
        const int k0 = kt * 32;
        const uint32_t base = uS + buf * HG_STG;
        const size_t oa0 = (size_t)(bm + ar0) * K + k0 + ac0 * 8;
        const size_t oa1 = (size_t)(bm + ar1) * K + k0 + ac0 * 8;
        const size_t ob  = (size_t)(bn + br ) * K + k0 + bc  * 8;
        cp16(base +          ar0 * 80 + ac0 * 16, Ath + oa0);
        cp16(base +          ar1 * 80 + ac0 * 16, Ath + oa1);
        cp16(base + 10240u + ar0 * 80 + ac0 * 16, Atl + oa0);
        cp16(base + 10240u + ar1 * 80 + ac0 * 16, Atl + oa1);
        cp16(base + 20480u + br  * 80 + bc  * 16, Bth + ob);
        cp16(base + 25600u + br  * 80 + bc  * 16, Btl + ob);
        CP_COMMIT();
    };

    issue(0, 0);
    issue(1, 1);

#pragma unroll 1
    for (int kt = 0; kt < KT; kt++) {
        if (kt == KT - 1) { CP_WAIT(0); } else { CP_WAIT(1); }
        __syncthreads();

        const uint32_t sb = uS + (kt & 1) * HG_STG;
#pragma unroll
        for (int ks = 0; ks < 2; ks++) {
            const uint32_t ko = ks * 32;
            uint32_t aH[2][4], aL[2][4], bH[4][2], bL[4][2];
            ldsm_x4(aH[0], sb + offAh + ko);
            ldsm_x4(aH[1], sb + offAh + 1280 + ko);
            ldsm_x4(aL[0], sb + offAl + ko);
            ldsm_x4(aL[1], sb + offAl + 1280 + ko);
            ldsm_x4(&bH[0][0], sb + offBh + ko);
            ldsm_x4(&bH[2][0], sb + offBh + 1280 + ko);
            ldsm_x4(&bL[0][0], sb + offBl + ko);
            ldsm_x4(&bL[2][0], sb + offBl + 1280 + ko);
#pragma unroll
            for (int t = 0; t < 2; t++)
#pragma unroll
                for (int u = 0; u < 4; u++) {
                    mma_bf16(acc[t][u], aH[t], bH[u]);
                    mma_bf16(acc[t][u], aH[t], bL[u]);
                    mma_bf16(acc[t][u], aL[t], bH[u]);
                }
        }
        __syncthreads();
        if (kt + 2 < KT) issue(kt + 2, kt & 1);
    }

    // ---- epilogue ----
    const int g = lane >> 2, tg = lane & 3;
    const int batch = bm / NVAL;
    const int head  = (bn + wn * 32) >> 5;     // MODE 2 only (N=256)
#pragma unroll
    for (int t = 0; t < 2; t++)
#pragma unroll
        for (int u = 0; u < 4; u++) {
            const int row = bm + wm * 32 + t * 16 + g;
            const int col = bn + wn * 32 + u * 8 + tg * 2;
            const float2 bv = *(const float2*)(bias + col);
            float2 o0 = make_float2(acc[t][u][0] + bv.x, acc[t][u][1] + bv.y);
            float2 o1 = make_float2(acc[t][u][2] + bv.x, acc[t][u][3] + bv.y);
            if (MODE == 1) {
                const float2 r0 = *(const float2*)(resid + (size_t)row * N + col);
                const float2 r1 = *(const float2*)(resid + (size_t)(row + 8) * N + col);
                o0.x += r0.x; o0.y += r0.y;
                o1.x += r1.x; o1.y += r1.y;
            }
            if (MODE == 2) {
                const int nv = row - batch * NVAL;
                const int dim = u * 8 + tg * 2;
                const size_t base =
                    ((size_t)(batch * NHEAD + head) * NVAL + nv) * DHEAD + dim;
                *(uint32_t*)(Cb + base)              = pack_bf16(o0.x, o0.y);
                *(uint32_t*)(Cb + base + 8 * DHEAD)  = pack_bf16(o1.x, o1.y);
            } else {
                *(float2*)(Cf + (size_t)row * N + col) = o0;
                *(float2*)(Cf + (size_t)(row + 8) * N + col) = o1;
            }
        }
}

// ---------------- sampling kernel: bf16 head-major gather ------------------
__global__ __launch_bounds__(256)
void sample_kernel(const float* __restrict__ refp)
{
    __shared__ __align__(16) unsigned long long sm_iw[8][4][24]; // [warp][corner][point]

    const int wslot = threadIdx.x >> 5;
    const int warp = blockIdx.x * 8 + wslot;
    const int lane = threadIdx.x & 31;
    const int h  = warp & 7;
    const int bq = warp >> 3;
    const int b  = bq >> 12;

    float a = -INFINITY;
    if (lane < 24) a = g_qa[(size_t)bq * NQA + NOFF + h * 24 + lane];
    float m = a;
#pragma unroll
    for (int s = 16; s; s >>= 1) m = fmaxf(m, __shfl_xor_sync(0xffffffffu, m, s));
    float e = (lane < 24) ? __expf(a - m) : 0.f;
    float ssum = e;
#pragma unroll
    for (int s = 16; s; s >>= 1) ssum += __shfl_xor_sync(0xffffffffu, ssum, s);
    const float aw = e / ssum;

    if (lane < 24) {
        const int l = lane >> 2;
        const int p = lane & 3;
        const int H = c_H[l], W = c_W[l], S = c_S[l];
        const size_t ob = (size_t)bq * NQA + (((h * NLVL + l) * NPT + p) << 1);
        const float offx = g_qa[ob + 0];
        const float offy = g_qa[ob + 1];
        const size_t rb = ((size_t)bq * NLVL + l) << 1;
        const float rx = refp[rb + 0];
        const float ry = refp[rb + 1];
        const float x = rx * (float)W + offx - 0.5f;
        const float y = ry * (float)H + offy - 0.5f;
        const float xf = floorf(x), yf = floorf(y);
        const float lx = x - xf, ly = y - yf;
        const int ix = (int)xf, iy = (int)yf;
        const bool vx0 = (ix     >= 0) && (ix     < W);
        const bool vx1 = (ix + 1 >= 0) && (ix + 1 < W);
        const bool vy0 = (iy     >= 0) && (iy     < H);
        const bool vy1 = (iy + 1 >= 0) && (iy + 1 < H);
        const int cx0 = min(max(ix, 0), W - 1);
        const int cx1 = min(max(ix + 1, 0), W - 1);
        const int cy0 = min(max(iy, 0), H - 1);
        const int cy1 = min(max(iy + 1, 0), H - 1);
        const unsigned o00 = (unsigned)(S + cy0 * W + cx0) << 6;
        const unsigned o01 = (unsigned)(S + cy0 * W + cx1) << 6;
        const unsigned o10 = (unsigned)(S + cy1 * W + cx0) << 6;
        const unsigned o11 = (unsigned)(S + cy1 * W + cx1) << 6;
        const float w00 = aw * (1.f - lx) * (1.f - ly) * (float)(vx0 && vy0);
        const float w01 = aw * lx         * (1.f - ly) * (float)(vx1 && vy0);
        const float w10 = aw * (1.f - lx) * ly         * (float)(vx0 && vy1);
        const float w11 = aw * lx         * ly         * (float)(vx1 && vy1);
        sm_iw[wslot][0][lane] =
            (unsigned long long)o00 | ((unsigned long long)__float_as_uint(w00) << 32);
        sm_iw[wslot][1][lane] =
            (unsigned long long)o01 | ((unsigned long long)__float_as_uint(w01) << 32);
        sm_iw[wslot][2][lane] =
            (unsigned long long)o10 | ((unsigned long long)__float_as_uint(w10) << 32);
        sm_iw[wslot][3][lane] =
            (unsigned long long)o11 | ((unsigned long long)__float_as_uint(w11) << 32);
    }
    __syncwarp();

    const int g  = lane >> 3;          // corner group
    const int li = lane & 7;           // dim slice (4 channels)
    const char* __restrict__ vbb =
        (const char*)g_vbf + (size_t)(b * NHEAD + h) * NVAL * (DHEAD * 2) + li * 8;

    float4 acc0 = make_float4(0.f, 0.f, 0.f, 0.f);
    float4 acc1 = make_float4(0.f, 0.f, 0.f, 0.f);
#pragma unroll
    for (int j = 0; j < 12; j++) {
        const uint4 t = *(const uint4*)&sm_iw[wslot][g][2 * j];
        const float w0 = __uint_as_float(t.y);
        const float w1 = __uint_as_float(t.w);
        const uint2 v0 = *(const uint2*)(vbb + t.x);
        const uint2 v1 = *(const uint2*)(vbb + t.z);
        acc0.x = fmaf(w0, __uint_as_float(v0.x << 16),         acc0.x);
        acc0.y = fmaf(w0, __uint_as_float(v0.x & 0xffff0000u), acc0.y);
        acc0.z = fmaf(w0, __uint_as_float(v0.y << 16),         acc0.z);
        acc0.w = fmaf(w0, __uint_as_float(v0.y & 0xffff0000u), acc0.w);
        acc1.x = fmaf(w1, __uint_as_float(v1.x << 16),         acc1.x);
        acc1.y = fmaf(w1, __uint_as_float(v1.x & 0xffff0000u), acc1.y);
        acc1.z = fmaf(w1, __uint_as_float(v1.y << 16),         acc1.z);
        acc1.w = fmaf(w1, __uint_as_float(v1.y & 0xffff0000u), acc1.w);
    }
    float4 acc = make_float4(acc0.x + acc1.x, acc0.y + acc1.y,
                             acc0.z + acc1.z, acc0.w + acc1.w);
#pragma unroll
    for (int s = 8; s <= 16; s <<= 1) {
        acc.x += __shfl_xor_sync(0xffffffffu, acc.x, s);
        acc.y += __shfl_xor_sync(0xffffffffu, acc.y, s);
        acc.z += __shfl_xor_sync(0xffffffffu, acc.z, s);
        acc.w += __shfl_xor_sync(0xffffffffu, acc.w, s);
    }
    if (lane < 8) {
        const size_t o4 = ((size_t)bq * CDIM + h * DHEAD + lane * 4) >> 2;
        const float hx = __bfloat162float(__float2bfloat16_rn(acc.x));
        const float hy = __bfloat162float(__float2bfloat16_rn(acc.y));
        const float hz = __bfloat162float(__float2bfloat16_rn(acc.z));
        const float hw = __bfloat162float(__float2bfloat16_rn(acc.w));
        ((uint2*)g_ms_h)[o4] = make_uint2(pack_bf16(acc.x, acc.y),
                                          pack_bf16(acc.z, acc.w));
        ((uint2*)g_ms_l)[o4] = make_uint2(pack_bf16(acc.x - hx, acc.y - hy),
                                          pack_bf16(acc.z - hz, acc.w - hw));
    }
}

// ---------------- launch ----------------
extern "C" void kernel_launch(void* const* d_in, const int* in_sizes, int n_in,
                              void* d_out, int out_size)
{
    const float* query  = (const float*)d_in[0];
    const float* qpos   = (const float*)d_in[1];
    const float* value  = (const float*)d_in[2];
    const float* refp   = (const float*)d_in[3];
    const float* W_off  = (const float*)d_in[5];
    const float* b_off  = (const float*)d_in[6];
    const float* W_attn = (const float*)d_in[7];
    const float* b_attn = (const float*)d_in[8];
    const float* W_val  = (const float*)d_in[9];
    const float* b_val  = (const float*)d_in[10];
    const float* W_out  = (const float*)d_in[11];
    const float* b_out  = (const float*)d_in[12];
    float* out = (float*)d_out;

    float *qa, *biasb;
    __nv_bfloat16 *vbf, *wth, *wtl, *valh, *vall, *qh, *ql, *msh, *msl;
    cudaGetSymbolAddress((void**)&vbf,   g_vbf);
    cudaGetSymbolAddress((void**)&qa,    g_qa);
    cudaGetSymbolAddress((void**)&biasb, g_bias);
    cudaGetSymbolAddress((void**)&wth,   g_Wt_hi);
    cudaGetSymbolAddress((void**)&wtl,   g_Wt_lo);
    cudaGetSymbolAddress((void**)&valh,  g_val_h);
    cudaGetSymbolAddress((void**)&vall,  g_val_l);
    cudaGetSymbolAddress((void**)&qh,    g_q_h);
    cudaGetSymbolAddress((void**)&ql,    g_q_l);
    cudaGetSymbolAddress((void**)&msh,   g_ms_h);
    cudaGetSymbolAddress((void**)&msl,   g_ms_l);

    static cudaStream_t s2 = nullptr;
    static cudaEvent_t evFork = nullptr, evJoin = nullptr;
    if (!s2) {
        cudaFuncSetAttribute(hgemm2_kernel<0>,
                             cudaFuncAttributeMaxDynamicSharedMemorySize, HG_SMEM);
        cudaFuncSetAttribute(hgemm2_kernel<1>,
                             cudaFuncAttributeMaxDynamicSharedMemorySize, HG_SMEM);
        cudaFuncSetAttribute(hgemm2_kernel<2>,
                             cudaFuncAttributeMaxDynamicSharedMemorySize, HG_SMEM);
        cudaStreamCreateWithFlags(&s2, cudaStreamNonBlocking);
        cudaEventCreateWithFlags(&evFork, cudaEventDisableTiming);
        cudaEventCreateWithFlags(&evJoin, cudaEventDisableTiming);
    }

    // ---- fork: branch B (value chain) on s2 ----
    cudaEventRecord(evFork, 0);
    cudaStreamWaitEvent(s2, evFork, 0);
    prep_v_kernel<<<PV_NB, 256, 0, s2>>>(value);
    hgemm2_kernel<2><<<dim3(MV / 128, CDIM / 64), 256, HG_SMEM, s2>>>(
        valh, vall, wth, wtl, biasb, nullptr, nullptr, vbf, MV, CDIM, CDIM);
    cudaEventRecord(evJoin, s2);

    // ---- branch A (query chain) on stream 0, concurrent with branch B ----
    prep_qw_kernel<<<PQW_NB, 256>>>(W_val, b_val, W_off, b_off,
                                    W_attn, b_attn, W_out, b_out, query, qpos);
    hgemm2_kernel<0><<<dim3(MQ / 128, NQA / 64), 256, HG_SMEM>>>(
        qh, ql, wth + 256 * CDIM, wtl + 256 * CDIM, biasb + 256,
        nullptr, qa, nullptr, MQ, NQA, CDIM);

    // ---- join, then sampler + out GEMM ----
    cudaStreamWaitEvent(0, evJoin, 0);
    sample_kernel<<<(MQ * NHEAD) / 8, 256>>>(refp);
    hgemm2_kernel<1><<<dim3(MQ / 128, CDIM / 64), 256, HG_SMEM>>>(
        msh, msl, wth + 832 * CDIM, wtl + 832 * CDIM, biasb + 832,
        query, out, nullptr, MQ, CDIM, CDIM);
}

// round 11
// speedup vs baseline: 1.1921x; 1.0772x over previous
#include <cuda_runtime.h>
#include <cuda_bf16.h>
#include <math.h>
#include <stdint.h>

// ---------------- problem constants (static per reference) ----------------
#define BSZ   8
#define NQ    4096
#define CDIM  256
#define NHEAD 8
#define NPT   4
#define NLVL  6
#define NVAL  10752
#define DHEAD 32
#define NOFF  384
#define NATT  192
#define NQA   576          // NOFF + NATT fused GEMM width
#define NWT   1088         // 256 (val) + 576 (off|attn) + 256 (out)
#define MQ    (BSZ * NQ)   // 32768
#define MV    (BSZ * NVAL) // 86016

// ---------------- device scratch (static, no allocation) ------------------
__device__ __nv_bfloat16 g_vbf [(size_t)MV * CDIM];    // vproj bf16, head-major
__device__ float g_qa   [(size_t)MQ * NQA];            // [off(384) | attn(192)]
__device__ __nv_bfloat16 g_val_h[(size_t)MV * CDIM];   // value, bf16 hi
__device__ __nv_bfloat16 g_val_l[(size_t)MV * CDIM];   // value, bf16 lo
__device__ __nv_bfloat16 g_q_h  [(size_t)MQ * CDIM];   // query+qpos hi
__device__ __nv_bfloat16 g_q_l  [(size_t)MQ * CDIM];   // query+qpos lo
__device__ __nv_bfloat16 g_ms_h [(size_t)MQ * CDIM];   // deform-attn out hi
__device__ __nv_bfloat16 g_ms_l [(size_t)MQ * CDIM];   // deform-attn out lo
__device__ __nv_bfloat16 g_Wt_hi[NWT * CDIM];          // all weights^T hi
__device__ __nv_bfloat16 g_Wt_lo[NWT * CDIM];          // all weights^T lo
__device__ float g_bias[NWT];

__constant__ int c_H[NLVL] = {64, 32, 16, 64, 32, 16};
__constant__ int c_W[NLVL] = {64, 32, 16, 64, 32, 16};
__constant__ int c_S[NLVL] = {0, 4096, 5120, 5376, 9472, 10496};

// ---------------- small helpers -------------------------------------------
__device__ __forceinline__ uint32_t smem_u32(const void* p) {
    uint32_t a;
    asm("{ .reg .u64 t; cvta.to.shared.u64 t, %1; cvt.u32.u64 %0, t; }"
        : "=r"(a) : "l"(p));
    return a;
}
__device__ __forceinline__ void ldsm_x4(uint32_t* r, uint32_t addr) {
    asm volatile("ldmatrix.sync.aligned.m8n8.x4.shared.b16 {%0,%1,%2,%3}, [%4];"
                 : "=r"(r[0]), "=r"(r[1]), "=r"(r[2]), "=r"(r[3]) : "r"(addr));
}
__device__ __forceinline__ void mma_bf16(float* c, const uint32_t* a,
                                         const uint32_t* b) {
    asm volatile(
        "mma.sync.aligned.m16n8k16.row.col.f32.bf16.bf16.f32 "
        "{%0,%1,%2,%3}, {%4,%5,%6,%7}, {%8,%9}, {%0,%1,%2,%3};"
        : "+f"(c[0]), "+f"(c[1]), "+f"(c[2]), "+f"(c[3])
        : "r"(a[0]), "r"(a[1]), "r"(a[2]), "r"(a[3]), "r"(b[0]), "r"(b[1]));
}
__device__ __forceinline__ uint32_t pack_bf16(float x, float y) {
    __nv_bfloat162 t = __halves2bfloat162(__float2bfloat16_rn(x),
                                          __float2bfloat16_rn(y));
    return *(uint32_t*)&t;
}
__device__ __forceinline__ void cp16(uint32_t dst, const void* src) {
    asm volatile("cp.async.cg.shared.global [%0], [%1], 16;"
                 :: "r"(dst), "l"(src));
}
#define CP_COMMIT() asm volatile("cp.async.commit_group;" ::: "memory")
#define CP_WAIT(n)  asm volatile("cp.async.wait_group %0;" :: "n"(n) : "memory")

// ============== prep branch A: weights + q split ============================
#define PQW_B0 1088
#define PQW_NB (PQW_B0 + (MQ * CDIM / 4) / 256)     // 1088 + 8192 = 9280

__global__ __launch_bounds__(256)
void prep_qw_kernel(const float* __restrict__ W_val,
                    const float* __restrict__ b_val,
                    const float* __restrict__ W_off,
                    const float* __restrict__ b_off,
                    const float* __restrict__ W_attn,
                    const float* __restrict__ b_attn,
                    const float* __restrict__ W_out,
                    const float* __restrict__ b_out,
                    const float* __restrict__ query,
                    const float* __restrict__ qpos)
{
    const int bx = blockIdx.x;
    const int tid = threadIdx.x;
    if (bx < PQW_B0) {
        const int n = bx, k = tid;
        float x, bb;
        if (n < 256)      { x = W_val[k * 256 + n];          bb = b_val[n]; }
        else if (n < 832) {
            const int m = n - 256;
            if (m < 384)  { x = W_off[k * 384 + m];          bb = b_off[m]; }
            else          { x = W_attn[k * 192 + (m - 384)]; bb = b_attn[m - 384]; }
        }
        else              { x = W_out[k * 256 + (n - 832)];  bb = b_out[n - 832]; }
        const __nv_bfloat16 hi = __float2bfloat16_rn(x);
        const __nv_bfloat16 lo = __float2bfloat16_rn(x - __bfloat162float(hi));
        g_Wt_hi[n * CDIM + k] = hi;
        g_Wt_lo[n * CDIM + k] = lo;
        if (k == 0) g_bias[n] = bb;
        return;
    }
    const size_t i4 = (size_t)(bx - PQW_B0) * 256 + tid;
    float4 v = ((const float4*)query)[i4];
    const float4 u = ((const float4*)qpos)[i4];
    v.x += u.x; v.y += u.y; v.z += u.z; v.w += u.w;
    const float hx = __bfloat162float(__float2bfloat16_rn(v.x));
    const float hy = __bfloat162float(__float2bfloat16_rn(v.y));
    const float hz = __bfloat162float(__float2bfloat16_rn(v.z));
    const float hw = __bfloat162float(__float2bfloat16_rn(v.w));
    ((uint2*)g_q_h)[i4] = make_uint2(pack_bf16(v.x, v.y), pack_bf16(v.z, v.w));
    ((uint2*)g_q_l)[i4] = make_uint2(pack_bf16(v.x - hx, v.y - hy),
                                     pack_bf16(v.z - hz, v.w - hw));
}

// ============== prep branch B: value split ==================================
#define PV_NB ((MV * CDIM / 4) / 256)               // 21504

__global__ __launch_bounds__(256)
void prep_v_kernel(const float* __restrict__ value)
{
    const size_t i4 = (size_t)blockIdx.x * 256 + threadIdx.x;
    const float4 v = ((const float4*)value)[i4];
    const float hx = __bfloat162float(__float2bfloat16_rn(v.x));
    const float hy = __bfloat162float(__float2bfloat16_rn(v.y));
    const float hz = __bfloat162float(__float2bfloat16_rn(v.z));
    const float hw = __bfloat162float(__float2bfloat16_rn(v.w));
    ((uint2*)g_val_h)[i4] = make_uint2(pack_bf16(v.x, v.y), pack_bf16(v.z, v.w));
    ((uint2*)g_val_l)[i4] = make_uint2(pack_bf16(v.x - hx, v.y - hy),
                                       pack_bf16(v.z - hz, v.w - hw));
}

// ============== bf16-split HMMA GEMM, 2-stage cp.async, XOR-swizzled ========
// MODE 0: C fp32            (qa GEMM)
// MODE 1: C fp32 + residual (out GEMM)
// MODE 2: C bf16 head-major [b][h][nv][32] (vproj GEMM)
// Layout per stage: Ah[128x64B] | Al | Bh[64x64B] | Bl, 64B pitch,
// phys_chunk = chunk ^ ((row>>1)&3) -> conflict-free ldsm with no padding.
#define HG_STG   24576
#define HG_SMEM  49152

template <int MODE>
__global__ __launch_bounds__(256, 4)
void hgemm2_kernel(const __nv_bfloat16* __restrict__ Ath,
                   const __nv_bfloat16* __restrict__ Atl,
                   const __nv_bfloat16* __restrict__ Bth,
                   const __nv_bfloat16* __restrict__ Btl,
                   const float* __restrict__ bias,
                   const float* __restrict__ resid, float* __restrict__ Cf,
                   __nv_bfloat16* __restrict__ Cb,
                   int M, int N, int K)
{
    extern __shared__ __align__(16) uint8_t smem[];
    const uint32_t uS = smem_u32(smem);

    const int tid  = threadIdx.x;
    const int lane = tid & 31;
    const int wid  = tid >> 5;
    const int wm   = wid >> 1;
    const int wn   = wid & 1;
    const int bm   = blockIdx.x * 128;
    const int bn   = blockIdx.y * 64;
    const int KT   = K >> 5;           // 8

    // ldmatrix lane rows + swizzled per-ks offsets
    const int lrA  = ((lane >> 3) & 1) * 8 + (lane & 7);
    const int lk8A = lane >> 4;                       // 0/1 -> k chunk low bit
    const int rowA = wm * 32 + lrA;
    const int xrA  = (rowA >> 1) & 3;
    const uint32_t offA0 = (uint32_t)(rowA * 64 + ((0 * 2 + lk8A) ^ xrA) * 16);
    const uint32_t offA1 = (uint32_t)(rowA * 64 + ((1 * 2 + lk8A) ^ xrA) * 16);

    const int lrB  = (lane >> 4) * 8 + (lane & 7);
    const int lk8B = (lane >> 3) & 1;
    const int rowB = wn * 32 + lrB;
    const int xrB  = (rowB >> 1) & 3;
    const uint32_t offB0 = (uint32_t)(16384 + rowB * 64 + ((0 * 2 + lk8B) ^ xrB) * 16);
    const uint32_t offB1 = (uint32_t)(16384 + rowB * 64 + ((1 * 2 + lk8B) ^ xrB) * 16);

    // staging indices (swizzled stores)
    const int ar0 = tid >> 2, ac0 = tid & 3;
    const int ar1 = ar0 + 64;
    const int br  = tid >> 2, bc = tid & 3;
    const uint32_t sA0 = (uint32_t)(ar0 * 64 + ((ac0 ^ ((ar0 >> 1) & 3)) * 16));
    const uint32_t sA1 = (uint32_t)(ar1 * 64 + ((ac0 ^ ((ar1 >> 1) & 3)) * 16));
    const uint32_t sB  = (uint32_t)(16384 + br * 64 + ((bc ^ ((br >> 1) & 3)) * 16));

    float acc[2][4][4];
#pragma unroll
    for (int t = 0; t < 2; t++)
#pragma unroll
        for (int u = 0; u < 4; u++)
#pragma unroll
            for (int i = 0; i < 4; i++) acc[t][u][i] = 0.f;

    auto issue = [&](int kt, int buf) {
        const int k0 = kt * 32;
        const uint32_t base = uS + buf * HG_STG;
        const size_t oa0 = (size_t)(bm + ar0) * K + k0 + ac0 * 8;
        const size_t oa1 = (size_t)(bm + ar1) * K + k0 + ac0 * 8;
        const size_t ob  = (size_t)(bn + br ) * K + k0 + bc  * 8;
        cp16(base +         sA0, Ath + oa0);
        cp16(base +         sA1, Ath + oa1);
        cp16(base + 8192u + sA0, Atl + oa0);
        cp16(base + 8192u + sA1, Atl + oa1);
        cp16(base +         sB,  Bth + ob);
        cp16(base + 4096u + sB,  Btl + ob);
        CP_COMMIT();
    };

    issue(0, 0);
    issue(1, 1);

#pragma unroll 1
    for (int kt = 0; kt < KT; kt++) {
        if (kt == KT - 1) { CP_WAIT(0); } else { CP_WAIT(1); }
        __syncthreads();

        const uint32_t sb = uS + (kt & 1) * HG_STG;
#pragma unroll
        for (int ks = 0; ks < 2; ks++) {
            const uint32_t oA = sb + (ks ? offA1 : offA0);
            const uint32_t oB = sb + (ks ? offB1 : offB0);
            uint32_t bH[4][2], bL[4][2];
            ldsm_x4(&bH[0][0], oB);
            ldsm_x4(&bH[2][0], oB + 1024);
            ldsm_x4(&bL[0][0], oB + 4096);
            ldsm_x4(&bL[2][0], oB + 4096 + 1024);
#pragma unroll
            for (int t = 0; t < 2; t++) {
                uint32_t aH[4], aL[4];
                ldsm_x4(aH, oA + t * 1024);
                ldsm_x4(aL, oA + 8192 + t * 1024);
#pragma unroll
                for (int u = 0; u < 4; u++) {
                    mma_bf16(acc[t][u], aH, bH[u]);
                    mma_bf16(acc[t][u], aH, bL[u]);
                    mma_bf16(acc[t][u], aL, bH[u]);
                }
            }
        }
        __syncthreads();
        if (kt + 2 < KT) issue(kt + 2, kt & 1);
    }

    // ---- epilogue (verified mapping, unchanged) ----
    const int g = lane >> 2, tg = lane & 3;
    const int batch = bm / NVAL;
    const int head  = (bn + wn * 32) >> 5;     // MODE 2 only (N=256)
#pragma unroll
    for (int t = 0; t < 2; t++)
#pragma unroll
        for (int u = 0; u < 4; u++) {
            const int row = bm + wm * 32 + t * 16 + g;
            const int col = bn + wn * 32 + u * 8 + tg * 2;
            const float2 bv = *(const float2*)(bias + col);
            float2 o0 = make_float2(acc[t][u][0] + bv.x, acc[t][u][1] + bv.y);
            float2 o1 = make_float2(acc[t][u][2] + bv.x, acc[t][u][3] + bv.y);
            if (MODE == 1) {
                const float2 r0 = *(const float2*)(resid + (size_t)row * N + col);
                const float2 r1 = *(const float2*)(resid + (size_t)(row + 8) * N + col);
                o0.x += r0.x; o0.y += r0.y;
                o1.x += r1.x; o1.y += r1.y;
            }
            if (MODE == 2) {
                const int nv = row - batch * NVAL;
                const int dim = u * 8 + tg * 2;
                const size_t base =
                    ((size_t)(batch * NHEAD + head) * NVAL + nv) * DHEAD + dim;
                *(uint32_t*)(Cb + base)              = pack_bf16(o0.x, o0.y);
                *(uint32_t*)(Cb + base + 8 * DHEAD)  = pack_bf16(o1.x, o1.y);
            } else {
                *(float2*)(Cf + (size_t)row * N + col) = o0;
                *(float2*)(Cf + (size_t)(row + 8) * N + col) = o1;
            }
        }
}

// ---------------- sampling kernel: bf16 head-major gather ------------------
__global__ __launch_bounds__(256)
void sample_kernel(const float* __restrict__ refp)
{
    __shared__ __align__(16) unsigned long long sm_iw[8][4][24]; // [warp][corner][point]

    const int wslot = threadIdx.x >> 5;
    const int warp = blockIdx.x * 8 + wslot;
    const int lane = threadIdx.x & 31;
    const int h  = warp & 7;
    const int bq = warp >> 3;
    const int b  = bq >> 12;

    float a = -INFINITY;
    if (lane < 24) a = g_qa[(size_t)bq * NQA + NOFF + h * 24 + lane];
    float m = a;
#pragma unroll
    for (int s = 16; s; s >>= 1) m = fmaxf(m, __shfl_xor_sync(0xffffffffu, m, s));
    float e = (lane < 24) ? __expf(a - m) : 0.f;
    float ssum = e;
#pragma unroll
    for (int s = 16; s; s >>= 1) ssum += __shfl_xor_sync(0xffffffffu, ssum, s);
    const float aw = e / ssum;

    if (lane < 24) {
        const int l = lane >> 2;
        const int p = lane & 3;
        const int H = c_H[l], W = c_W[l], S = c_S[l];
        const size_t ob = (size_t)bq * NQA + (((h * NLVL + l) * NPT + p) << 1);
        const float offx = g_qa[ob + 0];
        const float offy = g_qa[ob + 1];
        const size_t rb = ((size_t)bq * NLVL + l) << 1;
        const float rx = refp[rb + 0];
        const float ry = refp[rb + 1];
        const float x = rx * (float)W + offx - 0.5f;
        const float y = ry * (float)H + offy - 0.5f;
        const float xf = floorf(x), yf = floorf(y);
        const float lx = x - xf, ly = y - yf;
        const int ix = (int)xf, iy = (int)yf;
        const bool vx0 = (ix     >= 0) && (ix     < W);
        const bool vx1 = (ix + 1 >= 0) && (ix + 1 < W);
        const bool vy0 = (iy     >= 0) && (iy     < H);
        const bool vy1 = (iy + 1 >= 0) && (iy + 1 < H);
        const int cx0 = min(max(ix, 0), W - 1);
        const int cx1 = min(max(ix + 1, 0), W - 1);
        const int cy0 = min(max(iy, 0), H - 1);
        const int cy1 = min(max(iy + 1, 0), H - 1);
        const unsigned o00 = (unsigned)(S + cy0 * W + cx0) << 6;
        const unsigned o01 = (unsigned)(S + cy0 * W + cx1) << 6;
        const unsigned o10 = (unsigned)(S + cy1 * W + cx0) << 6;
        const unsigned o11 = (unsigned)(S + cy1 * W + cx1) << 6;
        const float w00 = aw * (1.f - lx) * (1.f - ly) * (float)(vx0 && vy0);
        const float w01 = aw * lx         * (1.f - ly) * (float)(vx1 && vy0);
        const float w10 = aw * (1.f - lx) * ly         * (float)(vx0 && vy1);
        const float w11 = aw * lx         * ly         * (float)(vx1 && vy1);
        sm_iw[wslot][0][lane] =
            (unsigned long long)o00 | ((unsigned long long)__float_as_uint(w00) << 32);
        sm_iw[wslot][1][lane] =
            (unsigned long long)o01 | ((unsigned long long)__float_as_uint(w01) << 32);
        sm_iw[wslot][2][lane] =
            (unsigned long long)o10 | ((unsigned long long)__float_as_uint(w10) << 32);
        sm_iw[wslot][3][lane] =
            (unsigned long long)o11 | ((unsigned long long)__float_as_uint(w11) << 32);
    }
    __syncwarp();

    const int g  = lane >> 3;          // corner group
    const int li = lane & 7;           // dim slice (4 channels)
    const char* __restrict__ vbb =
        (const char*)g_vbf + (size_t)(b * NHEAD + h) * NVAL * (DHEAD * 2) + li * 8;

    float4 acc0 = make_float4(0.f, 0.f, 0.f, 0.f);
    float4 acc1 = make_float4(0.f, 0.f, 0.f, 0.f);
#pragma unroll
    for (int j = 0; j < 12; j++) {
        const uint4 t = *(const uint4*)&sm_iw[wslot][g][2 * j];
        const float w0 = __uint_as_float(t.y);
        const float w1 = __uint_as_float(t.w);
        const uint2 v0 = *(const uint2*)(vbb + t.x);
        const uint2 v1 = *(const uint2*)(vbb + t.z);
        acc0.x = fmaf(w0, __uint_as_float(v0.x << 16),         acc0.x);
        acc0.y = fmaf(w0, __uint_as_float(v0.x & 0xffff0000u), acc0.y);
        acc0.z = fmaf(w0, __uint_as_float(v0.y << 16),         acc0.z);
        acc0.w = fmaf(w0, __uint_as_float(v0.y & 0xffff0000u), acc0.w);
        acc1.x = fmaf(w1, __uint_as_float(v1.x << 16),         acc1.x);
        acc1.y = fmaf(w1, __uint_as_float(v1.x & 0xffff0000u), acc1.y);
        acc1.z = fmaf(w1, __uint_as_float(v1.y << 16),         acc1.z);
        acc1.w = fmaf(w1, __uint_as_float(v1.y & 0xffff0000u), acc1.w);
    }
    float4 acc = make_float4(acc0.x + acc1.x, acc0.y + acc1.y,
                             acc0.z + acc1.z, acc0.w + acc1.w);
#pragma unroll
    for (int s = 8; s <= 16; s <<= 1) {
        acc.x += __shfl_xor_sync(0xffffffffu, acc.x, s);
        acc.y += __shfl_xor_sync(0xffffffffu, acc.y, s);
        acc.z += __shfl_xor_sync(0xffffffffu, acc.z, s);
        acc.w += __shfl_xor_sync(0xffffffffu, acc.w, s);
    }
    if (lane < 8) {
        const size_t o4 = ((size_t)bq * CDIM + h * DHEAD + lane * 4) >> 2;
        const float hx = __bfloat162float(__float2bfloat16_rn(acc.x));
        const float hy = __bfloat162float(__float2bfloat16_rn(acc.y));
        const float hz = __bfloat162float(__float2bfloat16_rn(acc.z));
        const float hw = __bfloat162float(__float2bfloat16_rn(acc.w));
        ((uint2*)g_ms_h)[o4] = make_uint2(pack_bf16(acc.x, acc.y),
                                          pack_bf16(acc.z, acc.w));
        ((uint2*)g_ms_l)[o4] = make_uint2(pack_bf16(acc.x - hx, acc.y - hy),
                                          pack_bf16(acc.z - hz, acc.w - hw));
    }
}

// ---------------- launch ----------------
extern "C" void kernel_launch(void* const* d_in, const int* in_sizes, int n_in,
                              void* d_out, int out_size)
{
    const float* query  = (const float*)d_in[0];
    const float* qpos   = (const float*)d_in[1];
    const float* value  = (const float*)d_in[2];
    const float* refp   = (const float*)d_in[3];
    const float* W_off  = (const float*)d_in[5];
    const float* b_off  = (const float*)d_in[6];
    const float* W_attn = (const float*)d_in[7];
    const float* b_attn = (const float*)d_in[8];
    const float* W_val  = (const float*)d_in[9];
    const float* b_val  = (const float*)d_in[10];
    const float* W_out  = (const float*)d_in[11];
    const float* b_out  = (const float*)d_in[12];
    float* out = (float*)d_out;

    float *qa, *biasb;
    __nv_bfloat16 *vbf, *wth, *wtl, *valh, *vall, *qh, *ql, *msh, *msl;
    cudaGetSymbolAddress((void**)&vbf,   g_vbf);
    cudaGetSymbolAddress((void**)&qa,    g_qa);
    cudaGetSymbolAddress((void**)&biasb, g_bias);
    cudaGetSymbolAddress((void**)&wth,   g_Wt_hi);
    cudaGetSymbolAddress((void**)&wtl,   g_Wt_lo);
    cudaGetSymbolAddress((void**)&valh,  g_val_h);
    cudaGetSymbolAddress((void**)&vall,  g_val_l);
    cudaGetSymbolAddress((void**)&qh,    g_q_h);
    cudaGetSymbolAddress((void**)&ql,    g_q_l);
    cudaGetSymbolAddress((void**)&msh,   g_ms_h);
    cudaGetSymbolAddress((void**)&msl,   g_ms_l);

    static cudaStream_t s2 = nullptr;
    static cudaEvent_t evFork = nullptr, evJoin = nullptr;
    if (!s2) {
        cudaFuncSetAttribute(hgemm2_kernel<0>,
                             cudaFuncAttributeMaxDynamicSharedMemorySize, HG_SMEM);
        cudaFuncSetAttribute(hgemm2_kernel<1>,
                             cudaFuncAttributeMaxDynamicSharedMemorySize, HG_SMEM);
        cudaFuncSetAttribute(hgemm2_kernel<2>,
                             cudaFuncAttributeMaxDynamicSharedMemorySize, HG_SMEM);
        cudaStreamCreateWithFlags(&s2, cudaStreamNonBlocking);
        cudaEventCreateWithFlags(&evFork, cudaEventDisableTiming);
        cudaEventCreateWithFlags(&evJoin, cudaEventDisableTiming);
    }

    // ---- fork: branch B (value chain) on s2 ----
    cudaEventRecord(evFork, 0);
    cudaStreamWaitEvent(s2, evFork, 0);
    prep_v_kernel<<<PV_NB, 256, 0, s2>>>(value);
    hgemm2_kernel<2><<<dim3(MV / 128, CDIM / 64), 256, HG_SMEM, s2>>>(
        valh, vall, wth, wtl, biasb, nullptr, nullptr, vbf, MV, CDIM, CDIM);
    cudaEventRecord(evJoin, s2);

    // ---- branch A (query chain) on stream 0, concurrent with branch B ----
    prep_qw_kernel<<<PQW_NB, 256>>>(W_val, b_val, W_off, b_off,
                                    W_attn, b_attn, W_out, b_out, query, qpos);
    hgemm2_kernel<0><<<dim3(MQ / 128, NQA / 64), 256, HG_SMEM>>>(
        qh, ql, wth + 256 * CDIM, wtl + 256 * CDIM, biasb + 256,
        nullptr, qa, nullptr, MQ, NQA, CDIM);

    // ---- join, then sampler + out GEMM ----
    cudaStreamWaitEvent(0, evJoin, 0);
    sample_kernel<<<(MQ * NHEAD) / 8, 256>>>(refp);
    hgemm2_kernel<1><<<dim3(MQ / 128, CDIM / 64), 256, HG_SMEM>>>(
        msh, msl, wth + 832 * CDIM, wtl + 832 * CDIM, biasb + 832,
        query, out, nullptr, MQ, CDIM, CDIM);
}

// round 12
// speedup vs baseline: 1.2251x; 1.0276x over previous
#include <cuda_runtime.h>
#include <cuda_bf16.h>
#include <math.h>
#include <stdint.h>

// ---------------- problem constants (static per reference) ----------------
#define BSZ   8
#define NQ    4096
#define CDIM  256
#define NHEAD 8
#define NPT   4
#define NLVL  6
#define NVAL  10752
#define DHEAD 32
#define NOFF  384
#define NATT  192
#define NQA   576          // NOFF + NATT fused GEMM width
#define NWT   1088         // 256 (val) + 576 (off|attn) + 256 (out)
#define MQ    (BSZ * NQ)   // 32768
#define MV    (BSZ * NVAL) // 86016

// ---------------- device scratch (static, no allocation) ------------------
__device__ __nv_bfloat16 g_vbf [(size_t)MV * CDIM];    // vproj bf16, head-major
__device__ float g_qa   [(size_t)MQ * NQA];            // [off(384) | attn(192)]
__device__ __nv_bfloat16 g_val_h[(size_t)MV * CDIM];   // value, bf16 hi
__device__ __nv_bfloat16 g_val_l[(size_t)MV * CDIM];   // value, bf16 lo
__device__ __nv_bfloat16 g_q_h  [(size_t)MQ * CDIM];   // query+qpos hi
__device__ __nv_bfloat16 g_q_l  [(size_t)MQ * CDIM];   // query+qpos lo
__device__ __nv_bfloat16 g_ms_h [(size_t)MQ * CDIM];   // deform-attn out hi
__device__ __nv_bfloat16 g_ms_l [(size_t)MQ * CDIM];   // deform-attn out lo
__device__ __nv_bfloat16 g_Wt_hi[NWT * CDIM];          // all weights^T hi
__device__ __nv_bfloat16 g_Wt_lo[NWT * CDIM];          // all weights^T lo
__device__ float g_bias[NWT];

__constant__ int c_H[NLVL] = {64, 32, 16, 64, 32, 16};
__constant__ int c_W[NLVL] = {64, 32, 16, 64, 32, 16};
__constant__ int c_S[NLVL] = {0, 4096, 5120, 5376, 9472, 10496};

// ---------------- small helpers -------------------------------------------
__device__ __forceinline__ uint32_t smem_u32(const void* p) {
    uint32_t a;
    asm("{ .reg .u64 t; cvta.to.shared.u64 t, %1; cvt.u32.u64 %0, t; }"
        : "=r"(a) : "l"(p));
    return a;
}
__device__ __forceinline__ void ldsm_x4(uint32_t* r, uint32_t addr) {
    asm volatile("ldmatrix.sync.aligned.m8n8.x4.shared.b16 {%0,%1,%2,%3}, [%4];"
                 : "=r"(r[0]), "=r"(r[1]), "=r"(r[2]), "=r"(r[3]) : "r"(addr));
}
__device__ __forceinline__ void mma_bf16(float* c, const uint32_t* a,
                                         const uint32_t* b) {
    asm volatile(
        "mma.sync.aligned.m16n8k16.row.col.f32.bf16.bf16.f32 "
        "{%0,%1,%2,%3}, {%4,%5,%6,%7}, {%8,%9}, {%0,%1,%2,%3};"
        : "+f"(c[0]), "+f"(c[1]), "+f"(c[2]), "+f"(c[3])
        : "r"(a[0]), "r"(a[1]), "r"(a[2]), "r"(a[3]), "r"(b[0]), "r"(b[1]));
}
__device__ __forceinline__ uint32_t pack_bf16(float x, float y) {
    __nv_bfloat162 t = __halves2bfloat162(__float2bfloat16_rn(x),
                                          __float2bfloat16_rn(y));
    return *(uint32_t*)&t;
}
__device__ __forceinline__ void cp16(uint32_t dst, const void* src) {
    asm volatile("cp.async.cg.shared.global [%0], [%1], 16;"
                 :: "r"(dst), "l"(src));
}
#define CP_COMMIT() asm volatile("cp.async.commit_group;" ::: "memory")
#define CP_WAIT(n)  asm volatile("cp.async.wait_group %0;" :: "n"(n) : "memory")

// ============== prep branch A: weights + q split ============================
#define PQW_B0 1088
#define PQW_NB (PQW_B0 + (MQ * CDIM / 4) / 256)     // 1088 + 8192 = 9280

__global__ __launch_bounds__(256)
void prep_qw_kernel(const float* __restrict__ W_val,
                    const float* __restrict__ b_val,
                    const float* __restrict__ W_off,
                    const float* __restrict__ b_off,
                    const float* __restrict__ W_attn,
                    const float* __restrict__ b_attn,
                    const float* __restrict__ W_out,
                    const float* __restrict__ b_out,
                    const float* __restrict__ query,
                    const float* __restrict__ qpos)
{
    const int bx = blockIdx.x;
    const int tid = threadIdx.x;
    if (bx < PQW_B0) {
        const int n = bx, k = tid;
        float x, bb;
        if (n < 256)      { x = W_val[k * 256 + n];          bb = b_val[n]; }
        else if (n < 832) {
            const int m = n - 256;
            if (m < 384)  { x = W_off[k * 384 + m];          bb = b_off[m]; }
            else          { x = W_attn[k * 192 + (m - 384)]; bb = b_attn[m - 384]; }
        }
        else              { x = W_out[k * 256 + (n - 832)];  bb = b_out[n - 832]; }
        const __nv_bfloat16 hi = __float2bfloat16_rn(x);
        const __nv_bfloat16 lo = __float2bfloat16_rn(x - __bfloat162float(hi));
        g_Wt_hi[n * CDIM + k] = hi;
        g_Wt_lo[n * CDIM + k] = lo;
        if (k == 0) g_bias[n] = bb;
        return;
    }
    const size_t i4 = (size_t)(bx - PQW_B0) * 256 + tid;
    float4 v = ((const float4*)query)[i4];
    const float4 u = ((const float4*)qpos)[i4];
    v.x += u.x; v.y += u.y; v.z += u.z; v.w += u.w;
    const float hx = __bfloat162float(__float2bfloat16_rn(v.x));
    const float hy = __bfloat162float(__float2bfloat16_rn(v.y));
    const float hz = __bfloat162float(__float2bfloat16_rn(v.z));
    const float hw = __bfloat162float(__float2bfloat16_rn(v.w));
    ((uint2*)g_q_h)[i4] = make_uint2(pack_bf16(v.x, v.y), pack_bf16(v.z, v.w));
    ((uint2*)g_q_l)[i4] = make_uint2(pack_bf16(v.x - hx, v.y - hy),
                                     pack_bf16(v.z - hz, v.w - hw));
}

// ============== prep branch B: value split ==================================
#define PV_NB ((MV * CDIM / 4) / 256)               // 21504

__global__ __launch_bounds__(256)
void prep_v_kernel(const float* __restrict__ value)
{
    const size_t i4 = (size_t)blockIdx.x * 256 + threadIdx.x;
    const float4 v = ((const float4*)value)[i4];
    const float hx = __bfloat162float(__float2bfloat16_rn(v.x));
    const float hy = __bfloat162float(__float2bfloat16_rn(v.y));
    const float hz = __bfloat162float(__float2bfloat16_rn(v.z));
    const float hw = __bfloat162float(__float2bfloat16_rn(v.w));
    ((uint2*)g_val_h)[i4] = make_uint2(pack_bf16(v.x, v.y), pack_bf16(v.z, v.w));
    ((uint2*)g_val_l)[i4] = make_uint2(pack_bf16(v.x - hx, v.y - hy),
                                       pack_bf16(v.z - hz, v.w - hw));
}

// ============== bf16-split HMMA GEMM, 2-stage single-sync pipeline ==========
// MODE 0: C fp32, 3 terms           (qa GEMM)
// MODE 1: C fp32 + residual, 3 terms (out GEMM)
// MODE 2: C bf16 head-major, 2 terms (vproj: D=(Ah+Al)*Bh — Bl dropped; the
//         output is rounded to bf16 anyway so weight-lo is below the noise)
// Single __syncthreads per k-tile: issue(kt+1) after the sync writes buffer
// (kt+1)&1, last consumed in iteration kt-1 which the sync just fenced.
#define HG_STG   24576
#define HG_SMEM  49152

template <int MODE>
__global__ __launch_bounds__(256, 4)
void hgemm2_kernel(const __nv_bfloat16* __restrict__ Ath,
                   const __nv_bfloat16* __restrict__ Atl,
                   const __nv_bfloat16* __restrict__ Bth,
                   const __nv_bfloat16* __restrict__ Btl,
                   const float* __restrict__ bias,
                   const float* __restrict__ resid, float* __restrict__ Cf,
                   __nv_bfloat16* __restrict__ Cb,
                   int M, int N, int K)
{
    extern __shared__ __align__(16) uint8_t smem[];
    const uint32_t uS = smem_u32(smem);

    const int tid  = threadIdx.x;
    const int lane = tid & 31;
    const int wid  = tid >> 5;
    const int wm   = wid >> 1;
    const int wn   = wid & 1;
    const int bm   = blockIdx.x * 128;
    const int bn   = blockIdx.y * 64;
    const int KT   = K >> 5;           // 8

    // ldmatrix lane rows + swizzled per-ks offsets
    const int lrA  = ((lane >> 3) & 1) * 8 + (lane & 7);
    const int lk8A = lane >> 4;
    const int rowA = wm * 32 + lrA;
    const int xrA  = (rowA >> 1) & 3;
    const uint32_t offA0 = (uint32_t)(rowA * 64 + ((0 * 2 + lk8A) ^ xrA) * 16);
    const uint32_t offA1 = (uint32_t)(rowA * 64 + ((1 * 2 + lk8A) ^ xrA) * 16);

    const int lrB  = (lane >> 4) * 8 + (lane & 7);
    const int lk8B = (lane >> 3) & 1;
    const int rowB = wn * 32 + lrB;
    const int xrB  = (rowB >> 1) & 3;
    const uint32_t offB0 = (uint32_t)(16384 + rowB * 64 + ((0 * 2 + lk8B) ^ xrB) * 16);
    const uint32_t offB1 = (uint32_t)(16384 + rowB * 64 + ((1 * 2 + lk8B) ^ xrB) * 16);

    // staging indices (swizzled stores)
    const int ar0 = tid >> 2, ac0 = tid & 3;
    const int ar1 = ar0 + 64;
    const int br  = tid >> 2, bc = tid & 3;
    const uint32_t sA0 = (uint32_t)(ar0 * 64 + ((ac0 ^ ((ar0 >> 1) & 3)) * 16));
    const uint32_t sA1 = (uint32_t)(ar1 * 64 + ((ac0 ^ ((ar1 >> 1) & 3)) * 16));
    const uint32_t sB  = (uint32_t)(16384 + br * 64 + ((bc ^ ((br >> 1) & 3)) * 16));

    float acc[2][4][4];
#pragma unroll
    for (int t = 0; t < 2; t++)
#pragma unroll
        for (int u = 0; u < 4; u++)
#pragma unroll
            for (int i = 0; i < 4; i++) acc[t][u][i] = 0.f;

    auto issue = [&](int kt, int buf) {
        const int k0 = kt * 32;
        const uint32_t base = uS + buf * HG_STG;
        const size_t oa0 = (size_t)(bm + ar0) * K + k0 + ac0 * 8;
        const size_t oa1 = (size_t)(bm + ar1) * K + k0 + ac0 * 8;
        const size_t ob  = (size_t)(bn + br ) * K + k0 + bc  * 8;
        cp16(base +         sA0, Ath + oa0);
        cp16(base +         sA1, Ath + oa1);
        cp16(base + 8192u + sA0, Atl + oa0);
        cp16(base + 8192u + sA1, Atl + oa1);
        cp16(base +         sB,  Bth + ob);
        if (MODE != 2)
            cp16(base + 4096u + sB, Btl + ob);
        CP_COMMIT();
    };

    issue(0, 0);

#pragma unroll 1
    for (int kt = 0; kt < KT; kt++) {
        CP_WAIT(0);
        __syncthreads();
        if (kt + 1 < KT) issue(kt + 1, (kt + 1) & 1);

        const uint32_t sb = uS + (kt & 1) * HG_STG;
#pragma unroll
        for (int ks = 0; ks < 2; ks++) {
            const uint32_t oA = sb + (ks ? offA1 : offA0);
            const uint32_t oB = sb + (ks ? offB1 : offB0);
            uint32_t bH[4][2], bL[4][2];
            ldsm_x4(&bH[0][0], oB);
            ldsm_x4(&bH[2][0], oB + 1024);
            if (MODE != 2) {
                ldsm_x4(&bL[0][0], oB + 4096);
                ldsm_x4(&bL[2][0], oB + 4096 + 1024);
            }
#pragma unroll
            for (int t = 0; t < 2; t++) {
                uint32_t aH[4], aL[4];
                ldsm_x4(aH, oA + t * 1024);
                ldsm_x4(aL, oA + 8192 + t * 1024);
#pragma unroll
                for (int u = 0; u < 4; u++) {
                    mma_bf16(acc[t][u], aH, bH[u]);
                    if (MODE != 2) mma_bf16(acc[t][u], aH, bL[u]);
                    mma_bf16(acc[t][u], aL, bH[u]);
                }
            }
        }
    }

    // ---- epilogue (verified mapping, unchanged) ----
    const int g = lane >> 2, tg = lane & 3;
    const int batch = bm / NVAL;
    const int head  = (bn + wn * 32) >> 5;     // MODE 2 only (N=256)
#pragma unroll
    for (int t = 0; t < 2; t++)
#pragma unroll
        for (int u = 0; u < 4; u++) {
            const int row = bm + wm * 32 + t * 16 + g;
            const int col = bn + wn * 32 + u * 8 + tg * 2;
            const float2 bv = *(const float2*)(bias + col);
            float2 o0 = make_float2(acc[t][u][0] + bv.x, acc[t][u][1] + bv.y);
            float2 o1 = make_float2(acc[t][u][2] + bv.x, acc[t][u][3] + bv.y);
            if (MODE == 1) {
                const float2 r0 = *(const float2*)(resid + (size_t)row * N + col);
                const float2 r1 = *(const float2*)(resid + (size_t)(row + 8) * N + col);
                o0.x += r0.x; o0.y += r0.y;
                o1.x += r1.x; o1.y += r1.y;
            }
            if (MODE == 2) {
                const int nv = row - batch * NVAL;
                const int dim = u * 8 + tg * 2;
                const size_t base =
                    ((size_t)(batch * NHEAD + head) * NVAL + nv) * DHEAD + dim;
                *(uint32_t*)(Cb + base)              = pack_bf16(o0.x, o0.y);
                *(uint32_t*)(Cb + base + 8 * DHEAD)  = pack_bf16(o1.x, o1.y);
            } else {
                *(float2*)(Cf + (size_t)row * N + col) = o0;
                *(float2*)(Cf + (size_t)(row + 8) * N + col) = o1;
            }
        }
}

// ---------------- sampling kernel: bf16 head-major gather ------------------
__global__ __launch_bounds__(256)
void sample_kernel(const float* __restrict__ refp)
{
    __shared__ __align__(16) unsigned long long sm_iw[8][4][24]; // [warp][corner][point]

    const int wslot = threadIdx.x >> 5;
    const int warp = blockIdx.x * 8 + wslot;
    const int lane = threadIdx.x & 31;
    const int h  = warp & 7;
    const int bq = warp >> 3;
    const int b  = bq >> 12;

    float a = -INFINITY;
    if (lane < 24) a = g_qa[(size_t)bq * NQA + NOFF + h * 24 + lane];
    float m = a;
#pragma unroll
    for (int s = 16; s; s >>= 1) m = fmaxf(m, __shfl_xor_sync(0xffffffffu, m, s));
    float e = (lane < 24) ? __expf(a - m) : 0.f;
    float ssum = e;
#pragma unroll
    for (int s = 16; s; s >>= 1) ssum += __shfl_xor_sync(0xffffffffu, ssum, s);
    const float aw = e / ssum;

    if (lane < 24) {
        const int l = lane >> 2;
        const int p = lane & 3;
        const int H = c_H[l], W = c_W[l], S = c_S[l];
        const size_t ob = (size_t)bq * NQA + (((h * NLVL + l) * NPT + p) << 1);
        const float offx = g_qa[ob + 0];
        const float offy = g_qa[ob + 1];
        const size_t rb = ((size_t)bq * NLVL + l) << 1;
        const float rx = refp[rb + 0];
        const float ry = refp[rb + 1];
        const float x = rx * (float)W + offx - 0.5f;
        const float y = ry * (float)H + offy - 0.5f;
        const float xf = floorf(x), yf = floorf(y);
        const float lx = x - xf, ly = y - yf;
        const int ix = (int)xf, iy = (int)yf;
        const bool vx0 = (ix     >= 0) && (ix     < W);
        const bool vx1 = (ix + 1 >= 0) && (ix + 1 < W);
        const bool vy0 = (iy     >= 0) && (iy     < H);
        const bool vy1 = (iy + 1 >= 0) && (iy + 1 < H);
        const int cx0 = min(max(ix, 0), W - 1);
        const int cx1 = min(max(ix + 1, 0), W - 1);
        const int cy0 = min(max(iy, 0), H - 1);
        const int cy1 = min(max(iy + 1, 0), H - 1);
        const unsigned o00 = (unsigned)(S + cy0 * W + cx0) << 6;
        const unsigned o01 = (unsigned)(S + cy0 * W + cx1) << 6;
        const unsigned o10 = (unsigned)(S + cy1 * W + cx0) << 6;
        const unsigned o11 = (unsigned)(S + cy1 * W + cx1) << 6;
        const float w00 = aw * (1.f - lx) * (1.f - ly) * (float)(vx0 && vy0);
        const float w01 = aw * lx         * (1.f - ly) * (float)(vx1 && vy0);
        const float w10 = aw * (1.f - lx) * ly         * (float)(vx0 && vy1);
        const float w11 = aw * lx         * ly         * (float)(vx1 && vy1);
        sm_iw[wslot][0][lane] =
            (unsigned long long)o00 | ((unsigned long long)__float_as_uint(w00) << 32);
        sm_iw[wslot][1][lane] =
            (unsigned long long)o01 | ((unsigned long long)__float_as_uint(w01) << 32);
        sm_iw[wslot][2][lane] =
            (unsigned long long)o10 | ((unsigned long long)__float_as_uint(w10) << 32);
        sm_iw[wslot][3][lane] =
            (unsigned long long)o11 | ((unsigned long long)__float_as_uint(w11) << 32);
    }
    __syncwarp();

    const int g  = lane >> 3;          // corner group
    const int li = lane & 7;           // dim slice (4 channels)
    const char* __restrict__ vbb =
        (const char*)g_vbf + (size_t)(b * NHEAD + h) * NVAL * (DHEAD * 2) + li * 8;

    float4 acc0 = make_float4(0.f, 0.f, 0.f, 0.f);
    float4 acc1 = make_float4(0.f, 0.f, 0.f, 0.f);
#pragma unroll
    for (int j = 0; j < 12; j++) {
        const uint4 t = *(const uint4*)&sm_iw[wslot][g][2 * j];
        const float w0 = __uint_as_float(t.y);
        const float w1 = __uint_as_float(t.w);
        const uint2 v0 = *(const uint2*)(vbb + t.x);
        const uint2 v1 = *(const uint2*)(vbb + t.z);
        acc0.x = fmaf(w0, __uint_as_float(v0.x << 16),         acc0.x);
        acc0.y = fmaf(w0, __uint_as_float(v0.x & 0xffff0000u), acc0.y);
        acc0.z = fmaf(w0, __uint_as_float(v0.y << 16),         acc0.z);
        acc0.w = fmaf(w0, __uint_as_float(v0.y & 0xffff0000u), acc0.w);
        acc1.x = fmaf(w1, __uint_as_float(v1.x << 16),         acc1.x);
        acc1.y = fmaf(w1, __uint_as_float(v1.x & 0xffff0000u), acc1.y);
        acc1.z = fmaf(w1, __uint_as_float(v1.y << 16),         acc1.z);
        acc1.w = fmaf(w1, __uint_as_float(v1.y & 0xffff0000u), acc1.w);
    }
    float4 acc = make_float4(acc0.x + acc1.x, acc0.y + acc1.y,
                             acc0.z + acc1.z, acc0.w + acc1.w);
#pragma unroll
    for (int s = 8; s <= 16; s <<= 1) {
        acc.x += __shfl_xor_sync(0xffffffffu, acc.x, s);
        acc.y += __shfl_xor_sync(0xffffffffu, acc.y, s);
        acc.z += __shfl_xor_sync(0xffffffffu, acc.z, s);
        acc.w += __shfl_xor_sync(0xffffffffu, acc.w, s);
    }
    if (lane < 8) {
        const size_t o4 = ((size_t)bq * CDIM + h * DHEAD + lane * 4) >> 2;
        const float hx = __bfloat162float(__float2bfloat16_rn(acc.x));
        const float hy = __bfloat162float(__float2bfloat16_rn(acc.y));
        const float hz = __bfloat162float(__float2bfloat16_rn(acc.z));
        const float hw = __bfloat162float(__float2bfloat16_rn(acc.w));
        ((uint2*)g_ms_h)[o4] = make_uint2(pack_bf16(acc.x, acc.y),
                                          pack_bf16(acc.z, acc.w));
        ((uint2*)g_ms_l)[o4] = make_uint2(pack_bf16(acc.x - hx, acc.y - hy),
                                          pack_bf16(acc.z - hz, acc.w - hw));
    }
}

// ---------------- launch ----------------
extern "C" void kernel_launch(void* const* d_in, const int* in_sizes, int n_in,
                              void* d_out, int out_size)
{
    const float* query  = (const float*)d_in[0];
    const float* qpos   = (const float*)d_in[1];
    const float* value  = (const float*)d_in[2];
    const float* refp   = (const float*)d_in[3];
    const float* W_off  = (const float*)d_in[5];
    const float* b_off  = (const float*)d_in[6];
    const float* W_attn = (const float*)d_in[7];
    const float* b_attn = (const float*)d_in[8];
    const float* W_val  = (const float*)d_in[9];
    const float* b_val  = (const float*)d_in[10];
    const float* W_out  = (const float*)d_in[11];
    const float* b_out  = (const float*)d_in[12];
    float* out = (float*)d_out;

    float *qa, *biasb;
    __nv_bfloat16 *vbf, *wth, *wtl, *valh, *vall, *qh, *ql, *msh, *msl;
    cudaGetSymbolAddress((void**)&vbf,   g_vbf);
    cudaGetSymbolAddress((void**)&qa,    g_qa);
    cudaGetSymbolAddress((void**)&biasb, g_bias);
    cudaGetSymbolAddress((void**)&wth,   g_Wt_hi);
    cudaGetSymbolAddress((void**)&wtl,   g_Wt_lo);
    cudaGetSymbolAddress((void**)&valh,  g_val_h);
    cudaGetSymbolAddress((void**)&vall,  g_val_l);
    cudaGetSymbolAddress((void**)&qh,    g_q_h);
    cudaGetSymbolAddress((void**)&ql,    g_q_l);
    cudaGetSymbolAddress((void**)&msh,   g_ms_h);
    cudaGetSymbolAddress((void**)&msl,   g_ms_l);

    static cudaStream_t s2 = nullptr;
    static cudaEvent_t evFork = nullptr, evJoin = nullptr;
    if (!s2) {
        cudaFuncSetAttribute(hgemm2_kernel<0>,
                             cudaFuncAttributeMaxDynamicSharedMemorySize, HG_SMEM);
        cudaFuncSetAttribute(hgemm2_kernel<1>,
                             cudaFuncAttributeMaxDynamicSharedMemorySize, HG_SMEM);
        cudaFuncSetAttribute(hgemm2_kernel<2>,
                             cudaFuncAttributeMaxDynamicSharedMemorySize, HG_SMEM);
        cudaStreamCreateWithFlags(&s2, cudaStreamNonBlocking);
        cudaEventCreateWithFlags(&evFork, cudaEventDisableTiming);
        cudaEventCreateWithFlags(&evJoin, cudaEventDisableTiming);
    }

    // ---- fork: branch B (value chain) on s2 ----
    cudaEventRecord(evFork, 0);
    cudaStreamWaitEvent(s2, evFork, 0);
    prep_v_kernel<<<PV_NB, 256, 0, s2>>>(value);
    hgemm2_kernel<2><<<dim3(MV / 128, CDIM / 64), 256, HG_SMEM, s2>>>(
        valh, vall, wth, wtl, biasb, nullptr, nullptr, vbf, MV, CDIM, CDIM);
    cudaEventRecord(evJoin, s2);

    // ---- branch A (query chain) on stream 0, concurrent with branch B ----
    prep_qw_kernel<<<PQW_NB, 256>>>(W_val, b_val, W_off, b_off,
                                    W_attn, b_attn, W_out, b_out, query, qpos);
    hgemm2_kernel<0><<<dim3(MQ / 128, NQA / 64), 256, HG_SMEM>>>(
        qh, ql, wth + 256 * CDIM, wtl + 256 * CDIM, biasb + 256,
        nullptr, qa, nullptr, MQ, NQA, CDIM);

    // ---- join, then sampler + out GEMM ----
    cudaStreamWaitEvent(0, evJoin, 0);
    sample_kernel<<<(MQ * NHEAD) / 8, 256>>>(refp);
    hgemm2_kernel<1><<<dim3(MQ / 128, CDIM / 64), 256, HG_SMEM>>>(
        msh, msl, wth + 832 * CDIM, wtl + 832 * CDIM, biasb + 832,
        query, out, nullptr, MQ, CDIM, CDIM);
}

// round 13
// speedup vs baseline: 1.2778x; 1.0430x over previous
#include <cuda_runtime.h>
#include <cuda_bf16.h>
#include <math.h>
#include <stdint.h>

// ---------------- problem constants (static per reference) ----------------
#define BSZ   8
#define NQ    4096
#define CDIM  256
#define NHEAD 8
#define NPT   4
#define NLVL  6
#define NVAL  10752
#define DHEAD 32
#define NOFF  384
#define NATT  192
#define NQA   576
#define NWT   1088
#define MQ    (BSZ * NQ)   // 32768
#define MV    (BSZ * NVAL) // 86016
#define MVH   (MV / 2)     // 43008 = batches 0..3
#define MQH   (MQ / 2)     // 16384

// ---------------- device scratch (static, no allocation) ------------------
__device__ __nv_bfloat16 g_vbf [(size_t)MV * CDIM];    // vproj bf16, head-major
__device__ float g_qa   [(size_t)MQ * NQA];            // [off(384) | attn(192)]
__device__ __nv_bfloat16 g_val_h[(size_t)MV * CDIM];
__device__ __nv_bfloat16 g_val_l[(size_t)MV * CDIM];
__device__ __nv_bfloat16 g_q_h  [(size_t)MQ * CDIM];
__device__ __nv_bfloat16 g_q_l  [(size_t)MQ * CDIM];
__device__ __nv_bfloat16 g_ms_h [(size_t)MQ * CDIM];
__device__ __nv_bfloat16 g_ms_l [(size_t)MQ * CDIM];
__device__ __nv_bfloat16 g_Wt_hi[NWT * CDIM];
__device__ __nv_bfloat16 g_Wt_lo[NWT * CDIM];
__device__ float g_bias[NWT];

__constant__ int c_H[NLVL] = {64, 32, 16, 64, 32, 16};
__constant__ int c_W[NLVL] = {64, 32, 16, 64, 32, 16};
__constant__ int c_S[NLVL] = {0, 4096, 5120, 5376, 9472, 10496};

// ---------------- small helpers -------------------------------------------
__device__ __forceinline__ uint32_t smem_u32(const void* p) {
    uint32_t a;
    asm("{ .reg .u64 t; cvta.to.shared.u64 t, %1; cvt.u32.u64 %0, t; }"
        : "=r"(a) : "l"(p));
    return a;
}
__device__ __forceinline__ void ldsm_x4(uint32_t* r, uint32_t addr) {
    asm volatile("ldmatrix.sync.aligned.m8n8.x4.shared.b16 {%0,%1,%2,%3}, [%4];"
                 : "=r"(r[0]), "=r"(r[1]), "=r"(r[2]), "=r"(r[3]) : "r"(addr));
}
__device__ __forceinline__ void mma_bf16(float* c, const uint32_t* a,
                                         const uint32_t* b) {
    asm volatile(
        "mma.sync.aligned.m16n8k16.row.col.f32.bf16.bf16.f32 "
        "{%0,%1,%2,%3}, {%4,%5,%6,%7}, {%8,%9}, {%0,%1,%2,%3};"
        : "+f"(c[0]), "+f"(c[1]), "+f"(c[2]), "+f"(c[3])
        : "r"(a[0]), "r"(a[1]), "r"(a[2]), "r"(a[3]), "r"(b[0]), "r"(b[1]));
}
__device__ __forceinline__ uint32_t pack_bf16(float x, float y) {
    __nv_bfloat162 t = __halves2bfloat162(__float2bfloat16_rn(x),
                                          __float2bfloat16_rn(y));
    return *(uint32_t*)&t;
}
__device__ __forceinline__ void cp16(uint32_t dst, const void* src) {
    asm volatile("cp.async.cg.shared.global [%0], [%1], 16;"
                 :: "r"(dst), "l"(src));
}
#define CP_COMMIT() asm volatile("cp.async.commit_group;" ::: "memory")
#define CP_WAIT(n)  asm volatile("cp.async.wait_group %0;" :: "n"(n) : "memory")

// ============== prep branch A: weights + q split ============================
#define PQW_B0 1088
#define PQW_NB (PQW_B0 + (MQ * CDIM / 4) / 256)     // 9280

__global__ __launch_bounds__(256)
void prep_qw_kernel(const float* __restrict__ W_val,
                    const float* __restrict__ b_val,
                    const float* __restrict__ W_off,
                    const float* __restrict__ b_off,
                    const float* __restrict__ W_attn,
                    const float* __restrict__ b_attn,
                    const float* __restrict__ W_out,
                    const float* __restrict__ b_out,
                    const float* __restrict__ query,
                    const float* __restrict__ qpos)
{
    const int bx = blockIdx.x;
    const int tid = threadIdx.x;
    if (bx < PQW_B0) {
        const int n = bx, k = tid;
        float x, bb;
        if (n < 256)      { x = W_val[k * 256 + n];          bb = b_val[n]; }
        else if (n < 832) {
            const int m = n - 256;
            if (m < 384)  { x = W_off[k * 384 + m];          bb = b_off[m]; }
            else          { x = W_attn[k * 192 + (m - 384)]; bb = b_attn[m - 384]; }
        }
        else              { x = W_out[k * 256 + (n - 832)];  bb = b_out[n - 832]; }
        const __nv_bfloat16 hi = __float2bfloat16_rn(x);
        const __nv_bfloat16 lo = __float2bfloat16_rn(x - __bfloat162float(hi));
        g_Wt_hi[n * CDIM + k] = hi;
        g_Wt_lo[n * CDIM + k] = lo;
        if (k == 0) g_bias[n] = bb;
        return;
    }
    const size_t i4 = (size_t)(bx - PQW_B0) * 256 + tid;
    float4 v = ((const float4*)query)[i4];
    const float4 u = ((const float4*)qpos)[i4];
    v.x += u.x; v.y += u.y; v.z += u.z; v.w += u.w;
    const float hx = __bfloat162float(__float2bfloat16_rn(v.x));
    const float hy = __bfloat162float(__float2bfloat16_rn(v.y));
    const float hz = __bfloat162float(__float2bfloat16_rn(v.z));
    const float hw = __bfloat162float(__float2bfloat16_rn(v.w));
    ((uint2*)g_q_h)[i4] = make_uint2(pack_bf16(v.x, v.y), pack_bf16(v.z, v.w));
    ((uint2*)g_q_l)[i4] = make_uint2(pack_bf16(v.x - hx, v.y - hy),
                                     pack_bf16(v.z - hz, v.w - hw));
}

// ============== prep branch B: value split ==================================
#define PV_NB ((MV * CDIM / 4) / 256)               // 21504

__global__ __launch_bounds__(256)
void prep_v_kernel(const float* __restrict__ value)
{
    const size_t i4 = (size_t)blockIdx.x * 256 + threadIdx.x;
    const float4 v = ((const float4*)value)[i4];
    const float hx = __bfloat162float(__float2bfloat16_rn(v.x));
    const float hy = __bfloat162float(__float2bfloat16_rn(v.y));
    const float hz = __bfloat162float(__float2bfloat16_rn(v.z));
    const float hw = __bfloat162float(__float2bfloat16_rn(v.w));
    ((uint2*)g_val_h)[i4] = make_uint2(pack_bf16(v.x, v.y), pack_bf16(v.z, v.w));
    ((uint2*)g_val_l)[i4] = make_uint2(pack_bf16(v.x - hx, v.y - hy),
                                       pack_bf16(v.z - hz, v.w - hw));
}

// ============== bf16-split HMMA GEMM, 2-stage dual-sync (round-11 core) ====
// MODE 0: C fp32, 3 terms            (qa GEMM)
// MODE 1: C fp32 + residual, 3 terms (out GEMM)
// MODE 2: C bf16 head-major, 2 terms (vproj; Bl dropped)
// m0 = row offset of this launch (batch-slicing).
#define HG_STG   24576
#define HG_SMEM  49152

template <int MODE>
__global__ __launch_bounds__(256, 4)
void hgemm2_kernel(const __nv_bfloat16* __restrict__ Ath,
                   const __nv_bfloat16* __restrict__ Atl,
                   const __nv_bfloat16* __restrict__ Bth,
                   const __nv_bfloat16* __restrict__ Btl,
                   const float* __restrict__ bias,
                   const float* __restrict__ resid, float* __restrict__ Cf,
                   __nv_bfloat16* __restrict__ Cb,
                   int m0, int N, int K)
{
    extern __shared__ __align__(16) uint8_t smem[];
    const uint32_t uS = smem_u32(smem);

    const int tid  = threadIdx.x;
    const int lane = tid & 31;
    const int wid  = tid >> 5;
    const int wm   = wid >> 1;
    const int wn   = wid & 1;
    const int bm   = m0 + blockIdx.x * 128;
    const int bn   = blockIdx.y * 64;
    const int KT   = K >> 5;

    const int lrA  = ((lane >> 3) & 1) * 8 + (lane & 7);
    const int lk8A = lane >> 4;
    const int rowA = wm * 32 + lrA;
    const int xrA  = (rowA >> 1) & 3;
    const uint32_t offA0 = (uint32_t)(rowA * 64 + ((0 * 2 + lk8A) ^ xrA) * 16);
    const uint32_t offA1 = (uint32_t)(rowA * 64 + ((1 * 2 + lk8A) ^ xrA) * 16);

    const int lrB  = (lane >> 4) * 8 + (lane & 7);
    const int lk8B = (lane >> 3) & 1;
    const int rowB = wn * 32 + lrB;
    const int xrB  = (rowB >> 1) & 3;
    const uint32_t offB0 = (uint32_t)(16384 + rowB * 64 + ((0 * 2 + lk8B) ^ xrB) * 16);
    const uint32_t offB1 = (uint32_t)(16384 + rowB * 64 + ((1 * 2 + lk8B) ^ xrB) * 16);

    const int ar0 = tid >> 2, ac0 = tid & 3;
    const int ar1 = ar0 + 64;
    const int br  = tid >> 2, bc = tid & 3;
    const uint32_t sA0 = (uint32_t)(ar0 * 64 + ((ac0 ^ ((ar0 >> 1) & 3)) * 16));
    const uint32_t sA1 = (uint32_t)(ar1 * 64 + ((ac0 ^ ((ar1 >> 1) & 3)) * 16));
    const uint32_t sB  = (uint32_t)(16384 + br * 64 + ((bc ^ ((br >> 1) & 3)) * 16));

    float acc[2][4][4];
#pragma unroll
    for (int t = 0; t < 2; t++)
#pragma unroll
        for (int u = 0; u < 4; u++)
#pragma unroll
            for (int i = 0; i < 4; i++) acc[t][u][i] = 0.f;

    auto issue = [&](int kt, int buf) {
        const int k0 = kt * 32;
        const uint32_t base = uS + buf * HG_STG;
        const size_t oa0 = (size_t)(bm + ar0) * K + k0 + ac0 * 8;
        const size_t oa1 = (size_t)(bm + ar1) * K + k0 + ac0 * 8;
        const size_t ob  = (size_t)(bn + br ) * K + k0 + bc  * 8;
        cp16(base +         sA0, Ath + oa0);
        cp16(base +         sA1, Ath + oa1);
        cp16(base + 8192u + sA0, Atl + oa0);
        cp16(base + 8192u + sA1, Atl + oa1);
        cp16(base +         sB,  Bth + ob);
        if (MODE != 2)
            cp16(base + 4096u + sB, Btl + ob);
        CP_COMMIT();
    };

    issue(0, 0);
    issue(1, 1);

#pragma unroll 1
    for (int kt = 0; kt < KT; kt++) {
        if (kt == KT - 1) { CP_WAIT(0); } else { CP_WAIT(1); }
        __syncthreads();

        const uint32_t sb = uS + (kt & 1) * HG_STG;
#pragma unroll
        for (int ks = 0; ks < 2; ks++) {
            const uint32_t oA = sb + (ks ? offA1 : offA0);
            const uint32_t oB = sb + (ks ? offB1 : offB0);
            uint32_t bH[4][2], bL[4][2];
            ldsm_x4(&bH[0][0], oB);
            ldsm_x4(&bH[2][0], oB + 1024);
            if (MODE != 2) {
                ldsm_x4(&bL[0][0], oB + 4096);
                ldsm_x4(&bL[2][0], oB + 4096 + 1024);
            }
#pragma unroll
            for (int t = 0; t < 2; t++) {
                uint32_t aH[4], aL[4];
                ldsm_x4(aH, oA + t * 1024);
                ldsm_x4(aL, oA + 8192 + t * 1024);
#pragma unroll
                for (int u = 0; u < 4; u++) {
                    mma_bf16(acc[t][u], aH, bH[u]);
                    if (MODE != 2) mma_bf16(acc[t][u], aH, bL[u]);
                    mma_bf16(acc[t][u], aL, bH[u]);
                }
            }
        }
        __syncthreads();
        if (kt + 2 < KT) issue(kt + 2, kt & 1);
    }

    // ---- epilogue ----
    const int g = lane >> 2, tg = lane & 3;
    const int batch = bm / NVAL;
    const int head  = (bn + wn * 32) >> 5;     // MODE 2 only
#pragma unroll
    for (int t = 0; t < 2; t++)
#pragma unroll
        for (int u = 0; u < 4; u++) {
            const int row = bm + wm * 32 + t * 16 + g;
            const int col = bn + wn * 32 + u * 8 + tg * 2;
            const float2 bv = *(const float2*)(bias + col);
            float2 o0 = make_float2(acc[t][u][0] + bv.x, acc[t][u][1] + bv.y);
            float2 o1 = make_float2(acc[t][u][2] + bv.x, acc[t][u][3] + bv.y);
            if (MODE == 1) {
                const float2 r0 = *(const float2*)(resid + (size_t)row * N + col);
                const float2 r1 = *(const float2*)(resid + (size_t)(row + 8) * N + col);
                o0.x += r0.x; o0.y += r0.y;
                o1.x += r1.x; o1.y += r1.y;
            }
            if (MODE == 2) {
                const int nv = row - batch * NVAL;
                const int dim = u * 8 + tg * 2;
                const size_t base =
                    ((size_t)(batch * NHEAD + head) * NVAL + nv) * DHEAD + dim;
                *(uint32_t*)(Cb + base)              = pack_bf16(o0.x, o0.y);
                *(uint32_t*)(Cb + base + 8 * DHEAD)  = pack_bf16(o1.x, o1.y);
            } else {
                *(float2*)(Cf + (size_t)row * N + col) = o0;
                *(float2*)(Cf + (size_t)(row + 8) * N + col) = o1;
            }
        }
}

// ---------------- sampling kernel: bf16 head-major gather ------------------
// warp0 = global warp offset for batch-sliced launches.
__global__ __launch_bounds__(256)
void sample_kernel(const float* __restrict__ refp, int warp0)
{
    __shared__ __align__(16) unsigned long long sm_iw[8][4][24];

    const int wslot = threadIdx.x >> 5;
    const int warp = warp0 + blockIdx.x * 8 + wslot;
    const int lane = threadIdx.x & 31;
    const int h  = warp & 7;
    const int bq = warp >> 3;
    const int b  = bq >> 12;

    float a = -INFINITY;
    if (lane < 24) a = g_qa[(size_t)bq * NQA + NOFF + h * 24 + lane];
    float m = a;
#pragma unroll
    for (int s = 16; s; s >>= 1) m = fmaxf(m, __shfl_xor_sync(0xffffffffu, m, s));
    float e = (lane < 24) ? __expf(a - m) : 0.f;
    float ssum = e;
#pragma unroll
    for (int s = 16; s; s >>= 1) ssum += __shfl_xor_sync(0xffffffffu, ssum, s);
    const float aw = e / ssum;

    if (lane < 24) {
        const int l = lane >> 2;
        const int p = lane & 3;
        const int H = c_H[l], W = c_W[l], S = c_S[l];
        const size_t ob = (size_t)bq * NQA + (((h * NLVL + l) * NPT + p) << 1);
        const float offx = g_qa[ob + 0];
        const float offy = g_qa[ob + 1];
        const size_t rb = ((size_t)bq * NLVL + l) << 1;
        const float rx = refp[rb + 0];
        const float ry = refp[rb + 1];
        const float x = rx * (float)W + offx - 0.5f;
        const float y = ry * (float)H + offy - 0.5f;
        const float xf = floorf(x), yf = floorf(y);
        const float lx = x - xf, ly = y - yf;
        const int ix = (int)xf, iy = (int)yf;
        const bool vx0 = (ix     >= 0) && (ix     < W);
        const bool vx1 = (ix + 1 >= 0) && (ix + 1 < W);
        const bool vy0 = (iy     >= 0) && (iy     < H);
        const bool vy1 = (iy + 1 >= 0) && (iy + 1 < H);
        const int cx0 = min(max(ix, 0), W - 1);
        const int cx1 = min(max(ix + 1, 0), W - 1);
        const int cy0 = min(max(iy, 0), H - 1);
        const int cy1 = min(max(iy + 1, 0), H - 1);
        const unsigned o00 = (unsigned)(S + cy0 * W + cx0) << 6;
        const unsigned o01 = (unsigned)(S + cy0 * W + cx1) << 6;
        const unsigned o10 = (unsigned)(S + cy1 * W + cx0) << 6;
        const unsigned o11 = (unsigned)(S + cy1 * W + cx1) << 6;
        const float w00 = aw * (1.f - lx) * (1.f - ly) * (float)(vx0 && vy0);
        const float w01 = aw * lx         * (1.f - ly) * (float)(vx1 && vy0);
        const float w10 = aw * (1.f - lx) * ly         * (float)(vx0 && vy1);
        const float w11 = aw * lx         * ly         * (float)(vx1 && vy1);
        sm_iw[wslot][0][lane] =
            (unsigned long long)o00 | ((unsigned long long)__float_as_uint(w00) << 32);
        sm_iw[wslot][1][lane] =
            (unsigned long long)o01 | ((unsigned long long)__float_as_uint(w01) << 32);
        sm_iw[wslot][2][lane] =
            (unsigned long long)o10 | ((unsigned long long)__float_as_uint(w10) << 32);
        sm_iw[wslot][3][lane] =
            (unsigned long long)o11 | ((unsigned long long)__float_as_uint(w11) << 32);
    }
    __syncwarp();

    const int g  = lane >> 3;
    const int li = lane & 7;
    const char* __restrict__ vbb =
        (const char*)g_vbf + (size_t)(b * NHEAD + h) * NVAL * (DHEAD * 2) + li * 8;

    float4 acc0 = make_float4(0.f, 0.f, 0.f, 0.f);
    float4 acc1 = make_float4(0.f, 0.f, 0.f, 0.f);
#pragma unroll
    for (int j = 0; j < 12; j++) {
        const uint4 t = *(const uint4*)&sm_iw[wslot][g][2 * j];
        const float w0 = __uint_as_float(t.y);
        const float w1 = __uint_as_float(t.w);
        const uint2 v0 = *(const uint2*)(vbb + t.x);
        const uint2 v1 = *(const uint2*)(vbb + t.z);
        acc0.x = fmaf(w0, __uint_as_float(v0.x << 16),         acc0.x);
        acc0.y = fmaf(w0, __uint_as_float(v0.x & 0xffff0000u), acc0.y);
        acc0.z = fmaf(w0, __uint_as_float(v0.y << 16),         acc0.z);
        acc0.w = fmaf(w0, __uint_as_float(v0.y & 0xffff0000u), acc0.w);
        acc1.x = fmaf(w1, __uint_as_float(v1.x << 16),         acc1.x);
        acc1.y = fmaf(w1, __uint_as_float(v1.x & 0xffff0000u), acc1.y);
        acc1.z = fmaf(w1, __uint_as_float(v1.y << 16),         acc1.z);
        acc1.w = fmaf(w1, __uint_as_float(v1.y & 0xffff0000u), acc1.w);
    }
    float4 acc = make_float4(acc0.x + acc1.x, acc0.y + acc1.y,
                             acc0.z + acc1.z, acc0.w + acc1.w);
#pragma unroll
    for (int s = 8; s <= 16; s <<= 1) {
        acc.x += __shfl_xor_sync(0xffffffffu, acc.x, s);
        acc.y += __shfl_xor_sync(0xffffffffu, acc.y, s);
        acc.z += __shfl_xor_sync(0xffffffffu, acc.z, s);
        acc.w += __shfl_xor_sync(0xffffffffu, acc.w, s);
    }
    if (lane < 8) {
        const size_t o4 = ((size_t)bq * CDIM + h * DHEAD + lane * 4) >> 2;
        const float hx = __bfloat162float(__float2bfloat16_rn(acc.x));
        const float hy = __bfloat162float(__float2bfloat16_rn(acc.y));
        const float hz = __bfloat162float(__float2bfloat16_rn(acc.z));
        const float hw = __bfloat162float(__float2bfloat16_rn(acc.w));
        ((uint2*)g_ms_h)[o4] = make_uint2(pack_bf16(acc.x, acc.y),
                                          pack_bf16(acc.z, acc.w));
        ((uint2*)g_ms_l)[o4] = make_uint2(pack_bf16(acc.x - hx, acc.y - hy),
                                          pack_bf16(acc.z - hz, acc.w - hw));
    }
}

// ---------------- launch: batch-sliced 3-stream pipeline --------------------
extern "C" void kernel_launch(void* const* d_in, const int* in_sizes, int n_in,
                              void* d_out, int out_size)
{
    const float* query  = (const float*)d_in[0];
    const float* qpos   = (const float*)d_in[1];
    const float* value  = (const float*)d_in[2];
    const float* refp   = (const float*)d_in[3];
    const float* W_off  = (const float*)d_in[5];
    const float* b_off  = (const float*)d_in[6];
    const float* W_attn = (const float*)d_in[7];
    const float* b_attn = (const float*)d_in[8];
    const float* W_val  = (const float*)d_in[9];
    const float* b_val  = (const float*)d_in[10];
    const float* W_out  = (const float*)d_in[11];
    const float* b_out  = (const float*)d_in[12];
    float* out = (float*)d_out;

    float *qa, *biasb;
    __nv_bfloat16 *vbf, *wth, *wtl, *valh, *vall, *qh, *ql, *msh, *msl;
    cudaGetSymbolAddress((void**)&vbf,   g_vbf);
    cudaGetSymbolAddress((void**)&qa,    g_qa);
    cudaGetSymbolAddress((void**)&biasb, g_bias);
    cudaGetSymbolAddress((void**)&wth,   g_Wt_hi);
    cudaGetSymbolAddress((void**)&wtl,   g_Wt_lo);
    cudaGetSymbolAddress((void**)&valh,  g_val_h);
    cudaGetSymbolAddress((void**)&vall,  g_val_l);
    cudaGetSymbolAddress((void**)&qh,    g_q_h);
    cudaGetSymbolAddress((void**)&ql,    g_q_l);
    cudaGetSymbolAddress((void**)&msh,   g_ms_h);
    cudaGetSymbolAddress((void**)&msl,   g_ms_l);

    static cudaStream_t s2 = nullptr, s3 = nullptr;
    static cudaEvent_t evFork, evV1, evV2, evQ1, evQ2, evS1, evS2;
    if (!s2) {
        cudaFuncSetAttribute(hgemm2_kernel<0>,
                             cudaFuncAttributeMaxDynamicSharedMemorySize, HG_SMEM);
        cudaFuncSetAttribute(hgemm2_kernel<1>,
                             cudaFuncAttributeMaxDynamicSharedMemorySize, HG_SMEM);
        cudaFuncSetAttribute(hgemm2_kernel<2>,
                             cudaFuncAttributeMaxDynamicSharedMemorySize, HG_SMEM);
        cudaStreamCreateWithFlags(&s2, cudaStreamNonBlocking);
        cudaStreamCreateWithFlags(&s3, cudaStreamNonBlocking);
        cudaEventCreateWithFlags(&evFork, cudaEventDisableTiming);
        cudaEventCreateWithFlags(&evV1, cudaEventDisableTiming);
        cudaEventCreateWithFlags(&evV2, cudaEventDisableTiming);
        cudaEventCreateWithFlags(&evQ1, cudaEventDisableTiming);
        cudaEventCreateWithFlags(&evQ2, cudaEventDisableTiming);
        cudaEventCreateWithFlags(&evS1, cudaEventDisableTiming);
        cudaEventCreateWithFlags(&evS2, cudaEventDisableTiming);
    }

    // ---- fork ----
    cudaEventRecord(evFork, 0);
    cudaStreamWaitEvent(s2, evFork, 0);
    cudaStreamWaitEvent(s3, evFork, 0);

    // s2: value chain, batch-sliced vproj
    prep_v_kernel<<<PV_NB, 256, 0, s2>>>(value);
    hgemm2_kernel<2><<<dim3(MVH / 128, CDIM / 64), 256, HG_SMEM, s2>>>(
        valh, vall, wth, wtl, biasb, nullptr, nullptr, vbf, 0, CDIM, CDIM);
    cudaEventRecord(evV1, s2);
    hgemm2_kernel<2><<<dim3(MVH / 128, CDIM / 64), 256, HG_SMEM, s2>>>(
        valh, vall, wth, wtl, biasb, nullptr, nullptr, vbf, MVH, CDIM, CDIM);
    cudaEventRecord(evV2, s2);

    // s0: query chain, batch-sliced qa
    prep_qw_kernel<<<PQW_NB, 256>>>(W_val, b_val, W_off, b_off,
                                    W_attn, b_attn, W_out, b_out, query, qpos);
    hgemm2_kernel<0><<<dim3(MQH / 128, NQA / 64), 256, HG_SMEM>>>(
        qh, ql, wth + 256 * CDIM, wtl + 256 * CDIM, biasb + 256,
        nullptr, qa, nullptr, 0, NQA, CDIM);
    cudaEventRecord(evQ1, 0);
    hgemm2_kernel<0><<<dim3(MQH / 128, NQA / 64), 256, HG_SMEM>>>(
        qh, ql, wth + 256 * CDIM, wtl + 256 * CDIM, biasb + 256,
        nullptr, qa, nullptr, MQH, NQA, CDIM);
    cudaEventRecord(evQ2, 0);

    // s3: samplers (half i needs vproj_i + qa_i)
    cudaStreamWaitEvent(s3, evQ1, 0);
    cudaStreamWaitEvent(s3, evV1, 0);
    sample_kernel<<<(MQH * NHEAD) / 8, 256, 0, s3>>>(refp, 0);
    cudaEventRecord(evS1, s3);
    cudaStreamWaitEvent(s3, evQ2, 0);
    cudaStreamWaitEvent(s3, evV2, 0);
    sample_kernel<<<(MQH * NHEAD) / 8, 256, 0, s3>>>(refp, MQH * NHEAD);
    cudaEventRecord(evS2, s3);

    // s0: out GEMM halves (half i needs sampler_i)
    cudaStreamWaitEvent(0, evS1, 0);
    hgemm2_kernel<1><<<dim3(MQH / 128, CDIM / 64), 256, HG_SMEM>>>(
        msh, msl, wth + 832 * CDIM, wtl + 832 * CDIM, biasb + 832,
        query, out, nullptr, 0, CDIM, CDIM);
    cudaStreamWaitEvent(0, evS2, 0);
    hgemm2_kernel<1><<<dim3(MQH / 128, CDIM / 64), 256, HG_SMEM>>>(
        msh, msl, wth + 832 * CDIM, wtl + 832 * CDIM, biasb + 832,
        query, out, nullptr, MQH, CDIM, CDIM);
}

// round 14
// speedup vs baseline: 1.3659x; 1.0690x over previous
#include <cuda_runtime.h>
#include <cuda_bf16.h>
#include <math.h>
#include <stdint.h>

// ---------------- problem constants (static per reference) ----------------
#define BSZ   8
#define NQ    4096
#define CDIM  256
#define NHEAD 8
#define NPT   4
#define NLVL  6
#define NVAL  10752
#define DHEAD 32
#define NOFF  384
#define NATT  192
#define NQA   576
#define NWT   1088
#define MQ    (BSZ * NQ)   // 32768
#define MV    (BSZ * NVAL) // 86016
#define NSLC  4
#define MVS   (MV / NSLC)  // 21504 (2 batches)
#define MQS   (MQ / NSLC)  // 8192

// ---------------- device scratch (static, no allocation) ------------------
__device__ __nv_bfloat16 g_vbf [(size_t)MV * CDIM];    // vproj bf16, head-major
__device__ float g_qa   [(size_t)MQ * NQA];            // [off(384) | attn(192)]
__device__ __nv_bfloat16 g_val_h[(size_t)MV * CDIM];   // value bf16 (hi only)
__device__ __nv_bfloat16 g_q_h  [(size_t)MQ * CDIM];
__device__ __nv_bfloat16 g_q_l  [(size_t)MQ * CDIM];
__device__ __nv_bfloat16 g_ms_h [(size_t)MQ * CDIM];
__device__ __nv_bfloat16 g_ms_l [(size_t)MQ * CDIM];
__device__ __nv_bfloat16 g_Wt_hi[NWT * CDIM];
__device__ __nv_bfloat16 g_Wt_lo[NWT * CDIM];
__device__ float g_bias[NWT];

__constant__ int c_H[NLVL] = {64, 32, 16, 64, 32, 16};
__constant__ int c_W[NLVL] = {64, 32, 16, 64, 32, 16};
__constant__ int c_S[NLVL] = {0, 4096, 5120, 5376, 9472, 10496};

// ---------------- small helpers -------------------------------------------
__device__ __forceinline__ uint32_t smem_u32(const void* p) {
    uint32_t a;
    asm("{ .reg .u64 t; cvta.to.shared.u64 t, %1; cvt.u32.u64 %0, t; }"
        : "=r"(a) : "l"(p));
    return a;
}
__device__ __forceinline__ void ldsm_x4(uint32_t* r, uint32_t addr) {
    asm volatile("ldmatrix.sync.aligned.m8n8.x4.shared.b16 {%0,%1,%2,%3}, [%4];"
                 : "=r"(r[0]), "=r"(r[1]), "=r"(r[2]), "=r"(r[3]) : "r"(addr));
}
__device__ __forceinline__ void mma_bf16(float* c, const uint32_t* a,
                                         const uint32_t* b) {
    asm volatile(
        "mma.sync.aligned.m16n8k16.row.col.f32.bf16.bf16.f32 "
        "{%0,%1,%2,%3}, {%4,%5,%6,%7}, {%8,%9}, {%0,%1,%2,%3};"
        : "+f"(c[0]), "+f"(c[1]), "+f"(c[2]), "+f"(c[3])
        : "r"(a[0]), "r"(a[1]), "r"(a[2]), "r"(a[3]), "r"(b[0]), "r"(b[1]));
}
__device__ __forceinline__ uint32_t pack_bf16(float x, float y) {
    __nv_bfloat162 t = __halves2bfloat162(__float2bfloat16_rn(x),
                                          __float2bfloat16_rn(y));
    return *(uint32_t*)&t;
}
__device__ __forceinline__ void cp16(uint32_t dst, const void* src) {
    asm volatile("cp.async.cg.shared.global [%0], [%1], 16;"
                 :: "r"(dst), "l"(src));
}
#define CP_COMMIT() asm volatile("cp.async.commit_group;" ::: "memory")
#define CP_WAIT(n)  asm volatile("cp.async.wait_group %0;" :: "n"(n) : "memory")

// ============== prep branch A: weights + q split ============================
#define PQW_B0 1088
#define PQW_NB (PQW_B0 + (MQ * CDIM / 4) / 256)     // 9280

__global__ __launch_bounds__(256)
void prep_qw_kernel(const float* __restrict__ W_val,
                    const float* __restrict__ b_val,
                    const float* __restrict__ W_off,
                    const float* __restrict__ b_off,
                    const float* __restrict__ W_attn,
                    const float* __restrict__ b_attn,
                    const float* __restrict__ W_out,
                    const float* __restrict__ b_out,
                    const float* __restrict__ query,
                    const float* __restrict__ qpos)
{
    const int bx = blockIdx.x;
    const int tid = threadIdx.x;
    if (bx < PQW_B0) {
        const int n = bx, k = tid;
        float x, bb;
        if (n < 256)      { x = W_val[k * 256 + n];          bb = b_val[n]; }
        else if (n < 832) {
            const int m = n - 256;
            if (m < 384)  { x = W_off[k * 384 + m];          bb = b_off[m]; }
            else          { x = W_attn[k * 192 + (m - 384)]; bb = b_attn[m - 384]; }
        }
        else              { x = W_out[k * 256 + (n - 832)];  bb = b_out[n - 832]; }
        const __nv_bfloat16 hi = __float2bfloat16_rn(x);
        const __nv_bfloat16 lo = __float2bfloat16_rn(x - __bfloat162float(hi));
        g_Wt_hi[n * CDIM + k] = hi;
        g_Wt_lo[n * CDIM + k] = lo;
        if (k == 0) g_bias[n] = bb;
        return;
    }
    const size_t i4 = (size_t)(bx - PQW_B0) * 256 + tid;
    float4 v = ((const float4*)query)[i4];
    const float4 u = ((const float4*)qpos)[i4];
    v.x += u.x; v.y += u.y; v.z += u.z; v.w += u.w;
    const float hx = __bfloat162float(__float2bfloat16_rn(v.x));
    const float hy = __bfloat162float(__float2bfloat16_rn(v.y));
    const float hz = __bfloat162float(__float2bfloat16_rn(v.z));
    const float hw = __bfloat162float(__float2bfloat16_rn(v.w));
    ((uint2*)g_q_h)[i4] = make_uint2(pack_bf16(v.x, v.y), pack_bf16(v.z, v.w));
    ((uint2*)g_q_l)[i4] = make_uint2(pack_bf16(v.x - hx, v.y - hy),
                                     pack_bf16(v.z - hz, v.w - hw));
}

// ============== prep branch B: value -> bf16 (hi only) ======================
#define PV_NB ((MV * CDIM / 4) / 256)               // 21504

__global__ __launch_bounds__(256)
void prep_v_kernel(const float* __restrict__ value)
{
    const size_t i4 = (size_t)blockIdx.x * 256 + threadIdx.x;
    const float4 v = ((const float4*)value)[i4];
    ((uint2*)g_val_h)[i4] = make_uint2(pack_bf16(v.x, v.y), pack_bf16(v.z, v.w));
}

// ============== bf16-split HMMA GEMM, 2-stage dual-sync =====================
// MODE 0: C fp32, 3 terms            (qa GEMM)
// MODE 1: C fp32 + residual, 3 terms (out GEMM)
// MODE 2: C bf16 head-major, 1 term  (vproj: D = Ah*Bh; value+weights in bf16)
#define HG_STG   24576
#define HG_SMEM  49152

template <int MODE>
__global__ __launch_bounds__(256, 4)
void hgemm2_kernel(const __nv_bfloat16* __restrict__ Ath,
                   const __nv_bfloat16* __restrict__ Atl,
                   const __nv_bfloat16* __restrict__ Bth,
                   const __nv_bfloat16* __restrict__ Btl,
                   const float* __restrict__ bias,
                   const float* __restrict__ resid, float* __restrict__ Cf,
                   __nv_bfloat16* __restrict__ Cb,
                   int m0, int N, int K)
{
    extern __shared__ __align__(16) uint8_t smem[];
    const uint32_t uS = smem_u32(smem);

    const int tid  = threadIdx.x;
    const int lane = tid & 31;
    const int wid  = tid >> 5;
    const int wm   = wid >> 1;
    const int wn   = wid & 1;
    const int bm   = m0 + blockIdx.x * 128;
    const int bn   = blockIdx.y * 64;
    const int KT   = K >> 5;

    const int lrA  = ((lane >> 3) & 1) * 8 + (lane & 7);
    const int lk8A = lane >> 4;
    const int rowA = wm * 32 + lrA;
    const int xrA  = (rowA >> 1) & 3;
    const uint32_t offA0 = (uint32_t)(rowA * 64 + ((0 * 2 + lk8A) ^ xrA) * 16);
    const uint32_t offA1 = (uint32_t)(rowA * 64 + ((1 * 2 + lk8A) ^ xrA) * 16);

    const int lrB  = (lane >> 4) * 8 + (lane & 7);
    const int lk8B = (lane >> 3) & 1;
    const int rowB = wn * 32 + lrB;
    const int xrB  = (rowB >> 1) & 3;
    const uint32_t offB0 = (uint32_t)(16384 + rowB * 64 + ((0 * 2 + lk8B) ^ xrB) * 16);
    const uint32_t offB1 = (uint32_t)(16384 + rowB * 64 + ((1 * 2 + lk8B) ^ xrB) * 16);

    const int ar0 = tid >> 2, ac0 = tid & 3;
    const int ar1 = ar0 + 64;
    const int br  = tid >> 2, bc = tid & 3;
    const uint32_t sA0 = (uint32_t)(ar0 * 64 + ((ac0 ^ ((ar0 >> 1) & 3)) * 16));
    const uint32_t sA1 = (uint32_t)(ar1 * 64 + ((ac0 ^ ((ar1 >> 1) & 3)) * 16));
    const uint32_t sB  = (uint32_t)(16384 + br * 64 + ((bc ^ ((br >> 1) & 3)) * 16));

    float acc[2][4][4];
#pragma unroll
    for (int t = 0; t < 2; t++)
#pragma unroll
        for (int u = 0; u < 4; u++)
#pragma unroll
            for (int i = 0; i < 4; i++) acc[t][u][i] = 0.f;

    auto issue = [&](int kt, int buf) {
        const int k0 = kt * 32;
        const uint32_t base = uS + buf * HG_STG;
        const size_t oa0 = (size_t)(bm + ar0) * K + k0 + ac0 * 8;
        const size_t oa1 = (size_t)(bm + ar1) * K + k0 + ac0 * 8;
        const size_t ob  = (size_t)(bn + br ) * K + k0 + bc  * 8;
        cp16(base +         sA0, Ath + oa0);
        cp16(base +         sA1, Ath + oa1);
        if (MODE != 2) {
            cp16(base + 8192u + sA0, Atl + oa0);
            cp16(base + 8192u + sA1, Atl + oa1);
        }
        cp16(base +         sB,  Bth + ob);
        if (MODE != 2)
            cp16(base + 4096u + sB, Btl + ob);
        CP_COMMIT();
    };

    issue(0, 0);
    issue(1, 1);

#pragma unroll 1
    for (int kt = 0; kt < KT; kt++) {
        if (kt == KT - 1) { CP_WAIT(0); } else { CP_WAIT(1); }
        __syncthreads();

        const uint32_t sb = uS + (kt & 1) * HG_STG;
#pragma unroll
        for (int ks = 0; ks < 2; ks++) {
            const uint32_t oA = sb + (ks ? offA1 : offA0);
            const uint32_t oB = sb + (ks ? offB1 : offB0);
            uint32_t bH[4][2], bL[4][2];
            ldsm_x4(&bH[0][0], oB);
            ldsm_x4(&bH[2][0], oB + 1024);
            if (MODE != 2) {
                ldsm_x4(&bL[0][0], oB + 4096);
                ldsm_x4(&bL[2][0], oB + 4096 + 1024);
            }
#pragma unroll
            for (int t = 0; t < 2; t++) {
                uint32_t aH[4], aL[4];
                ldsm_x4(aH, oA + t * 1024);
                if (MODE != 2) ldsm_x4(aL, oA + 8192 + t * 1024);
#pragma unroll
                for (int u = 0; u < 4; u++) {
                    mma_bf16(acc[t][u], aH, bH[u]);
                    if (MODE != 2) {
                        mma_bf16(acc[t][u], aH, bL[u]);
                        mma_bf16(acc[t][u], aL, bH[u]);
                    }
                }
            }
        }
        __syncthreads();
        if (kt + 2 < KT) issue(kt + 2, kt & 1);
    }

    // ---- epilogue ----
    const int g = lane >> 2, tg = lane & 3;
    const int batch = bm / NVAL;
    const int head  = (bn + wn * 32) >> 5;     // MODE 2 only
#pragma unroll
    for (int t = 0; t < 2; t++)
#pragma unroll
        for (int u = 0; u < 4; u++) {
            const int row = bm + wm * 32 + t * 16 + g;
            const int col = bn + wn * 32 + u * 8 + tg * 2;
            const float2 bv = *(const float2*)(bias + col);
            float2 o0 = make_float2(acc[t][u][0] + bv.x, acc[t][u][1] + bv.y);
            float2 o1 = make_float2(acc[t][u][2] + bv.x, acc[t][u][3] + bv.y);
            if (MODE == 1) {
                const float2 r0 = *(const float2*)(resid + (size_t)row * N + col);
                const float2 r1 = *(const float2*)(resid + (size_t)(row + 8) * N + col);
                o0.x += r0.x; o0.y += r0.y;
                o1.x += r1.x; o1.y += r1.y;
            }
            if (MODE == 2) {
                const int nv = row - batch * NVAL;
                const int dim = u * 8 + tg * 2;
                const size_t base =
                    ((size_t)(batch * NHEAD + head) * NVAL + nv) * DHEAD + dim;
                *(uint32_t*)(Cb + base)              = pack_bf16(o0.x, o0.y);
                *(uint32_t*)(Cb + base + 8 * DHEAD)  = pack_bf16(o1.x, o1.y);
            } else {
                *(float2*)(Cf + (size_t)row * N + col) = o0;
                *(float2*)(Cf + (size_t)(row + 8) * N + col) = o1;
            }
        }
}

// ---------------- sampling kernel: bf16 head-major gather ------------------
__global__ __launch_bounds__(256)
void sample_kernel(const float* __restrict__ refp, int warp0)
{
    __shared__ __align__(16) unsigned long long sm_iw[8][4][24];

    const int wslot = threadIdx.x >> 5;
    const int warp = warp0 + blockIdx.x * 8 + wslot;
    const int lane = threadIdx.x & 31;
    const int h  = warp & 7;
    const int bq = warp >> 3;
    const int b  = bq >> 12;

    float a = -INFINITY;
    if (lane < 24) a = g_qa[(size_t)bq * NQA + NOFF + h * 24 + lane];
    float m = a;
#pragma unroll
    for (int s = 16; s; s >>= 1) m = fmaxf(m, __shfl_xor_sync(0xffffffffu, m, s));
    float e = (lane < 24) ? __expf(a - m) : 0.f;
    float ssum = e;
#pragma unroll
    for (int s = 16; s; s >>= 1) ssum += __shfl_xor_sync(0xffffffffu, ssum, s);
    const float aw = e / ssum;

    if (lane < 24) {
        const int l = lane >> 2;
        const int p = lane & 3;
        const int H = c_H[l], W = c_W[l], S = c_S[l];
        const size_t ob = (size_t)bq * NQA + (((h * NLVL + l) * NPT + p) << 1);
        const float offx = g_qa[ob + 0];
        const float offy = g_qa[ob + 1];
        const size_t rb = ((size_t)bq * NLVL + l) << 1;
        const float rx = refp[rb + 0];
        const float ry = refp[rb + 1];
        const float x = rx * (float)W + offx - 0.5f;
        const float y = ry * (float)H + offy - 0.5f;
        const float xf = floorf(x), yf = floorf(y);
        const float lx = x - xf, ly = y - yf;
        const int ix = (int)xf, iy = (int)yf;
        const bool vx0 = (ix     >= 0) && (ix     < W);
        const bool vx1 = (ix + 1 >= 0) && (ix + 1 < W);
        const bool vy0 = (iy     >= 0) && (iy     < H);
        const bool vy1 = (iy + 1 >= 0) && (iy + 1 < H);
        const int cx0 = min(max(ix, 0), W - 1);
        const int cx1 = min(max(ix + 1, 0), W - 1);
        const int cy0 = min(max(iy, 0), H - 1);
        const int cy1 = min(max(iy + 1, 0), H - 1);
        const unsigned o00 = (unsigned)(S + cy0 * W + cx0) << 6;
        const unsigned o01 = (unsigned)(S + cy0 * W + cx1) << 6;
        const unsigned o10 = (unsigned)(S + cy1 * W + cx0) << 6;
        const unsigned o11 = (unsigned)(S + cy1 * W + cx1) << 6;
        const float w00 = aw * (1.f - lx) * (1.f - ly) * (float)(vx0 && vy0);
        const float w01 = aw * lx         * (1.f - ly) * (float)(vx1 && vy0);
        const float w10 = aw * (1.f - lx) * ly         * (float)(vx0 && vy1);
        const float w11 = aw * lx         * ly         * (float)(vx1 && vy1);
        sm_iw[wslot][0][lane] =
            (unsigned long long)o00 | ((unsigned long long)__float_as_uint(w00) << 32);
        sm_iw[wslot][1][lane] =
            (unsigned long long)o01 | ((unsigned long long)__float_as_uint(w01) << 32);
        sm_iw[wslot][2][lane] =
            (unsigned long long)o10 | ((unsigned long long)__float_as_uint(w10) << 32);
        sm_iw[wslot][3][lane] =
            (unsigned long long)o11 | ((unsigned long long)__float_as_uint(w11) << 32);
    }
    __syncwarp();

    const int g  = lane >> 3;
    const int li = lane & 7;
    const char* __restrict__ vbb =
        (const char*)g_vbf + (size_t)(b * NHEAD + h) * NVAL * (DHEAD * 2) + li * 8;

    float4 acc0 = make_float4(0.f, 0.f, 0.f, 0.f);
    float4 acc1 = make_float4(0.f, 0.f, 0.f, 0.f);
#pragma unroll
    for (int j = 0; j < 12; j++) {
        const uint4 t = *(const uint4*)&sm_iw[wslot][g][2 * j];
        const float w0 = __uint_as_float(t.y);
        const float w1 = __uint_as_float(t.w);
        const uint2 v0 = *(const uint2*)(vbb + t.x);
        const uint2 v1 = *(const uint2*)(vbb + t.z);
        acc0.x = fmaf(w0, __uint_as_float(v0.x << 16),         acc0.x);
        acc0.y = fmaf(w0, __uint_as_float(v0.x & 0xffff0000u), acc0.y);
        acc0.z = fmaf(w0, __uint_as_float(v0.y << 16),         acc0.z);
        acc0.w = fmaf(w0, __uint_as_float(v0.y & 0xffff0000u), acc0.w);
        acc1.x = fmaf(w1, __uint_as_float(v1.x << 16),         acc1.x);
        acc1.y = fmaf(w1, __uint_as_float(v1.x & 0xffff0000u), acc1.y);
        acc1.z = fmaf(w1, __uint_as_float(v1.y << 16),         acc1.z);
        acc1.w = fmaf(w1, __uint_as_float(v1.y & 0xffff0000u), acc1.w);
    }
    float4 acc = make_float4(acc0.x + acc1.x, acc0.y + acc1.y,
                             acc0.z + acc1.z, acc0.w + acc1.w);
#pragma unroll
    for (int s = 8; s <= 16; s <<= 1) {
        acc.x += __shfl_xor_sync(0xffffffffu, acc.x, s);
        acc.y += __shfl_xor_sync(0xffffffffu, acc.y, s);
        acc.z += __shfl_xor_sync(0xffffffffu, acc.z, s);
        acc.w += __shfl_xor_sync(0xffffffffu, acc.w, s);
    }
    if (lane < 8) {
        const size_t o4 = ((size_t)bq * CDIM + h * DHEAD + lane * 4) >> 2;
        const float hx = __bfloat162float(__float2bfloat16_rn(acc.x));
        const float hy = __bfloat162float(__float2bfloat16_rn(acc.y));
        const float hz = __bfloat162float(__float2bfloat16_rn(acc.z));
        const float hw = __bfloat162float(__float2bfloat16_rn(acc.w));
        ((uint2*)g_ms_h)[o4] = make_uint2(pack_bf16(acc.x, acc.y),
                                          pack_bf16(acc.z, acc.w));
        ((uint2*)g_ms_l)[o4] = make_uint2(pack_bf16(acc.x - hx, acc.y - hy),
                                          pack_bf16(acc.z - hz, acc.w - hw));
    }
}

// ---------------- launch: 4-slice 3-stream pipeline -------------------------
extern "C" void kernel_launch(void* const* d_in, const int* in_sizes, int n_in,
                              void* d_out, int out_size)
{
    const float* query  = (const float*)d_in[0];
    const float* qpos   = (const float*)d_in[1];
    const float* value  = (const float*)d_in[2];
    const float* refp   = (const float*)d_in[3];
    const float* W_off  = (const float*)d_in[5];
    const float* b_off  = (const float*)d_in[6];
    const float* W_attn = (const float*)d_in[7];
    const float* b_attn = (const float*)d_in[8];
    const float* W_val  = (const float*)d_in[9];
    const float* b_val  = (const float*)d_in[10];
    const float* W_out  = (const float*)d_in[11];
    const float* b_out  = (const float*)d_in[12];
    float* out = (float*)d_out;

    float *qa, *biasb;
    __nv_bfloat16 *vbf, *wth, *wtl, *valh, *qh, *ql, *msh, *msl;
    cudaGetSymbolAddress((void**)&vbf,   g_vbf);
    cudaGetSymbolAddress((void**)&qa,    g_qa);
    cudaGetSymbolAddress((void**)&biasb, g_bias);
    cudaGetSymbolAddress((void**)&wth,   g_Wt_hi);
    cudaGetSymbolAddress((void**)&wtl,   g_Wt_lo);
    cudaGetSymbolAddress((void**)&valh,  g_val_h);
    cudaGetSymbolAddress((void**)&qh,    g_q_h);
    cudaGetSymbolAddress((void**)&ql,    g_q_l);
    cudaGetSymbolAddress((void**)&msh,   g_ms_h);
    cudaGetSymbolAddress((void**)&msl,   g_ms_l);

    static cudaStream_t s2 = nullptr, s3 = nullptr;
    static cudaEvent_t evFork, evV[NSLC], evQ[NSLC], evS[NSLC];
    if (!s2) {
        cudaFuncSetAttribute(hgemm2_kernel<0>,
                             cudaFuncAttributeMaxDynamicSharedMemorySize, HG_SMEM);
        cudaFuncSetAttribute(hgemm2_kernel<1>,
                             cudaFuncAttributeMaxDynamicSharedMemorySize, HG_SMEM);
        cudaFuncSetAttribute(hgemm2_kernel<2>,
                             cudaFuncAttributeMaxDynamicSharedMemorySize, HG_SMEM);
        cudaStreamCreateWithFlags(&s2, cudaStreamNonBlocking);
        cudaStreamCreateWithFlags(&s3, cudaStreamNonBlocking);
        cudaEventCreateWithFlags(&evFork, cudaEventDisableTiming);
        for (int i = 0; i < NSLC; i++) {
            cudaEventCreateWithFlags(&evV[i], cudaEventDisableTiming);
            cudaEventCreateWithFlags(&evQ[i], cudaEventDisableTiming);
            cudaEventCreateWithFlags(&evS[i], cudaEventDisableTiming);
        }
    }

    // ---- fork ----
    cudaEventRecord(evFork, 0);
    cudaStreamWaitEvent(s2, evFork, 0);
    cudaStreamWaitEvent(s3, evFork, 0);

    // s2: value chain — prep + vproj slices
    prep_v_kernel<<<PV_NB, 256, 0, s2>>>(value);
    for (int i = 0; i < NSLC; i++) {
        hgemm2_kernel<2><<<dim3(MVS / 128, CDIM / 64), 256, HG_SMEM, s2>>>(
            valh, nullptr, wth, nullptr, biasb, nullptr, nullptr, vbf,
            i * MVS, CDIM, CDIM);
        cudaEventRecord(evV[i], s2);
    }

    // s0: query chain — prep + qa slices
    prep_qw_kernel<<<PQW_NB, 256>>>(W_val, b_val, W_off, b_off,
                                    W_attn, b_attn, W_out, b_out, query, qpos);
    for (int i = 0; i < NSLC; i++) {
        hgemm2_kernel<0><<<dim3(MQS / 128, NQA / 64), 256, HG_SMEM>>>(
            qh, ql, wth + 256 * CDIM, wtl + 256 * CDIM, biasb + 256,
            nullptr, qa, nullptr, i * MQS, NQA, CDIM);
        cudaEventRecord(evQ[i], 0);
    }

    // s3: sampler slices (slice i needs vproj_i + qa_i)
    for (int i = 0; i < NSLC; i++) {
        cudaStreamWaitEvent(s3, evQ[i], 0);
        cudaStreamWaitEvent(s3, evV[i], 0);
        sample_kernel<<<(MQS * NHEAD) / 8, 256, 0, s3>>>(refp, i * MQS * NHEAD);
        cudaEventRecord(evS[i], s3);
    }

    // s2: out GEMM slices (slice i needs sampler_i); s2 is idle after vproj
    for (int i = 0; i < NSLC; i++) {
        cudaStreamWaitEvent(s2, evS[i], 0);
        hgemm2_kernel<1><<<dim3(MQS / 128, CDIM / 64), 256, HG_SMEM, s2>>>(
            msh, msl, wth + 832 * CDIM, wtl + 832 * CDIM, biasb + 832,
            query, out, nullptr, i * MQS, CDIM, CDIM);
    }

    // join: make stream 0 (capture stream) wait for the last out slice
    static cudaEvent_t evDone = nullptr;
    if (!evDone) cudaEventCreateWithFlags(&evDone, cudaEventDisableTiming);
    cudaEventRecord(evDone, s2);
    cudaStreamWaitEvent(0, evDone, 0);
}

// round 15
// speedup vs baseline: 1.3661x; 1.0002x over previous
#include <cuda_runtime.h>
#include <cuda_bf16.h>
#include <math.h>
#include <stdint.h>

// ---------------- problem constants (static per reference) ----------------
#define BSZ   8
#define NQ    4096
#define CDIM  256
#define NHEAD 8
#define NPT   4
#define NLVL  6
#define NVAL  10752
#define DHEAD 32
#define NOFF  384
#define NATT  192
#define NQA   576
#define NWT   1088
#define MQ    (BSZ * NQ)   // 32768
#define MV    (BSZ * NVAL) // 86016
#define NSLC  4
#define MVS   (MV / NSLC)  // 21504 (2 batches)
#define MQS   (MQ / NSLC)  // 8192

// ---------------- device scratch (static, no allocation) ------------------
__device__ __nv_bfloat16 g_vbf [(size_t)MV * CDIM];    // vproj bf16, head-major
__device__ float g_qa   [(size_t)MQ * NQA];            // [off(384) | attn(192)]
__device__ __nv_bfloat16 g_val_h[(size_t)MV * CDIM];   // value bf16 (hi only)
__device__ __nv_bfloat16 g_q_h  [(size_t)MQ * CDIM];
__device__ __nv_bfloat16 g_q_l  [(size_t)MQ * CDIM];
__device__ __nv_bfloat16 g_ms_h [(size_t)MQ * CDIM];
__device__ __nv_bfloat16 g_ms_l [(size_t)MQ * CDIM];
__device__ __nv_bfloat16 g_Wt_hi[NWT * CDIM];
__device__ __nv_bfloat16 g_Wt_lo[NWT * CDIM];
__device__ float g_bias[NWT];

__constant__ int c_H[NLVL] = {64, 32, 16, 64, 32, 16};
__constant__ int c_W[NLVL] = {64, 32, 16, 64, 32, 16};
__constant__ int c_S[NLVL] = {0, 4096, 5120, 5376, 9472, 10496};

// ---------------- small helpers -------------------------------------------
__device__ __forceinline__ uint32_t smem_u32(const void* p) {
    uint32_t a;
    asm("{ .reg .u64 t; cvta.to.shared.u64 t, %1; cvt.u32.u64 %0, t; }"
        : "=r"(a) : "l"(p));
    return a;
}
__device__ __forceinline__ void ldsm_x4(uint32_t* r, uint32_t addr) {
    asm volatile("ldmatrix.sync.aligned.m8n8.x4.shared.b16 {%0,%1,%2,%3}, [%4];"
                 : "=r"(r[0]), "=r"(r[1]), "=r"(r[2]), "=r"(r[3]) : "r"(addr));
}
__device__ __forceinline__ void mma_bf16(float* c, const uint32_t* a,
                                         const uint32_t* b) {
    asm volatile(
        "mma.sync.aligned.m16n8k16.row.col.f32.bf16.bf16.f32 "
        "{%0,%1,%2,%3}, {%4,%5,%6,%7}, {%8,%9}, {%0,%1,%2,%3};"
        : "+f"(c[0]), "+f"(c[1]), "+f"(c[2]), "+f"(c[3])
        : "r"(a[0]), "r"(a[1]), "r"(a[2]), "r"(a[3]), "r"(b[0]), "r"(b[1]));
}
__device__ __forceinline__ uint32_t pack_bf16(float x, float y) {
    __nv_bfloat162 t = __halves2bfloat162(__float2bfloat16_rn(x),
                                          __float2bfloat16_rn(y));
    return *(uint32_t*)&t;
}
__device__ __forceinline__ void cp16(uint32_t dst, const void* src) {
    asm volatile("cp.async.cg.shared.global [%0], [%1], 16;"
                 :: "r"(dst), "l"(src));
}
#define CP_COMMIT() asm volatile("cp.async.commit_group;" ::: "memory")
#define CP_WAIT(n)  asm volatile("cp.async.wait_group %0;" :: "n"(n) : "memory")

// ============== prep branch A: weights + q split ============================
#define PQW_B0 1088
#define PQW_NB (PQW_B0 + (MQ * CDIM / 4) / 256)     // 9280

__global__ __launch_bounds__(256)
void prep_qw_kernel(const float* __restrict__ W_val,
                    const float* __restrict__ b_val,
                    const float* __restrict__ W_off,
                    const float* __restrict__ b_off,
                    const float* __restrict__ W_attn,
                    const float* __restrict__ b_attn,
                    const float* __restrict__ W_out,
                    const float* __restrict__ b_out,
                    const float* __restrict__ query,
                    const float* __restrict__ qpos)
{
    const int bx = blockIdx.x;
    const int tid = threadIdx.x;
    if (bx < PQW_B0) {
        const int n = bx, k = tid;
        float x, bb;
        if (n < 256)      { x = W_val[k * 256 + n];          bb = b_val[n]; }
        else if (n < 832) {
            const int m = n - 256;
            if (m < 384)  { x = W_off[k * 384 + m];          bb = b_off[m]; }
            else          { x = W_attn[k * 192 + (m - 384)]; bb = b_attn[m - 384]; }
        }
        else              { x = W_out[k * 256 + (n - 832)];  bb = b_out[n - 832]; }
        const __nv_bfloat16 hi = __float2bfloat16_rn(x);
        const __nv_bfloat16 lo = __float2bfloat16_rn(x - __bfloat162float(hi));
        g_Wt_hi[n * CDIM + k] = hi;
        g_Wt_lo[n * CDIM + k] = lo;
        if (k == 0) g_bias[n] = bb;
        return;
    }
    const size_t i4 = (size_t)(bx - PQW_B0) * 256 + tid;
    float4 v = ((const float4*)query)[i4];
    const float4 u = ((const float4*)qpos)[i4];
    v.x += u.x; v.y += u.y; v.z += u.z; v.w += u.w;
    const float hx = __bfloat162float(__float2bfloat16_rn(v.x));
    const float hy = __bfloat162float(__float2bfloat16_rn(v.y));
    const float hz = __bfloat162float(__float2bfloat16_rn(v.z));
    const float hw = __bfloat162float(__float2bfloat16_rn(v.w));
    ((uint2*)g_q_h)[i4] = make_uint2(pack_bf16(v.x, v.y), pack_bf16(v.z, v.w));
    ((uint2*)g_q_l)[i4] = make_uint2(pack_bf16(v.x - hx, v.y - hy),
                                     pack_bf16(v.z - hz, v.w - hw));
}

// ============== prep branch B: value -> bf16 (hi only) ======================
#define PV_NB ((MV * CDIM / 4) / 256)               // 21504

__global__ __launch_bounds__(256)
void prep_v_kernel(const float* __restrict__ value)
{
    const size_t i4 = (size_t)blockIdx.x * 256 + threadIdx.x;
    const float4 v = ((const float4*)value)[i4];
    ((uint2*)g_val_h)[i4] = make_uint2(pack_bf16(v.x, v.y), pack_bf16(v.z, v.w));
}

// ============== bf16-split HMMA GEMM, 3-stage single-sync pipeline ==========
// MODE 0: C fp32, 3 terms            (qa GEMM)
// MODE 1: C fp32 + residual, 3 terms (out GEMM)
// MODE 2: C bf16 head-major, 1 term  (vproj: D = Ah*Bh)
// 3 stages x 24576 B = 73728 B -> 3 CTAs/SM. ONE __syncthreads per k-tile:
// issue(kt+2) targets buffer (kt+2)%3 == (kt-1)%3, consumed in iteration
// kt-1 which the sync at the top of iteration kt has fenced. CP_WAIT(1)
// guarantees group kt complete while kt+1 may stay in flight.
#define HG_STG   24576
#define HG_SMEM  (3 * HG_STG)

template <int MODE>
__global__ __launch_bounds__(256, 3)
void hgemm2_kernel(const __nv_bfloat16* __restrict__ Ath,
                   const __nv_bfloat16* __restrict__ Atl,
                   const __nv_bfloat16* __restrict__ Bth,
                   const __nv_bfloat16* __restrict__ Btl,
                   const float* __restrict__ bias,
                   const float* __restrict__ resid, float* __restrict__ Cf,
                   __nv_bfloat16* __restrict__ Cb,
                   int m0, int N, int K)
{
    extern __shared__ __align__(16) uint8_t smem[];
    const uint32_t uS = smem_u32(smem);

    const int tid  = threadIdx.x;
    const int lane = tid & 31;
    const int wid  = tid >> 5;
    const int wm   = wid >> 1;
    const int wn   = wid & 1;
    const int bm   = m0 + blockIdx.x * 128;
    const int bn   = blockIdx.y * 64;
    const int KT   = K >> 5;

    const int lrA  = ((lane >> 3) & 1) * 8 + (lane & 7);
    const int lk8A = lane >> 4;
    const int rowA = wm * 32 + lrA;
    const int xrA  = (rowA >> 1) & 3;
    const uint32_t offA0 = (uint32_t)(rowA * 64 + ((0 * 2 + lk8A) ^ xrA) * 16);
    const uint32_t offA1 = (uint32_t)(rowA * 64 + ((1 * 2 + lk8A) ^ xrA) * 16);

    const int lrB  = (lane >> 4) * 8 + (lane & 7);
    const int lk8B = (lane >> 3) & 1;
    const int rowB = wn * 32 + lrB;
    const int xrB  = (rowB >> 1) & 3;
    const uint32_t offB0 = (uint32_t)(16384 + rowB * 64 + ((0 * 2 + lk8B) ^ xrB) * 16);
    const uint32_t offB1 = (uint32_t)(16384 + rowB * 64 + ((1 * 2 + lk8B) ^ xrB) * 16);

    const int ar0 = tid >> 2, ac0 = tid & 3;
    const int ar1 = ar0 + 64;
    const int br  = tid >> 2, bc = tid & 3;
    const uint32_t sA0 = (uint32_t)(ar0 * 64 + ((ac0 ^ ((ar0 >> 1) & 3)) * 16));
    const uint32_t sA1 = (uint32_t)(ar1 * 64 + ((ac0 ^ ((ar1 >> 1) & 3)) * 16));
    const uint32_t sB  = (uint32_t)(16384 + br * 64 + ((bc ^ ((br >> 1) & 3)) * 16));

    float acc[2][4][4];
#pragma unroll
    for (int t = 0; t < 2; t++)
#pragma unroll
        for (int u = 0; u < 4; u++)
#pragma unroll
            for (int i = 0; i < 4; i++) acc[t][u][i] = 0.f;

    auto issue = [&](int kt) {
        const int k0 = kt * 32;
        const uint32_t base = uS + (uint32_t)(kt % 3) * HG_STG;
        const size_t oa0 = (size_t)(bm + ar0) * K + k0 + ac0 * 8;
        const size_t oa1 = (size_t)(bm + ar1) * K + k0 + ac0 * 8;
        const size_t ob  = (size_t)(bn + br ) * K + k0 + bc  * 8;
        cp16(base +         sA0, Ath + oa0);
        cp16(base +         sA1, Ath + oa1);
        if (MODE != 2) {
            cp16(base + 8192u + sA0, Atl + oa0);
            cp16(base + 8192u + sA1, Atl + oa1);
        }
        cp16(base +         sB,  Bth + ob);
        if (MODE != 2)
            cp16(base + 4096u + sB, Btl + ob);
        CP_COMMIT();
    };

    issue(0);
    issue(1);

#pragma unroll 1
    for (int kt = 0; kt < KT; kt++) {
        if (kt == KT - 1) { CP_WAIT(0); } else { CP_WAIT(1); }
        __syncthreads();
        if (kt + 2 < KT) issue(kt + 2);

        const uint32_t sb = uS + (uint32_t)(kt % 3) * HG_STG;
#pragma unroll
        for (int ks = 0; ks < 2; ks++) {
            const uint32_t oA = sb + (ks ? offA1 : offA0);
            const uint32_t oB = sb + (ks ? offB1 : offB0);
            uint32_t bH[4][2], bL[4][2];
            ldsm_x4(&bH[0][0], oB);
            ldsm_x4(&bH[2][0], oB + 1024);
            if (MODE != 2) {
                ldsm_x4(&bL[0][0], oB + 4096);
                ldsm_x4(&bL[2][0], oB + 4096 + 1024);
            }
#pragma unroll
            for (int t = 0; t < 2; t++) {
                uint32_t aH[4], aL[4];
                ldsm_x4(aH, oA + t * 1024);
                if (MODE != 2) ldsm_x4(aL, oA + 8192 + t * 1024);
#pragma unroll
                for (int u = 0; u < 4; u++) {
                    mma_bf16(acc[t][u], aH, bH[u]);
                    if (MODE != 2) {
                        mma_bf16(acc[t][u], aH, bL[u]);
                        mma_bf16(acc[t][u], aL, bH[u]);
                    }
                }
            }
        }
    }

    // ---- epilogue ----
    const int g = lane >> 2, tg = lane & 3;
    const int batch = bm / NVAL;
    const int head  = (bn + wn * 32) >> 5;     // MODE 2 only
#pragma unroll
    for (int t = 0; t < 2; t++)
#pragma unroll
        for (int u = 0; u < 4; u++) {
            const int row = bm + wm * 32 + t * 16 + g;
            const int col = bn + wn * 32 + u * 8 + tg * 2;
            const float2 bv = *(const float2*)(bias + col);
            float2 o0 = make_float2(acc[t][u][0] + bv.x, acc[t][u][1] + bv.y);
            float2 o1 = make_float2(acc[t][u][2] + bv.x, acc[t][u][3] + bv.y);
            if (MODE == 1) {
                const float2 r0 = *(const float2*)(resid + (size_t)row * N + col);
                const float2 r1 = *(const float2*)(resid + (size_t)(row + 8) * N + col);
                o0.x += r0.x; o0.y += r0.y;
                o1.x += r1.x; o1.y += r1.y;
            }
            if (MODE == 2) {
                const int nv = row - batch * NVAL;
                const int dim = u * 8 + tg * 2;
                const size_t base =
                    ((size_t)(batch * NHEAD + head) * NVAL + nv) * DHEAD + dim;
                *(uint32_t*)(Cb + base)              = pack_bf16(o0.x, o0.y);
                *(uint32_t*)(Cb + base + 8 * DHEAD)  = pack_bf16(o1.x, o1.y);
            } else {
                *(float2*)(Cf + (size_t)row * N + col) = o0;
                *(float2*)(Cf + (size_t)(row + 8) * N + col) = o1;
            }
        }
}

// ---------------- sampling kernel: bf16 head-major gather ------------------
__global__ __launch_bounds__(256)
void sample_kernel(const float* __restrict__ refp, int warp0)
{
    __shared__ __align__(16) unsigned long long sm_iw[8][4][24];

    const int wslot = threadIdx.x >> 5;
    const int warp = warp0 + blockIdx.x * 8 + wslot;
    const int lane = threadIdx.x & 31;
    const int h  = warp & 7;
    const int bq = warp >> 3;
    const int b  = bq >> 12;

    float a = -INFINITY;
    if (lane < 24) a = g_qa[(size_t)bq * NQA + NOFF + h * 24 + lane];
    float m = a;
#pragma unroll
    for (int s = 16; s; s >>= 1) m = fmaxf(m, __shfl_xor_sync(0xffffffffu, m, s));
    float e = (lane < 24) ? __expf(a - m) : 0.f;
    float ssum = e;
#pragma unroll
    for (int s = 16; s; s >>= 1) ssum += __shfl_xor_sync(0xffffffffu, ssum, s);
    const float aw = e / ssum;

    if (lane < 24) {
        const int l = lane >> 2;
        const int p = lane & 3;
        const int H = c_H[l], W = c_W[l], S = c_S[l];
        const size_t ob = (size_t)bq * NQA + (((h * NLVL + l) * NPT + p) << 1);
        const float2 off2 = *(const float2*)(g_qa + ob);
        const float offx = off2.x;
        const float offy = off2.y;
        const size_t rb = ((size_t)bq * NLVL + l) << 1;
        const float rx = refp[rb + 0];
        const float ry = refp[rb + 1];
        const float x = rx * (float)W + offx - 0.5f;
        const float y = ry * (float)H + offy - 0.5f;
        const float xf = floorf(x), yf = floorf(y);
        const float lx = x - xf, ly = y - yf;
        const int ix = (int)xf, iy = (int)yf;
        const bool vx0 = (ix     >= 0) && (ix     < W);
        const bool vx1 = (ix + 1 >= 0) && (ix + 1 < W);
        const bool vy0 = (iy     >= 0) && (iy     < H);
        const bool vy1 = (iy + 1 >= 0) && (iy + 1 < H);
        const int cx0 = min(max(ix, 0), W - 1);
        const int cx1 = min(max(ix + 1, 0), W - 1);
        const int cy0 = min(max(iy, 0), H - 1);
        const int cy1 = min(max(iy + 1, 0), H - 1);
        const unsigned o00 = (unsigned)(S + cy0 * W + cx0) << 6;
        const unsigned o01 = (unsigned)(S + cy0 * W + cx1) << 6;
        const unsigned o10 = (unsigned)(S + cy1 * W + cx0) << 6;
        const unsigned o11 = (unsigned)(S + cy1 * W + cx1) << 6;
        const float w00 = aw * (1.f - lx) * (1.f - ly) * (float)(vx0 && vy0);
        const float w01 = aw * lx         * (1.f - ly) * (float)(vx1 && vy0);
        const float w10 = aw * (1.f - lx) * ly         * (float)(vx0 && vy1);
        const float w11 = aw * lx         * ly         * (float)(vx1 && vy1);
        sm_iw[wslot][0][lane] =
            (unsigned long long)o00 | ((unsigned long long)__float_as_uint(w00) << 32);
        sm_iw[wslot][1][lane] =
            (unsigned long long)o01 | ((unsigned long long)__float_as_uint(w01) << 32);
        sm_iw[wslot][2][lane] =
            (unsigned long long)o10 | ((unsigned long long)__float_as_uint(w10) << 32);
        sm_iw[wslot][3][lane] =
            (unsigned long long)o11 | ((unsigned long long)__float_as_uint(w11) << 32);
    }
    __syncwarp();

    const int g  = lane >> 3;
    const int li = lane & 7;
    const char* __restrict__ vbb =
        (const char*)g_vbf + (size_t)(b * NHEAD + h) * NVAL * (DHEAD * 2) + li * 8;

    float4 acc0 = make_float4(0.f, 0.f, 0.f, 0.f);
    float4 acc1 = make_float4(0.f, 0.f, 0.f, 0.f);
#pragma unroll
    for (int j = 0; j < 12; j++) {
        const uint4 t = *(const uint4*)&sm_iw[wslot][g][2 * j];
        const float w0 = __uint_as_float(t.y);
        const float w1 = __uint_as_float(t.w);
        const uint2 v0 = *(const uint2*)(vbb + t.x);
        const uint2 v1 = *(const uint2*)(vbb + t.z);
        acc0.x = fmaf(w0, __uint_as_float(v0.x << 16),         acc0.x);
        acc0.y = fmaf(w0, __uint_as_float(v0.x & 0xffff0000u), acc0.y);
        acc0.z = fmaf(w0, __uint_as_float(v0.y << 16),         acc0.z);
        acc0.w = fmaf(w0, __uint_as_float(v0.y & 0xffff0000u), acc0.w);
        acc1.x = fmaf(w1, __uint_as_float(v1.x << 16),         acc1.x);
        acc1.y = fmaf(w1, __uint_as_float(v1.x & 0xffff0000u), acc1.y);
        acc1.z = fmaf(w1, __uint_as_float(v1.y << 16),         acc1.z);
        acc1.w = fmaf(w1, __uint_as_float(v1.y & 0xffff0000u), acc1.w);
    }
    float4 acc = make_float4(acc0.x + acc1.x, acc0.y + acc1.y,
                             acc0.z + acc1.z, acc0.w + acc1.w);
#pragma unroll
    for (int s = 8; s <= 16; s <<= 1) {
        acc.x += __shfl_xor_sync(0xffffffffu, acc.x, s);
        acc.y += __shfl_xor_sync(0xffffffffu, acc.y, s);
        acc.z += __shfl_xor_sync(0xffffffffu, acc.z, s);
        acc.w += __shfl_xor_sync(0xffffffffu, acc.w, s);
    }
    if (lane < 8) {
        const size_t o4 = ((size_t)bq * CDIM + h * DHEAD + lane * 4) >> 2;
        const float hx = __bfloat162float(__float2bfloat16_rn(acc.x));
        const float hy = __bfloat162float(__float2bfloat16_rn(acc.y));
        const float hz = __bfloat162float(__float2bfloat16_rn(acc.z));
        const float hw = __bfloat162float(__float2bfloat16_rn(acc.w));
        ((uint2*)g_ms_h)[o4] = make_uint2(pack_bf16(acc.x, acc.y),
                                          pack_bf16(acc.z, acc.w));
        ((uint2*)g_ms_l)[o4] = make_uint2(pack_bf16(acc.x - hx, acc.y - hy),
                                          pack_bf16(acc.z - hz, acc.w - hw));
    }
}

// ---------------- launch: 4-slice 3-stream pipeline -------------------------
extern "C" void kernel_launch(void* const* d_in, const int* in_sizes, int n_in,
                              void* d_out, int out_size)
{
    const float* query  = (const float*)d_in[0];
    const float* qpos   = (const float*)d_in[1];
    const float* value  = (const float*)d_in[2];
    const float* refp   = (const float*)d_in[3];
    const float* W_off  = (const float*)d_in[5];
    const float* b_off  = (const float*)d_in[6];
    const float* W_attn = (const float*)d_in[7];
    const float* b_attn = (const float*)d_in[8];
    const float* W_val  = (const float*)d_in[9];
    const float* b_val  = (const float*)d_in[10];
    const float* W_out  = (const float*)d_in[11];
    const float* b_out  = (const float*)d_in[12];
    float* out = (float*)d_out;

    float *qa, *biasb;
    __nv_bfloat16 *vbf, *wth, *wtl, *valh, *qh, *ql, *msh, *msl;
    cudaGetSymbolAddress((void**)&vbf,   g_vbf);
    cudaGetSymbolAddress((void**)&qa,    g_qa);
    cudaGetSymbolAddress((void**)&biasb, g_bias);
    cudaGetSymbolAddress((void**)&wth,   g_Wt_hi);
    cudaGetSymbolAddress((void**)&wtl,   g_Wt_lo);
    cudaGetSymbolAddress((void**)&valh,  g_val_h);
    cudaGetSymbolAddress((void**)&qh,    g_q_h);
    cudaGetSymbolAddress((void**)&ql,    g_q_l);
    cudaGetSymbolAddress((void**)&msh,   g_ms_h);
    cudaGetSymbolAddress((void**)&msl,   g_ms_l);

    static cudaStream_t s2 = nullptr, s3 = nullptr;
    static cudaEvent_t evFork, evV[NSLC], evQ[NSLC], evS[NSLC];
    if (!s2) {
        cudaFuncSetAttribute(hgemm2_kernel<0>,
                             cudaFuncAttributeMaxDynamicSharedMemorySize, HG_SMEM);
        cudaFuncSetAttribute(hgemm2_kernel<1>,
                             cudaFuncAttributeMaxDynamicSharedMemorySize, HG_SMEM);
        cudaFuncSetAttribute(hgemm2_kernel<2>,
                             cudaFuncAttributeMaxDynamicSharedMemorySize, HG_SMEM);
        cudaStreamCreateWithFlags(&s2, cudaStreamNonBlocking);
        cudaStreamCreateWithFlags(&s3, cudaStreamNonBlocking);
        cudaEventCreateWithFlags(&evFork, cudaEventDisableTiming);
        for (int i = 0; i < NSLC; i++) {
            cudaEventCreateWithFlags(&evV[i], cudaEventDisableTiming);
            cudaEventCreateWithFlags(&evQ[i], cudaEventDisableTiming);
            cudaEventCreateWithFlags(&evS[i], cudaEventDisableTiming);
        }
    }

    // ---- fork ----
    cudaEventRecord(evFork, 0);
    cudaStreamWaitEvent(s2, evFork, 0);
    cudaStreamWaitEvent(s3, evFork, 0);

    // s2: value chain — prep + vproj slices
    prep_v_kernel<<<PV_NB, 256, 0, s2>>>(value);
    for (int i = 0; i < NSLC; i++) {
        hgemm2_kernel<2><<<dim3(MVS / 128, CDIM / 64), 256, HG_SMEM, s2>>>(
            valh, nullptr, wth, nullptr, biasb, nullptr, nullptr, vbf,
            i * MVS, CDIM, CDIM);
        cudaEventRecord(evV[i], s2);
    }

    // s0: query chain — prep + qa slices
    prep_qw_kernel<<<PQW_NB, 256>>>(W_val, b_val, W_off, b_off,
                                    W_attn, b_attn, W_out, b_out, query, qpos);
    for (int i = 0; i < NSLC; i++) {
        hgemm2_kernel<0><<<dim3(MQS / 128, NQA / 64), 256, HG_SMEM>>>(
            qh, ql, wth + 256 * CDIM, wtl + 256 * CDIM, biasb + 256,
            nullptr, qa, nullptr, i * MQS, NQA, CDIM);
        cudaEventRecord(evQ[i], 0);
    }

    // s3: sampler slices (slice i needs vproj_i + qa_i)
    for (int i = 0; i < NSLC; i++) {
        cudaStreamWaitEvent(s3, evQ[i], 0);
        cudaStreamWaitEvent(s3, evV[i], 0);
        sample_kernel<<<(MQS * NHEAD) / 8, 256, 0, s3>>>(refp, i * MQS * NHEAD);
        cudaEventRecord(evS[i], s3);
    }

    // s2: out GEMM slices (slice i needs sampler_i); s2 idle after vproj
    for (int i = 0; i < NSLC; i++) {
        cudaStreamWaitEvent(s2, evS[i], 0);
        hgemm2_kernel<1><<<dim3(MQS / 128, CDIM / 64), 256, HG_SMEM, s2>>>(
            msh, msl, wth + 832 * CDIM, wtl + 832 * CDIM, biasb + 832,
            query, out, nullptr, i * MQS, CDIM, CDIM);
    }

    // join
    static cudaEvent_t evDone = nullptr;
    if (!evDone) cudaEventCreateWithFlags(&evDone, cudaEventDisableTiming);
    cudaEventRecord(evDone, s2);
    cudaStreamWaitEvent(0, evDone, 0);
}

// round 16
// speedup vs baseline: 1.4404x; 1.0543x over previous
#include <cuda_runtime.h>
#include <cuda_bf16.h>
#include <math.h>
#include <stdint.h>

// ---------------- problem constants (static per reference) ----------------
#define BSZ   8
#define NQ    4096
#define CDIM  256
#define NHEAD 8
#define NPT   4
#define NLVL  6
#define NVAL  10752
#define DHEAD 32
#define NOFF  384
#define NATT  192
#define NQA   576
#define NWT   1088
#define MQ    (BSZ * NQ)   // 32768
#define MV    (BSZ * NVAL) // 86016
#define NSLC  4
#define MVS   (MV / NSLC)  // 21504 (2 batches)
#define MQS   (MQ / NSLC)  // 8192

// ---------------- device scratch (static, no allocation) ------------------
__device__ __nv_bfloat16 g_vbf [(size_t)MV * CDIM];    // vproj bf16, head-major
__device__ float g_qa   [(size_t)MQ * NQA];            // [off(384) | attn(192)]
__device__ __nv_bfloat16 g_val_h[(size_t)MV * CDIM];   // value bf16 (hi only)
__device__ __nv_bfloat16 g_q_h  [(size_t)MQ * CDIM];
__device__ __nv_bfloat16 g_q_l  [(size_t)MQ * CDIM];
__device__ __nv_bfloat16 g_ms_h [(size_t)MQ * CDIM];   // deform-attn out (bf16)
__device__ __nv_bfloat16 g_Wt_hi[NWT * CDIM];
__device__ __nv_bfloat16 g_Wt_lo[NWT * CDIM];
__device__ float g_bias[NWT];

__constant__ int c_H[NLVL] = {64, 32, 16, 64, 32, 16};
__constant__ int c_W[NLVL] = {64, 32, 16, 64, 32, 16};
__constant__ int c_S[NLVL] = {0, 4096, 5120, 5376, 9472, 10496};

// ---------------- small helpers -------------------------------------------
__device__ __forceinline__ uint32_t smem_u32(const void* p) {
    uint32_t a;
    asm("{ .reg .u64 t; cvta.to.shared.u64 t, %1; cvt.u32.u64 %0, t; }"
        : "=r"(a) : "l"(p));
    return a;
}
__device__ __forceinline__ void ldsm_x4(uint32_t* r, uint32_t addr) {
    asm volatile("ldmatrix.sync.aligned.m8n8.x4.shared.b16 {%0,%1,%2,%3}, [%4];"
                 : "=r"(r[0]), "=r"(r[1]), "=r"(r[2]), "=r"(r[3]) : "r"(addr));
}
__device__ __forceinline__ void mma_bf16(float* c, const uint32_t* a,
                                         const uint32_t* b) {
    asm volatile(
        "mma.sync.aligned.m16n8k16.row.col.f32.bf16.bf16.f32 "
        "{%0,%1,%2,%3}, {%4,%5,%6,%7}, {%8,%9}, {%0,%1,%2,%3};"
        : "+f"(c[0]), "+f"(c[1]), "+f"(c[2]), "+f"(c[3])
        : "r"(a[0]), "r"(a[1]), "r"(a[2]), "r"(a[3]), "r"(b[0]), "r"(b[1]));
}
__device__ __forceinline__ uint32_t pack_bf16(float x, float y) {
    __nv_bfloat162 t = __halves2bfloat162(__float2bfloat16_rn(x),
                                          __float2bfloat16_rn(y));
    return *(uint32_t*)&t;
}
__device__ __forceinline__ void cp16(uint32_t dst, const void* src) {
    asm volatile("cp.async.cg.shared.global [%0], [%1], 16;"
                 :: "r"(dst), "l"(src));
}
#define CP_COMMIT() asm volatile("cp.async.commit_group;" ::: "memory")
#define CP_WAIT(n)  asm volatile("cp.async.wait_group %0;" :: "n"(n) : "memory")

// ============== prep branch A: weights + q split ============================
#define PQW_B0 1088
#define PQW_NB (PQW_B0 + (MQ * CDIM / 4) / 256)     // 9280

__global__ __launch_bounds__(256)
void prep_qw_kernel(const float* __restrict__ W_val,
                    const float* __restrict__ b_val,
                    const float* __restrict__ W_off,
                    const float* __restrict__ b_off,
                    const float* __restrict__ W_attn,
                    const float* __restrict__ b_attn,
                    const float* __restrict__ W_out,
                    const float* __restrict__ b_out,
                    const float* __restrict__ query,
                    const float* __restrict__ qpos)
{
    const int bx = blockIdx.x;
    const int tid = threadIdx.x;
    if (bx < PQW_B0) {
        const int n = bx, k = tid;
        float x, bb;
        if (n < 256)      { x = W_val[k * 256 + n];          bb = b_val[n]; }
        else if (n < 832) {
            const int m = n - 256;
            if (m < 384)  { x = W_off[k * 384 + m];          bb = b_off[m]; }
            else          { x = W_attn[k * 192 + (m - 384)]; bb = b_attn[m - 384]; }
        }
        else              { x = W_out[k * 256 + (n - 832)];  bb = b_out[n - 832]; }
        const __nv_bfloat16 hi = __float2bfloat16_rn(x);
        const __nv_bfloat16 lo = __float2bfloat16_rn(x - __bfloat162float(hi));
        g_Wt_hi[n * CDIM + k] = hi;
        g_Wt_lo[n * CDIM + k] = lo;
        if (k == 0) g_bias[n] = bb;
        return;
    }
    const size_t i4 = (size_t)(bx - PQW_B0) * 256 + tid;
    float4 v = ((const float4*)query)[i4];
    const float4 u = ((const float4*)qpos)[i4];
    v.x += u.x; v.y += u.y; v.z += u.z; v.w += u.w;
    const float hx = __bfloat162float(__float2bfloat16_rn(v.x));
    const float hy = __bfloat162float(__float2bfloat16_rn(v.y));
    const float hz = __bfloat162float(__float2bfloat16_rn(v.z));
    const float hw = __bfloat162float(__float2bfloat16_rn(v.w));
    ((uint2*)g_q_h)[i4] = make_uint2(pack_bf16(v.x, v.y), pack_bf16(v.z, v.w));
    ((uint2*)g_q_l)[i4] = make_uint2(pack_bf16(v.x - hx, v.y - hy),
                                     pack_bf16(v.z - hz, v.w - hw));
}

// ============== prep branch B: value -> bf16 (hi only) ======================
#define PV_NB ((MV * CDIM / 4) / 256)               // 21504

__global__ __launch_bounds__(256)
void prep_v_kernel(const float* __restrict__ value)
{
    const size_t i4 = (size_t)blockIdx.x * 256 + threadIdx.x;
    const float4 v = ((const float4*)value)[i4];
    ((uint2*)g_val_h)[i4] = make_uint2(pack_bf16(v.x, v.y), pack_bf16(v.z, v.w));
}

// ============== bf16-split HMMA GEMM, 2-stage dual-sync (round-14 core) ====
// MODE 0 (qa):    3 terms  AhBh + AhBl + AlBh, C fp32
// MODE 1 (out):   2 terms  AhBh + AhBl (A = ms already bf16), C fp32 + resid
// MODE 2 (vproj): 1 term   AhBh, C bf16 head-major
#define HG_STG   24576
#define HG_SMEM  49152

template <int MODE>
__global__ __launch_bounds__(256, 4)
void hgemm2_kernel(const __nv_bfloat16* __restrict__ Ath,
                   const __nv_bfloat16* __restrict__ Atl,
                   const __nv_bfloat16* __restrict__ Bth,
                   const __nv_bfloat16* __restrict__ Btl,
                   const float* __restrict__ bias,
                   const float* __restrict__ resid, float* __restrict__ Cf,
                   __nv_bfloat16* __restrict__ Cb,
                   int m0, int N, int K)
{
    constexpr bool A_LO = (MODE == 0);
    constexpr bool B_LO = (MODE != 2);

    extern __shared__ __align__(16) uint8_t smem[];
    const uint32_t uS = smem_u32(smem);

    const int tid  = threadIdx.x;
    const int lane = tid & 31;
    const int wid  = tid >> 5;
    const int wm   = wid >> 1;
    const int wn   = wid & 1;
    const int bm   = m0 + blockIdx.x * 128;
    const int bn   = blockIdx.y * 64;
    const int KT   = K >> 5;

    const int lrA  = ((lane >> 3) & 1) * 8 + (lane & 7);
    const int lk8A = lane >> 4;
    const int rowA = wm * 32 + lrA;
    const int xrA  = (rowA >> 1) & 3;
    const uint32_t offA0 = (uint32_t)(rowA * 64 + ((0 * 2 + lk8A) ^ xrA) * 16);
    const uint32_t offA1 = (uint32_t)(rowA * 64 + ((1 * 2 + lk8A) ^ xrA) * 16);

    const int lrB  = (lane >> 4) * 8 + (lane & 7);
    const int lk8B = (lane >> 3) & 1;
    const int rowB = wn * 32 + lrB;
    const int xrB  = (rowB >> 1) & 3;
    const uint32_t offB0 = (uint32_t)(16384 + rowB * 64 + ((0 * 2 + lk8B) ^ xrB) * 16);
    const uint32_t offB1 = (uint32_t)(16384 + rowB * 64 + ((1 * 2 + lk8B) ^ xrB) * 16);

    const int ar0 = tid >> 2, ac0 = tid & 3;
    const int ar1 = ar0 + 64;
    const int br  = tid >> 2, bc = tid & 3;
    const uint32_t sA0 = (uint32_t)(ar0 * 64 + ((ac0 ^ ((ar0 >> 1) & 3)) * 16));
    const uint32_t sA1 = (uint32_t)(ar1 * 64 + ((ac0 ^ ((ar1 >> 1) & 3)) * 16));
    const uint32_t sB  = (uint32_t)(16384 + br * 64 + ((bc ^ ((br >> 1) & 3)) * 16));

    float acc[2][4][4];
#pragma unroll
    for (int t = 0; t < 2; t++)
#pragma unroll
        for (int u = 0; u < 4; u++)
#pragma unroll
            for (int i = 0; i < 4; i++) acc[t][u][i] = 0.f;

    auto issue = [&](int kt, int buf) {
        const int k0 = kt * 32;
        const uint32_t base = uS + buf * HG_STG;
        const size_t oa0 = (size_t)(bm + ar0) * K + k0 + ac0 * 8;
        const size_t oa1 = (size_t)(bm + ar1) * K + k0 + ac0 * 8;
        const size_t ob  = (size_t)(bn + br ) * K + k0 + bc  * 8;
        cp16(base +         sA0, Ath + oa0);
        cp16(base +         sA1, Ath + oa1);
        if (A_LO) {
            cp16(base + 8192u + sA0, Atl + oa0);
            cp16(base + 8192u + sA1, Atl + oa1);
        }
        cp16(base +         sB,  Bth + ob);
        if (B_LO)
            cp16(base + 4096u + sB, Btl + ob);
        CP_COMMIT();
    };

    issue(0, 0);
    issue(1, 1);

#pragma unroll 1
    for (int kt = 0; kt < KT; kt++) {
        if (kt == KT - 1) { CP_WAIT(0); } else { CP_WAIT(1); }
        __syncthreads();

        const uint32_t sb = uS + (kt & 1) * HG_STG;
#pragma unroll
        for (int ks = 0; ks < 2; ks++) {
            const uint32_t oA = sb + (ks ? offA1 : offA0);
            const uint32_t oB = sb + (ks ? offB1 : offB0);
            uint32_t bH[4][2], bL[4][2];
            ldsm_x4(&bH[0][0], oB);
            ldsm_x4(&bH[2][0], oB + 1024);
            if (B_LO) {
                ldsm_x4(&bL[0][0], oB + 4096);
                ldsm_x4(&bL[2][0], oB + 4096 + 1024);
            }
#pragma unroll
            for (int t = 0; t < 2; t++) {
                uint32_t aH[4], aL[4];
                ldsm_x4(aH, oA + t * 1024);
                if (A_LO) ldsm_x4(aL, oA + 8192 + t * 1024);
#pragma unroll
                for (int u = 0; u < 4; u++) {
                    mma_bf16(acc[t][u], aH, bH[u]);
                    if (B_LO) mma_bf16(acc[t][u], aH, bL[u]);
                    if (A_LO) mma_bf16(acc[t][u], aL, bH[u]);
                }
            }
        }
        __syncthreads();
        if (kt + 2 < KT) issue(kt + 2, kt & 1);
    }

    // ---- epilogue ----
    const int g = lane >> 2, tg = lane & 3;
    const int batch = bm / NVAL;
    const int head  = (bn + wn * 32) >> 5;     // MODE 2 only
#pragma unroll
    for (int t = 0; t < 2; t++)
#pragma unroll
        for (int u = 0; u < 4; u++) {
            const int row = bm + wm * 32 + t * 16 + g;
            const int col = bn + wn * 32 + u * 8 + tg * 2;
            const float2 bv = *(const float2*)(bias + col);
            float2 o0 = make_float2(acc[t][u][0] + bv.x, acc[t][u][1] + bv.y);
            float2 o1 = make_float2(acc[t][u][2] + bv.x, acc[t][u][3] + bv.y);
            if (MODE == 1) {
                const float2 r0 = *(const float2*)(resid + (size_t)row * N + col);
                const float2 r1 = *(const float2*)(resid + (size_t)(row + 8) * N + col);
                o0.x += r0.x; o0.y += r0.y;
                o1.x += r1.x; o1.y += r1.y;
            }
            if (MODE == 2) {
                const int nv = row - batch * NVAL;
                const int dim = u * 8 + tg * 2;
                const size_t base =
                    ((size_t)(batch * NHEAD + head) * NVAL + nv) * DHEAD + dim;
                *(uint32_t*)(Cb + base)              = pack_bf16(o0.x, o0.y);
                *(uint32_t*)(Cb + base + 8 * DHEAD)  = pack_bf16(o1.x, o1.y);
            } else {
                *(float2*)(Cf + (size_t)row * N + col) = o0;
                *(float2*)(Cf + (size_t)(row + 8) * N + col) = o1;
            }
        }
}

// ---------------- sampling kernel: bf16 head-major gather ------------------
__global__ __launch_bounds__(256)
void sample_kernel(const float* __restrict__ refp, int warp0)
{
    __shared__ __align__(16) unsigned long long sm_iw[8][4][24];

    const int wslot = threadIdx.x >> 5;
    const int warp = warp0 + blockIdx.x * 8 + wslot;
    const int lane = threadIdx.x & 31;
    const int h  = warp & 7;
    const int bq = warp >> 3;
    const int b  = bq >> 12;

    float a = -INFINITY;
    if (lane < 24) a = g_qa[(size_t)bq * NQA + NOFF + h * 24 + lane];
    float m = a;
#pragma unroll
    for (int s = 16; s; s >>= 1) m = fmaxf(m, __shfl_xor_sync(0xffffffffu, m, s));
    float e = (lane < 24) ? __expf(a - m) : 0.f;
    float ssum = e;
#pragma unroll
    for (int s = 16; s; s >>= 1) ssum += __shfl_xor_sync(0xffffffffu, ssum, s);
    const float aw = e / ssum;

    if (lane < 24) {
        const int l = lane >> 2;
        const int p = lane & 3;
        const int H = c_H[l], W = c_W[l], S = c_S[l];
        const size_t ob = (size_t)bq * NQA + (((h * NLVL + l) * NPT + p) << 1);
        const float2 off2 = *(const float2*)(g_qa + ob);
        const size_t rb = ((size_t)bq * NLVL + l) << 1;
        const float rx = refp[rb + 0];
        const float ry = refp[rb + 1];
        const float x = rx * (float)W + off2.x - 0.5f;
        const float y = ry * (float)H + off2.y - 0.5f;
        const float xf = floorf(x), yf = floorf(y);
        const float lx = x - xf, ly = y - yf;
        const int ix = (int)xf, iy = (int)yf;
        const bool vx0 = (ix     >= 0) && (ix     < W);
        const bool vx1 = (ix + 1 >= 0) && (ix + 1 < W);
        const bool vy0 = (iy     >= 0) && (iy     < H);
        const bool vy1 = (iy + 1 >= 0) && (iy + 1 < H);
        const int cx0 = min(max(ix, 0), W - 1);
        const int cx1 = min(max(ix + 1, 0), W - 1);
        const int cy0 = min(max(iy, 0), H - 1);
        const int cy1 = min(max(iy + 1, 0), H - 1);
        const unsigned o00 = (unsigned)(S + cy0 * W + cx0) << 6;
        const unsigned o01 = (unsigned)(S + cy0 * W + cx1) << 6;
        const unsigned o10 = (unsigned)(S + cy1 * W + cx0) << 6;
        const unsigned o11 = (unsigned)(S + cy1 * W + cx1) << 6;
        const float w00 = aw * (1.f - lx) * (1.f - ly) * (float)(vx0 && vy0);
        const float w01 = aw * lx         * (1.f - ly) * (float)(vx1 && vy0);
        const float w10 = aw * (1.f - lx) * ly         * (float)(vx0 && vy1);
        const float w11 = aw * lx         * ly         * (float)(vx1 && vy1);
        sm_iw[wslot][0][lane] =
            (unsigned long long)o00 | ((unsigned long long)__float_as_uint(w00) << 32);
        sm_iw[wslot][1][lane] =
            (unsigned long long)o01 | ((unsigned long long)__float_as_uint(w01) << 32);
        sm_iw[wslot][2][lane] =
            (unsigned long long)o10 | ((unsigned long long)__float_as_uint(w10) << 32);
        sm_iw[wslot][3][lane] =
            (unsigned long long)o11 | ((unsigned long long)__float_as_uint(w11) << 32);
    }
    __syncwarp();

    const int g  = lane >> 3;
    const int li = lane & 7;
    const char* __restrict__ vbb =
        (const char*)g_vbf + (size_t)(b * NHEAD + h) * NVAL * (DHEAD * 2) + li * 8;

    float4 acc0 = make_float4(0.f, 0.f, 0.f, 0.f);
    float4 acc1 = make_float4(0.f, 0.f, 0.f, 0.f);
#pragma unroll
    for (int j = 0; j < 12; j++) {
        const uint4 t = *(const uint4*)&sm_iw[wslot][g][2 * j];
        const float w0 = __uint_as_float(t.y);
        const float w1 = __uint_as_float(t.w);
        const uint2 v0 = *(const uint2*)(vbb + t.x);
        const uint2 v1 = *(const uint2*)(vbb + t.z);
        acc0.x = fmaf(w0, __uint_as_float(v0.x << 16),         acc0.x);
        acc0.y = fmaf(w0, __uint_as_float(v0.x & 0xffff0000u), acc0.y);
        acc0.z = fmaf(w0, __uint_as_float(v0.y << 16),         acc0.z);
        acc0.w = fmaf(w0, __uint_as_float(v0.y & 0xffff0000u), acc0.w);
        acc1.x = fmaf(w1, __uint_as_float(v1.x << 16),         acc1.x);
        acc1.y = fmaf(w1, __uint_as_float(v1.x & 0xffff0000u), acc1.y);
        acc1.z = fmaf(w1, __uint_as_float(v1.y << 16),         acc1.z);
        acc1.w = fmaf(w1, __uint_as_float(v1.y & 0xffff0000u), acc1.w);
    }
    float4 acc = make_float4(acc0.x + acc1.x, acc0.y + acc1.y,
                             acc0.z + acc1.z, acc0.w + acc1.w);
#pragma unroll
    for (int s = 8; s <= 16; s <<= 1) {
        acc.x += __shfl_xor_sync(0xffffffffu, acc.x, s);
        acc.y += __shfl_xor_sync(0xffffffffu, acc.y, s);
        acc.z += __shfl_xor_sync(0xffffffffu, acc.z, s);
        acc.w += __shfl_xor_sync(0xffffffffu, acc.w, s);
    }
    if (lane < 8) {
        const size_t o4 = ((size_t)bq * CDIM + h * DHEAD + lane * 4) >> 2;
        ((uint2*)g_ms_h)[o4] = make_uint2(pack_bf16(acc.x, acc.y),
                                          pack_bf16(acc.z, acc.w));
    }
}

// ---------------- launch: 4-slice 3-stream pipeline -------------------------
extern "C" void kernel_launch(void* const* d_in, const int* in_sizes, int n_in,
                              void* d_out, int out_size)
{
    const float* query  = (const float*)d_in[0];
    const float* qpos   = (const float*)d_in[1];
    const float* value  = (const float*)d_in[2];
    const float* refp   = (const float*)d_in[3];
    const float* W_off  = (const float*)d_in[5];
    const float* b_off  = (const float*)d_in[6];
    const float* W_attn = (const float*)d_in[7];
    const float* b_attn = (const float*)d_in[8];
    const float* W_val  = (const float*)d_in[9];
    const float* b_val  = (const float*)d_in[10];
    const float* W_out  = (const float*)d_in[11];
    const float* b_out  = (const float*)d_in[12];
    float* out = (float*)d_out;

    float *qa, *biasb;
    __nv_bfloat16 *vbf, *wth, *wtl, *valh, *qh, *ql, *msh;
    cudaGetSymbolAddress((void**)&vbf,   g_vbf);
    cudaGetSymbolAddress((void**)&qa,    g_qa);
    cudaGetSymbolAddress((void**)&biasb, g_bias);
    cudaGetSymbolAddress((void**)&wth,   g_Wt_hi);
    cudaGetSymbolAddress((void**)&wtl,   g_Wt_lo);
    cudaGetSymbolAddress((void**)&valh,  g_val_h);
    cudaGetSymbolAddress((void**)&qh,    g_q_h);
    cudaGetSymbolAddress((void**)&ql,    g_q_l);
    cudaGetSymbolAddress((void**)&msh,   g_ms_h);

    static cudaStream_t s2 = nullptr, s3 = nullptr;
    static cudaEvent_t evFork, evV[NSLC], evQ[NSLC], evS[NSLC];
    if (!s2) {
        cudaFuncSetAttribute(hgemm2_kernel<0>,
                             cudaFuncAttributeMaxDynamicSharedMemorySize, HG_SMEM);
        cudaFuncSetAttribute(hgemm2_kernel<1>,
                             cudaFuncAttributeMaxDynamicSharedMemorySize, HG_SMEM);
        cudaFuncSetAttribute(hgemm2_kernel<2>,
                             cudaFuncAttributeMaxDynamicSharedMemorySize, HG_SMEM);
        cudaStreamCreateWithFlags(&s2, cudaStreamNonBlocking);
        cudaStreamCreateWithFlags(&s3, cudaStreamNonBlocking);
        cudaEventCreateWithFlags(&evFork, cudaEventDisableTiming);
        for (int i = 0; i < NSLC; i++) {
            cudaEventCreateWithFlags(&evV[i], cudaEventDisableTiming);
            cudaEventCreateWithFlags(&evQ[i], cudaEventDisableTiming);
            cudaEventCreateWithFlags(&evS[i], cudaEventDisableTiming);
        }
    }

    // ---- fork ----
    cudaEventRecord(evFork, 0);
    cudaStreamWaitEvent(s2, evFork, 0);
    cudaStreamWaitEvent(s3, evFork, 0);

    // s2: value chain — prep + vproj slices
    prep_v_kernel<<<PV_NB, 256, 0, s2>>>(value);
    for (int i = 0; i < NSLC; i++) {
        hgemm2_kernel<2><<<dim3(MVS / 128, CDIM / 64), 256, HG_SMEM, s2>>>(
            valh, nullptr, wth, nullptr, biasb, nullptr, nullptr, vbf,
            i * MVS, CDIM, CDIM);
        cudaEventRecord(evV[i], s2);
    }

    // s0: query chain — prep + qa slices
    prep_qw_kernel<<<PQW_NB, 256>>>(W_val, b_val, W_off, b_off,
                                    W_attn, b_attn, W_out, b_out, query, qpos);
    for (int i = 0; i < NSLC; i++) {
        hgemm2_kernel<0><<<dim3(MQS / 128, NQA / 64), 256, HG_SMEM>>>(
            qh, ql, wth + 256 * CDIM, wtl + 256 * CDIM, biasb + 256,
            nullptr, qa, nullptr, i * MQS, NQA, CDIM);
        cudaEventRecord(evQ[i], 0);
    }

    // s3: sampler slices (slice i needs vproj_i + qa_i)
    for (int i = 0; i < NSLC; i++) {
        cudaStreamWaitEvent(s3, evQ[i], 0);
        cudaStreamWaitEvent(s3, evV[i], 0);
        sample_kernel<<<(MQS * NHEAD) / 8, 256, 0, s3>>>(refp, i * MQS * NHEAD);
        cudaEventRecord(evS[i], s3);
    }

    // s2: out GEMM slices (slice i needs sampler_i); s2 idle after vproj
    for (int i = 0; i < NSLC; i++) {
        cudaStreamWaitEvent(s2, evS[i], 0);
        hgemm2_kernel<1><<<dim3(MQS / 128, CDIM / 64), 256, HG_SMEM, s2>>>(
            msh, nullptr, wth + 832 * CDIM, wtl + 832 * CDIM, biasb + 832,
            query, out, nullptr, i * MQS, CDIM, CDIM);
    }

    // join
    static cudaEvent_t evDone = nullptr;
    if (!evDone) cudaEventCreateWithFlags(&evDone, cudaEventDisableTiming);
    cudaEventRecord(evDone, s2);
    cudaStreamWaitEvent(0, evDone, 0);
}